// round 13
// baseline (speedup 1.0000x reference)
#include <cuda_runtime.h>
#include <cstdint>

#define BB 2
#define TT 4096
#define DD 128
#define KK 256
#define BT (BB * TT)

// ---------------- scratch ----------------
__device__ float g_mf[BT * DD];
__device__ float g_a0[BT * DD];   // zero-initialized; invariant: zero between stages
__device__ float g_zc[BT * DD];
__device__ float g_va[BT * DD];
__device__ unsigned short g_qhh[BT * DD];
__device__ unsigned short g_qhl[BT * DD];
__device__ unsigned short g_khh[BT * DD];
__device__ unsigned short g_khl[BT * DD];
__device__ unsigned short g_woh[DD * DD];
__device__ unsigned short g_wol[DD * DD];
__device__ unsigned short g_wqh[DD * DD];
__device__ unsigned short g_wql[DD * DD];

// ================= helpers =================
typedef unsigned long long ull;
__device__ __forceinline__ uint32_t smem_u32(const void* p) {
    uint32_t a;
    asm("{ .reg .u64 t; cvta.to.shared.u64 t, %1; cvt.u32.u64 %0, t; }" : "=r"(a) : "l"(p));
    return a;
}
__device__ __forceinline__ void ldsm4(uint32_t& r0, uint32_t& r1, uint32_t& r2, uint32_t& r3,
                                      uint32_t addr) {
    asm volatile("ldmatrix.sync.aligned.m8n8.x4.shared.b16 {%0,%1,%2,%3}, [%4];"
                 : "=r"(r0), "=r"(r1), "=r"(r2), "=r"(r3) : "r"(addr));
}
__device__ __forceinline__ void ldsm4t(uint32_t& r0, uint32_t& r1, uint32_t& r2, uint32_t& r3,
                                       uint32_t addr) {
    asm volatile("ldmatrix.sync.aligned.m8n8.x4.trans.shared.b16 {%0,%1,%2,%3}, [%4];"
                 : "=r"(r0), "=r"(r1), "=r"(r2), "=r"(r3) : "r"(addr));
}
__device__ __forceinline__ void mma16816(float* c, uint32_t a0, uint32_t a1, uint32_t a2,
                                         uint32_t a3, uint32_t b0, uint32_t b1) {
    asm volatile(
        "mma.sync.aligned.m16n8k16.row.col.f32.bf16.bf16.f32 "
        "{%0,%1,%2,%3}, {%4,%5,%6,%7}, {%8,%9}, {%0,%1,%2,%3};"
        : "+f"(c[0]), "+f"(c[1]), "+f"(c[2]), "+f"(c[3])
        : "r"(a0), "r"(a1), "r"(a2), "r"(a3), "r"(b0), "r"(b1));
}
__device__ __forceinline__ void bsplit2(float x0, float x1, uint32_t& h, uint32_t& l) {
    uint16_t h0, h1, l0, l1;
    asm("cvt.rn.bf16.f32 %0, %1;" : "=h"(h0) : "f"(x0));
    asm("cvt.rn.bf16.f32 %0, %1;" : "=h"(h1) : "f"(x1));
    float f0 = __uint_as_float((uint32_t)h0 << 16);
    float f1 = __uint_as_float((uint32_t)h1 << 16);
    asm("cvt.rn.bf16.f32 %0, %1;" : "=h"(l0) : "f"(x0 - f0));
    asm("cvt.rn.bf16.f32 %0, %1;" : "=h"(l1) : "f"(x1 - f1));
    h = (uint32_t)h0 | ((uint32_t)h1 << 16);
    l = (uint32_t)l0 | ((uint32_t)l1 << 16);
}
__device__ __forceinline__ uint32_t sw_off(int row, int d) {
    return (uint32_t)(row * 256 + ((((d >> 3) ^ (row & 7)) & 15) << 4) + (d & 7) * 2);
}
__device__ __forceinline__ float sinpoly(float x) {
    float x2 = x * x;
    float pp = fmaf(x2, 2.7557319e-06f, -1.9841270e-04f);
    pp = fmaf(x2, pp, 8.3333333e-03f);
    pp = fmaf(x2, pp, -1.6666667e-01f);
    return fmaf(x * x2, pp, x);
}
__device__ __forceinline__ ull dup2(float x) {
    ull r; asm("mov.b64 %0, {%1, %1};" : "=l"(r) : "f"(x)); return r;
}
__device__ __forceinline__ ull pack2(float x, float y) {
    ull r; asm("mov.b64 %0, {%1, %2};" : "=l"(r) : "f"(x), "f"(y)); return r;
}
__device__ __forceinline__ void fma2(ull& d, ull a, ull b) {
    asm("fma.rn.f32x2 %0, %1, %2, %0;" : "+l"(d) : "l"(a), "l"(b));
}
__device__ __forceinline__ float2 unpk(ull v) {
    float2 r; asm("mov.b64 {%0, %1}, %2;" : "=f"(r.x), "=f"(r.y) : "l"(v)); return r;
}

__device__ __forceinline__ void cvt_store8o(char* smcp, uint32_t hoff, uint32_t loff,
                                            int row, int col, float4 a, float4 b) {
    uint32_t hw[4], lw[4];
    bsplit2(a.x, a.y, hw[0], lw[0]);
    bsplit2(a.z, a.w, hw[1], lw[1]);
    bsplit2(b.x, b.y, hw[2], lw[2]);
    bsplit2(b.z, b.w, hw[3], lw[3]);
    uint32_t off = sw_off(row, col);
    *(uint4*)(smcp + hoff + off) = make_uint4(hw[0], hw[1], hw[2], hw[3]);
    *(uint4*)(smcp + loff + off) = make_uint4(lw[0], lw[1], lw[2], lw[3]);
}

// ---------------- one-time W prepack ----------------
__global__ __launch_bounds__(256) void prep_w(const float* __restrict__ Wo,
                                              const float* __restrict__ Wq,
                                              unsigned short* __restrict__ Woh,
                                              unsigned short* __restrict__ Wol,
                                              unsigned short* __restrict__ Wqh,
                                              unsigned short* __restrict__ Wql) {
    int i = blockIdx.x * 256 + threadIdx.x;
    float2 a = *(const float2*)(Wo + 2 * i);
    uint32_t h, l;
    bsplit2(a.x, a.y, h, l);
    *(uint32_t*)(Woh + 2 * i) = h;
    *(uint32_t*)(Wol + 2 * i) = l;
    float2 b = *(const float2*)(Wq + 2 * i);
    bsplit2(b.x, b.y, h, l);
    *(uint32_t*)(Wqh + 2 * i) = h;
    *(uint32_t*)(Wql + 2 * i) = l;
}

// attn smem: Qhi 16K | Qlo 16K | K double-buffered (hi 16K + lo 16K) x2 = 96KB
#define QH_OFF 0
#define QL_OFF 16384
#define KBASE_OFF 32768
#define ATTN_SMEM 98304

// ---------------- causal sin-attention (R11 body + diagonal-tile skip) ----------------
__global__ __launch_bounds__(128, 2) void attn_kernel(const unsigned short* __restrict__ Qhh,
                                                      const unsigned short* __restrict__ Qhl,
                                                      const unsigned short* __restrict__ Khh,
                                                      const unsigned short* __restrict__ Khl,
                                                      float* __restrict__ O) {
    extern __shared__ char smc[];
    const uint32_t sbase = smem_u32(smc);
    const int tid = threadIdx.x;
    const int lane = tid & 31, w = tid >> 5;
    const int P = blockIdx.x, split = blockIdx.y;
    const int g = lane >> 3, r = lane & 7;
    const int krow = tid >> 1, kc0 = (tid & 1) * 64;
    const int lo = (130 * split) / 9, hi = (130 * (split + 1)) / 9;

    int c = 0;
    for (int sp = 0; sp < 4; sp++) {
        const int b = sp >> 1;
        const int R = (sp & 1) ? (63 - P) : P;
        const int n = R + 1;
        int s_lo = lo - c; if (s_lo < 0) s_lo = 0;
        int s_hi = hi - c; if (s_hi > n) s_hi = n;
        c += n;
        if (s_lo >= s_hi) continue;

        const unsigned short* Qhb = Qhh + (long long)b * TT * DD;
        const unsigned short* Qlb = Qhl + (long long)b * TT * DD;
        const unsigned short* Khb = Khh + (long long)b * TT * DD;
        const unsigned short* Klb = Khl + (long long)b * TT * DD;

        __syncthreads();
        for (int t = tid; t < 1024; t += 128) {
            int row = t >> 4, d0 = (t & 15) * 8;
            long long src = ((long long)R * 64 + row) * DD + d0;
            uint32_t off = sw_off(row, d0);
            *(uint4*)(smc + QH_OFF + off) = *(const uint4*)(Qhb + src);
            *(uint4*)(smc + QL_OFF + off) = *(const uint4*)(Qlb + src);
        }
        {
            long long src = ((long long)s_lo * 64 + krow) * DD + kc0;
#pragma unroll
            for (int q = 0; q < 8; q++) {
                uint32_t off = sw_off(krow, kc0 + 8 * q);
                *(uint4*)(smc + KBASE_OFF + off) = *(const uint4*)(Khb + src + 8 * q);
                *(uint4*)(smc + KBASE_OFF + 16384 + off) = *(const uint4*)(Klb + src + 8 * q);
            }
        }
        float Oc[16][4];
#pragma unroll
        for (int nf = 0; nf < 16; nf++)
#pragma unroll
            for (int e = 0; e < 4; e++) Oc[nf][e] = 0.f;
        __syncthreads();

        // hoist Q A-frags (hi AND lo) into registers
        uint32_t qah[8][4], qal[8][4];
#pragma unroll
        for (int kc = 0; kc < 8; kc++) {
            uint32_t aoff = sw_off(w * 16 + ((g & 1) ? 8 : 0) + r, kc * 16 + ((g >> 1) ? 8 : 0));
            ldsm4(qah[kc][0], qah[kc][1], qah[kc][2], qah[kc][3], sbase + QH_OFF + aoff);
            ldsm4(qal[kc][0], qal[kc][1], qal[kc][2], qal[kc][3], sbase + QL_OFF + aoff);
        }

        for (int sb = s_lo; sb < s_hi; sb++) {
            const int cur = (sb - s_lo) & 1;
            const uint32_t KH = KBASE_OFF + (uint32_t)cur * 32768;
            const uint32_t KL = KH + 16384;
            const bool pre = (sb + 1 < s_hi);
            const uint32_t NH = KBASE_OFF + (uint32_t)(1 - cur) * 32768;
            long long psrc = ((long long)(sb + 1) * 64 + krow) * DD + kc0;
            const bool diag = (sb == R);   // diagonal tile: cols sb*64.. vs rows R*64..

            float C[8][4];
#pragma unroll
            for (int nf = 0; nf < 8; nf++)
#pragma unroll
                for (int e = 0; e < 4; e++) C[nf][e] = 0.f;
#pragma unroll
            for (int kc = 0; kc < 8; kc++) {
                int d0 = kc * 16;
                uint32_t bh[4][4], bl[4][4];
#pragma unroll
                for (int nfp = 0; nfp < 4; nfp++) {
                    if (diag && nfp > w) continue;   // fully masked (warp-uniform)
                    uint32_t boff = sw_off(nfp * 16 + ((g >> 1) ? 8 : 0) + r,
                                           d0 + ((g & 1) ? 8 : 0));
                    ldsm4(bh[nfp][0], bh[nfp][1], bh[nfp][2], bh[nfp][3], sbase + KH + boff);
                    ldsm4(bl[nfp][0], bl[nfp][1], bl[nfp][2], bl[nfp][3], sbase + KL + boff);
                }
#pragma unroll
                for (int nfp = 0; nfp < 4; nfp++) {
                    if (diag && nfp > w) continue;
                    mma16816(C[2 * nfp],     qah[kc][0], qah[kc][1], qah[kc][2], qah[kc][3], bh[nfp][0], bh[nfp][1]);
                    mma16816(C[2 * nfp + 1], qah[kc][0], qah[kc][1], qah[kc][2], qah[kc][3], bh[nfp][2], bh[nfp][3]);
                }
#pragma unroll
                for (int nfp = 0; nfp < 4; nfp++) {
                    if (diag && nfp > w) continue;
                    mma16816(C[2 * nfp],     qah[kc][0], qah[kc][1], qah[kc][2], qah[kc][3], bl[nfp][0], bl[nfp][1]);
                    mma16816(C[2 * nfp + 1], qah[kc][0], qah[kc][1], qah[kc][2], qah[kc][3], bl[nfp][2], bl[nfp][3]);
                }
#pragma unroll
                for (int nfp = 0; nfp < 4; nfp++) {
                    if (diag && nfp > w) continue;
                    mma16816(C[2 * nfp],     qal[kc][0], qal[kc][1], qal[kc][2], qal[kc][3], bh[nfp][0], bh[nfp][1]);
                    mma16816(C[2 * nfp + 1], qal[kc][0], qal[kc][1], qal[kc][2], qal[kc][3], bh[nfp][2], bh[nfp][3]);
                }
            }
            if (pre) {
#pragma unroll
                for (int q = 0; q < 8; q++)
                    *(uint4*)(smc + NH + sw_off(krow, kc0 + 8 * q)) =
                        *(const uint4*)(Khb + psrc + 8 * q);
            }

            uint32_t a2h[4][4], a2l[4][4];
            const int ig = R * 64 + w * 16 + (lane >> 2);
#pragma unroll
            for (int nf = 0; nf < 8; nf++) {
                int jb = sb * 64 + nf * 8 + 2 * (lane & 3);
                float s0 = sinpoly(C[nf][0]); if (jb > ig) s0 = 0.f;
                float s1 = sinpoly(C[nf][1]); if (jb + 1 > ig) s1 = 0.f;
                float s2 = sinpoly(C[nf][2]); if (jb > ig + 8) s2 = 0.f;
                float s3 = sinpoly(C[nf][3]); if (jb + 1 > ig + 8) s3 = 0.f;
                int kc2 = nf >> 1, hk = (nf & 1) ? 2 : 0;
                bsplit2(s0, s1, a2h[kc2][hk], a2l[kc2][hk]);
                bsplit2(s2, s3, a2h[kc2][hk + 1], a2l[kc2][hk + 1]);
            }

#pragma unroll
            for (int kc2 = 0; kc2 < 4; kc2++) {
                if (diag && kc2 > w) continue;   // S frags all-zero (warp-uniform)
                int j0 = kc2 * 16;
#pragma unroll
                for (int hh = 0; hh < 2; hh++) {
                    uint32_t th[4][4], tl[4][4];
#pragma unroll
                    for (int q = 0; q < 4; q++) {
                        int nfp = hh * 4 + q;
                        uint32_t boff = sw_off(j0 + ((g & 1) ? 8 : 0) + r,
                                               nfp * 16 + ((g >> 1) ? 8 : 0));
                        ldsm4t(th[q][0], th[q][1], th[q][2], th[q][3], sbase + KH + boff);
                        ldsm4t(tl[q][0], tl[q][1], tl[q][2], tl[q][3], sbase + KL + boff);
                    }
#pragma unroll
                    for (int q = 0; q < 4; q++) {
                        int nfp = hh * 4 + q;
                        mma16816(Oc[2 * nfp],     a2h[kc2][0], a2h[kc2][1], a2h[kc2][2], a2h[kc2][3], th[q][0], th[q][1]);
                        mma16816(Oc[2 * nfp + 1], a2h[kc2][0], a2h[kc2][1], a2h[kc2][2], a2h[kc2][3], th[q][2], th[q][3]);
                    }
#pragma unroll
                    for (int q = 0; q < 4; q++) {
                        int nfp = hh * 4 + q;
                        mma16816(Oc[2 * nfp],     a2h[kc2][0], a2h[kc2][1], a2h[kc2][2], a2h[kc2][3], tl[q][0], tl[q][1]);
                        mma16816(Oc[2 * nfp + 1], a2h[kc2][0], a2h[kc2][1], a2h[kc2][2], a2h[kc2][3], tl[q][2], tl[q][3]);
                    }
#pragma unroll
                    for (int q = 0; q < 4; q++) {
                        int nfp = hh * 4 + q;
                        mma16816(Oc[2 * nfp],     a2l[kc2][0], a2l[kc2][1], a2l[kc2][2], a2l[kc2][3], th[q][0], th[q][1]);
                        mma16816(Oc[2 * nfp + 1], a2l[kc2][0], a2l[kc2][1], a2l[kc2][2], a2l[kc2][3], th[q][2], th[q][3]);
                    }
                }
            }
            if (pre) {
#pragma unroll
                for (int q = 0; q < 8; q++)
                    *(uint4*)(smc + NH + 16384 + sw_off(krow, kc0 + 8 * q)) =
                        *(const uint4*)(Klb + psrc + 8 * q);
            }
            __syncthreads();
        }

        {
            long long rbase = (long long)b * TT + (long long)R * 64 + w * 16 + (lane >> 2);
#pragma unroll
            for (int nf = 0; nf < 16; nf++) {
                int d = nf * 8 + 2 * (lane & 3);
                atomicAdd(O + rbase * DD + d,       Oc[nf][0]);
                atomicAdd(O + rbase * DD + d + 1,   Oc[nf][1]);
                atomicAdd(O + (rbase + 8) * DD + d,     Oc[nf][2]);
                atomicAdd(O + (rbase + 8) * DD + d + 1, Oc[nf][3]);
            }
        }
    }
}

// ---------------- depthwise causal conv ----------------
__global__ __launch_bounds__(512) void conv_kernel(const float* __restrict__ z,
                                                   const float* __restrict__ w,
                                                   const float* __restrict__ bias,
                                                   float* __restrict__ mf) {
    int d0 = threadIdx.x * 2;
    int t = blockIdx.x * 8 + threadIdx.y;
    int b = blockIdx.y;
    float2 bv = *(const float2*)(bias + d0);
    ull acc = pack2(bv.x, bv.y);
    int kstart = (KK - 1) - t;
    if (kstart < 0) kstart = 0;
    const float* zp = z + ((long long)b * TT + t - (KK - 1)) * DD + d0;
    const float* wp = w + d0;
#pragma unroll 4
    for (int k = kstart; k < KK; k++)
        fma2(acc, *(const ull*)(zp + (long long)k * DD), *(const ull*)(wp + (long long)k * DD));
    float2 res = unpk(acc);
    *(float2*)(mf + ((long long)b * TT + t) * DD + d0) = res;
}

// ---------------- group reduce (dual_gemm_norm) ----------------
__device__ __forceinline__ void group_reduce8(float v[8], float* red, int grp, int wig, int lane) {
#pragma unroll
    for (int k = 0; k < 8; k++) {
        float x = v[k];
#pragma unroll
        for (int o = 16; o; o >>= 1) x += __shfl_xor_sync(0xffffffffu, x, o);
        if (lane == 0) red[grp * 32 + wig * 8 + k] = x;
    }
    __syncthreads();
#pragma unroll
    for (int k = 0; k < 8; k++)
        v[k] = red[grp * 32 + k] + red[grp * 32 + 8 + k] + red[grp * 32 + 16 + k] +
               red[grp * 32 + 24 + k];
    __syncthreads();
}

__device__ __forceinline__ void matvec8(const float* Ws, const float* xg, int d, float bias,
                                        float tot[8]) {
    ull acc0 = dup2(bias), acc1 = dup2(bias), acc2 = dup2(bias), acc3 = dup2(bias);
#pragma unroll 4
    for (int j = 0; j < 128; j++) {
        ull w2 = dup2(Ws[j * 128 + d]);
        ulonglong2 x01 = *(const ulonglong2*)(xg + j * 8);
        ulonglong2 x23 = *(const ulonglong2*)(xg + j * 8 + 4);
        fma2(acc0, x01.x, w2);
        fma2(acc1, x01.y, w2);
        fma2(acc2, x23.x, w2);
        fma2(acc3, x23.y, w2);
    }
    float2 a0 = unpk(acc0), a1 = unpk(acc1), a2 = unpk(acc2), a3 = unpk(acc3);
    tot[0] = a0.x; tot[1] = a0.y; tot[2] = a1.x; tot[3] = a1.y;
    tot[4] = a2.x; tot[5] = a2.y; tot[6] = a3.x; tot[7] = a3.y;
}

#define DUAL_SMEM ((16384 + 16384 + 4096 + 128) * 4)

__global__ __launch_bounds__(512) void dual_gemm_norm(const float* __restrict__ X,
                                                      const float* __restrict__ W1,
                                                      const float* __restrict__ b1,
                                                      const float* __restrict__ W2,
                                                      const float* __restrict__ b2,
                                                      unsigned short* __restrict__ Y1h,
                                                      unsigned short* __restrict__ Y1l,
                                                      unsigned short* __restrict__ Y2h,
                                                      unsigned short* __restrict__ Y2l) {
    extern __shared__ float sm[];
    float* W1s = sm;
    float* W2s = sm + 16384;
    float* xp  = sm + 32768;
    float* red = sm + 36864;
    int tid = threadIdx.x, grp = tid >> 7, d = tid & 127, wig = (tid >> 5) & 3, lane = tid & 31;
    for (int i = tid; i < 16384; i += 512) { W1s[i] = W1[i]; W2s[i] = W2[i]; }
    float b1v = b1[d], b2v = b2[d];
    __syncthreads();
    long long row0 = (long long)blockIdx.x * 64 + grp * 16;
    float* xg = xp + grp * 1024;
    for (int gg = 0; gg < 16; gg += 8) {
#pragma unroll
        for (int k = 0; k < 8; k++)
            xg[d * 8 + k] = X[(row0 + gg + k) * DD + d];
        __syncthreads();
        float tot[8], v[8];
        matvec8(W1s, xg, d, b1v, tot);
#pragma unroll
        for (int k = 0; k < 8; k++) v[k] = tot[k] * tot[k];
        group_reduce8(v, red, grp, wig, lane);
#pragma unroll
        for (int k = 0; k < 8; k++) {
            float y = __fdividef(tot[k], fmaxf(sqrtf(v[k]), 1e-8f));
            uint16_t h;
            asm("cvt.rn.bf16.f32 %0, %1;" : "=h"(h) : "f"(y));
            float fh = __uint_as_float((uint32_t)h << 16);
            uint16_t l;
            asm("cvt.rn.bf16.f32 %0, %1;" : "=h"(l) : "f"(y - fh));
            long long off = (row0 + gg + k) * DD + d;
            Y1h[off] = h; Y1l[off] = l;
        }
        matvec8(W2s, xg, d, b2v, tot);
#pragma unroll
        for (int k = 0; k < 8; k++) v[k] = tot[k] * tot[k];
        group_reduce8(v, red, grp, wig, lane);
#pragma unroll
        for (int k = 0; k < 8; k++) {
            float y = __fdividef(tot[k], fmaxf(sqrtf(v[k]), 1e-8f));
            uint16_t h;
            asm("cvt.rn.bf16.f32 %0, %1;" : "=h"(h) : "f"(y));
            float fh = __uint_as_float((uint32_t)h << 16);
            uint16_t l;
            asm("cvt.rn.bf16.f32 %0, %1;" : "=h"(l) : "f"(y - fh));
            long long off = (row0 + gg + k) * DD + d;
            Y2h[off] = h; Y2l[off] = l;
        }
        __syncthreads();
    }
}

// ================== MMA epilogue: full W resident, sync-free GEMMs ==================
#define E_AH 0
#define E_AL 16384
#define E_WH 32768
#define E_WL 65536
#define E_RED 98304
#define EPI3_SMEM 98816

__global__ __launch_bounds__(256, 2) void epilogue_mma(
    float* __restrict__ A0,
    const unsigned short* __restrict__ Woh, const unsigned short* __restrict__ Wol,
    const float* __restrict__ bo,
    const unsigned short* __restrict__ Wqh, const unsigned short* __restrict__ Wql,
    const float* __restrict__ bq,
    const float* __restrict__ mf, const float* __restrict__ zin,
    const float* __restrict__ zbase, float* __restrict__ vacc,
    float* __restrict__ zc, unsigned short* __restrict__ qhh,
    unsigned short* __restrict__ qhl, float* __restrict__ out,
    float sw, float rc, int first, int has_next) {
    extern __shared__ char smc[];
    const uint32_t sbase = smem_u32(smc);
    float* red = (float*)(smc + E_RED);
    const int tid = threadIdx.x;
    const int lane = tid & 31, w = tid >> 5;
    const int wr = w & 3, whalf = w >> 2;
    const int ncol0 = whalf * 64;
    const int g = lane >> 3, r = lane & 7;
    const long long row0 = (long long)blockIdx.x * 64;
    const int rowL = wr * 16 + (lane >> 2);
    const long long gA = row0 + rowL;
    const long long gB = gA + 8;

    // stage A (fp32 -> bf16 hi/lo), zero a0 behind the read; copy full Wo planes
    const float4 z4 = make_float4(0.f, 0.f, 0.f, 0.f);
    for (int t = tid; t < 1024; t += 256) {
        int row = t >> 4, d0 = (t & 15) * 8;
        float* src = A0 + (row0 + row) * DD + d0;
        float4 a = *(const float4*)src;
        float4 b = *(const float4*)(src + 4);
        cvt_store8o(smc, E_AH, E_AL, row, d0, a, b);
        *(float4*)src = z4;
        *(float4*)(src + 4) = z4;
    }
    for (int t = tid; t < 2048; t += 256) {
        int row = t >> 4, d0 = (t & 15) * 8;
        uint32_t off = sw_off(row, d0);
        *(uint4*)(smc + E_WH + off) = *(const uint4*)(Woh + row * DD + d0);
        *(uint4*)(smc + E_WL + off) = *(const uint4*)(Wol + row * DD + d0);
    }
    __syncthreads();

    float C[8][4];
#pragma unroll
    for (int nf = 0; nf < 8; nf++)
#pragma unroll
        for (int e = 0; e < 4; e++) C[nf][e] = 0.f;

    // ---- GEMM1: C = A @ Wo ----
#pragma unroll
    for (int kc = 0; kc < 8; kc++) {
        uint32_t aoff = sw_off(wr * 16 + ((g & 1) ? 8 : 0) + r, kc * 16 + ((g >> 1) ? 8 : 0));
        uint32_t ah0, ah1, ah2, ah3, al0, al1, al2, al3;
        ldsm4(ah0, ah1, ah2, ah3, sbase + E_AH + aoff);
        ldsm4(al0, al1, al2, al3, sbase + E_AL + aoff);
        uint32_t th[4][4], tl[4][4];
#pragma unroll
        for (int nfp = 0; nfp < 4; nfp++) {
            uint32_t boff = sw_off(kc * 16 + ((g & 1) ? 8 : 0) + r,
                                   ncol0 + nfp * 16 + ((g >> 1) ? 8 : 0));
            ldsm4t(th[nfp][0], th[nfp][1], th[nfp][2], th[nfp][3], sbase + E_WH + boff);
            ldsm4t(tl[nfp][0], tl[nfp][1], tl[nfp][2], tl[nfp][3], sbase + E_WL + boff);
        }
#pragma unroll
        for (int nfp = 0; nfp < 4; nfp++) {
            mma16816(C[2 * nfp],     ah0, ah1, ah2, ah3, th[nfp][0], th[nfp][1]);
            mma16816(C[2 * nfp + 1], ah0, ah1, ah2, ah3, th[nfp][2], th[nfp][3]);
        }
#pragma unroll
        for (int nfp = 0; nfp < 4; nfp++) {
            mma16816(C[2 * nfp],     ah0, ah1, ah2, ah3, tl[nfp][0], tl[nfp][1]);
            mma16816(C[2 * nfp + 1], ah0, ah1, ah2, ah3, tl[nfp][2], tl[nfp][3]);
        }
#pragma unroll
        for (int nfp = 0; nfp < 4; nfp++) {
            mma16816(C[2 * nfp],     al0, al1, al2, al3, th[nfp][0], th[nfp][1]);
            mma16816(C[2 * nfp + 1], al0, al1, al2, al3, th[nfp][2], th[nfp][3]);
        }
    }

    // ---- bias + mf, tangent dot ----
    float dotA = 0.f, dotB = 0.f;
#pragma unroll
    for (int nf = 0; nf < 8; nf++) {
        int col = ncol0 + nf * 8 + 2 * (lane & 3);
        float2 bov = *(const float2*)(bo + col);
        float2 mA = *(const float2*)(mf + gA * DD + col);
        float2 mB = *(const float2*)(mf + gB * DD + col);
        C[nf][0] += bov.x + mA.x; C[nf][1] += bov.y + mA.y;
        C[nf][2] += bov.x + mB.x; C[nf][3] += bov.y + mB.y;
        float2 zA = *(const float2*)(zin + gA * DD + col);
        float2 zB = *(const float2*)(zin + gB * DD + col);
        dotA += C[nf][0] * zA.x + C[nf][1] * zA.y;
        dotB += C[nf][2] * zB.x + C[nf][3] * zB.y;
    }
    dotA += __shfl_xor_sync(0xffffffffu, dotA, 1);
    dotA += __shfl_xor_sync(0xffffffffu, dotA, 2);
    dotB += __shfl_xor_sync(0xffffffffu, dotB, 1);
    dotB += __shfl_xor_sync(0xffffffffu, dotB, 2);
    if ((lane & 3) == 0) {
        red[whalf * 64 + rowL] = dotA;
        red[whalf * 64 + rowL + 8] = dotB;
    }
    __syncthreads();
    dotA = red[rowL] + red[64 + rowL];
    dotB = red[rowL + 8] + red[64 + rowL + 8];
    __syncthreads();

    // ---- proj, vacc update, zn sumsq; load Wq into W buffer ----
    for (int t = tid; t < 2048; t += 256) {
        int row = t >> 4, d0 = (t & 15) * 8;
        uint32_t off = sw_off(row, d0);
        *(uint4*)(smc + E_WH + off) = *(const uint4*)(Wqh + row * DD + d0);
        *(uint4*)(smc + E_WL + off) = *(const uint4*)(Wql + row * DD + d0);
    }
    float ssA = 0.f, ssB = 0.f;
#pragma unroll
    for (int nf = 0; nf < 8; nf++) {
        int col = ncol0 + nf * 8 + 2 * (lane & 3);
        float2 zA = *(const float2*)(zin + gA * DD + col);
        float2 zB = *(const float2*)(zin + gB * DD + col);
        C[nf][0] -= dotA * zA.x; C[nf][1] -= dotA * zA.y;
        C[nf][2] -= dotB * zB.x; C[nf][3] -= dotB * zB.y;
        float2* vA = (float2*)(vacc + gA * DD + col);
        float2* vB = (float2*)(vacc + gB * DD + col);
        float2 vpA = first ? make_float2(0.f, 0.f) : *vA;
        float2 vpB = first ? make_float2(0.f, 0.f) : *vB;
        float2 vnA = make_float2(vpA.x + sw * C[nf][0], vpA.y + sw * C[nf][1]);
        float2 vnB = make_float2(vpB.x + sw * C[nf][2], vpB.y + sw * C[nf][3]);
        *vA = vnA; *vB = vnB;
        float2 zbA = *(const float2*)(zbase + gA * DD + col);
        float2 zbB = *(const float2*)(zbase + gB * DD + col);
        if (has_next) {
            float a0v = zbA.x + rc * C[nf][0], a1v = zbA.y + rc * C[nf][1];
            float b0v = zbB.x + rc * C[nf][2], b1v = zbB.y + rc * C[nf][3];
            ssA += a0v * a0v + a1v * a1v;
            ssB += b0v * b0v + b1v * b1v;
            C[nf][0] = a0v; C[nf][1] = a1v; C[nf][2] = b0v; C[nf][3] = b1v;
        } else {
            float a0v = zbA.x + vnA.x, a1v = zbA.y + vnA.y;
            float b0v = zbB.x + vnB.x, b1v = zbB.y + vnB.y;
            ssA += a0v * a0v + a1v * a1v;
            ssB += b0v * b0v + b1v * b1v;
            C[nf][0] = a0v; C[nf][1] = a1v; C[nf][2] = b0v; C[nf][3] = b1v;
        }
    }
    ssA += __shfl_xor_sync(0xffffffffu, ssA, 1);
    ssA += __shfl_xor_sync(0xffffffffu, ssA, 2);
    ssB += __shfl_xor_sync(0xffffffffu, ssB, 1);
    ssB += __shfl_xor_sync(0xffffffffu, ssB, 2);
    if ((lane & 3) == 0) {
        red[whalf * 64 + rowL] = ssA;
        red[whalf * 64 + rowL + 8] = ssB;
    }
    __syncthreads();
    ssA = red[rowL] + red[64 + rowL];
    ssB = red[rowL + 8] + red[64 + rowL + 8];
    __syncthreads();
    float invA = __fdividef(1.f, fmaxf(sqrtf(ssA), 1e-8f));
    float invB = __fdividef(1.f, fmaxf(sqrtf(ssB), 1e-8f));

    if (!has_next) {
#pragma unroll
        for (int nf = 0; nf < 8; nf++) {
            int col = ncol0 + nf * 8 + 2 * (lane & 3);
            *(float2*)(out + gA * DD + col) = make_float2(C[nf][0] * invA, C[nf][1] * invA);
            *(float2*)(out + gB * DD + col) = make_float2(C[nf][2] * invB, C[nf][3] * invB);
        }
        return;
    }

    // ---- z0 = norm(zbase + rc*proj): store zc + restage into A tile ----
#pragma unroll
    for (int nf = 0; nf < 8; nf++) {
        int col = ncol0 + nf * 8 + 2 * (lane & 3);
        float a0v = C[nf][0] * invA, a1v = C[nf][1] * invA;
        float b0v = C[nf][2] * invB, b1v = C[nf][3] * invB;
        *(float2*)(zc + gA * DD + col) = make_float2(a0v, a1v);
        *(float2*)(zc + gB * DD + col) = make_float2(b0v, b1v);
        uint32_t h, l;
        bsplit2(a0v, a1v, h, l);
        *(uint32_t*)(smc + E_AH + sw_off(rowL, col)) = h;
        *(uint32_t*)(smc + E_AL + sw_off(rowL, col)) = l;
        bsplit2(b0v, b1v, h, l);
        *(uint32_t*)(smc + E_AH + sw_off(rowL + 8, col)) = h;
        *(uint32_t*)(smc + E_AL + sw_off(rowL + 8, col)) = l;
    }
    __syncthreads();

    // ---- GEMM2: C = z0 @ Wq ----
#pragma unroll
    for (int nf = 0; nf < 8; nf++)
#pragma unroll
        for (int e = 0; e < 4; e++) C[nf][e] = 0.f;
#pragma unroll
    for (int kc = 0; kc < 8; kc++) {
        uint32_t aoff = sw_off(wr * 16 + ((g & 1) ? 8 : 0) + r, kc * 16 + ((g >> 1) ? 8 : 0));
        uint32_t ah0, ah1, ah2, ah3, al0, al1, al2, al3;
        ldsm4(ah0, ah1, ah2, ah3, sbase + E_AH + aoff);
        ldsm4(al0, al1, al2, al3, sbase + E_AL + aoff);
        uint32_t th[4][4], tl[4][4];
#pragma unroll
        for (int nfp = 0; nfp < 4; nfp++) {
            uint32_t boff = sw_off(kc * 16 + ((g & 1) ? 8 : 0) + r,
                                   ncol0 + nfp * 16 + ((g >> 1) ? 8 : 0));
            ldsm4t(th[nfp][0], th[nfp][1], th[nfp][2], th[nfp][3], sbase + E_WH + boff);
            ldsm4t(tl[nfp][0], tl[nfp][1], tl[nfp][2], tl[nfp][3], sbase + E_WL + boff);
        }
#pragma unroll
        for (int nfp = 0; nfp < 4; nfp++) {
            mma16816(C[2 * nfp],     ah0, ah1, ah2, ah3, th[nfp][0], th[nfp][1]);
            mma16816(C[2 * nfp + 1], ah0, ah1, ah2, ah3, th[nfp][2], th[nfp][3]);
        }
#pragma unroll
        for (int nfp = 0; nfp < 4; nfp++) {
            mma16816(C[2 * nfp],     ah0, ah1, ah2, ah3, tl[nfp][0], tl[nfp][1]);
            mma16816(C[2 * nfp + 1], ah0, ah1, ah2, ah3, tl[nfp][2], tl[nfp][3]);
        }
#pragma unroll
        for (int nfp = 0; nfp < 4; nfp++) {
            mma16816(C[2 * nfp],     al0, al1, al2, al3, th[nfp][0], th[nfp][1]);
            mma16816(C[2 * nfp + 1], al0, al1, al2, al3, th[nfp][2], th[nfp][3]);
        }
    }

    // ---- qh = norm(C + bq) -> prepacked bf16 hi/lo ----
    float qsA = 0.f, qsB = 0.f;
#pragma unroll
    for (int nf = 0; nf < 8; nf++) {
        int col = ncol0 + nf * 8 + 2 * (lane & 3);
        float2 bqv = *(const float2*)(bq + col);
        C[nf][0] += bqv.x; C[nf][1] += bqv.y;
        C[nf][2] += bqv.x; C[nf][3] += bqv.y;
        qsA += C[nf][0] * C[nf][0] + C[nf][1] * C[nf][1];
        qsB += C[nf][2] * C[nf][2] + C[nf][3] * C[nf][3];
    }
    qsA += __shfl_xor_sync(0xffffffffu, qsA, 1);
    qsA += __shfl_xor_sync(0xffffffffu, qsA, 2);
    qsB += __shfl_xor_sync(0xffffffffu, qsB, 1);
    qsB += __shfl_xor_sync(0xffffffffu, qsB, 2);
    if ((lane & 3) == 0) {
        red[whalf * 64 + rowL] = qsA;
        red[whalf * 64 + rowL + 8] = qsB;
    }
    __syncthreads();
    qsA = red[rowL] + red[64 + rowL];
    qsB = red[rowL + 8] + red[64 + rowL + 8];
    float qiA = __fdividef(1.f, fmaxf(sqrtf(qsA), 1e-8f));
    float qiB = __fdividef(1.f, fmaxf(sqrtf(qsB), 1e-8f));
#pragma unroll
    for (int nf = 0; nf < 8; nf++) {
        int col = ncol0 + nf * 8 + 2 * (lane & 3);
        uint32_t h, l;
        bsplit2(C[nf][0] * qiA, C[nf][1] * qiA, h, l);
        *(uint32_t*)(qhh + gA * DD + col) = h;
        *(uint32_t*)(qhl + gA * DD + col) = l;
        bsplit2(C[nf][2] * qiB, C[nf][3] * qiB, h, l);
        *(uint32_t*)(qhh + gB * DD + col) = h;
        *(uint32_t*)(qhl + gB * DD + col) = l;
    }
}

// ---------------- launch ----------------
extern "C" void kernel_launch(void* const* d_in, const int* in_sizes, int n_in,
                              void* d_out, int out_size) {
    const float* z  = (const float*)d_in[0];
    const float* ck = (const float*)d_in[1];
    const float* cb = (const float*)d_in[2];
    const float* Wq = (const float*)d_in[3];
    const float* bq = (const float*)d_in[4];
    const float* Wk = (const float*)d_in[5];
    const float* bk = (const float*)d_in[6];
    const float* Wo = (const float*)d_in[7];
    const float* bo = (const float*)d_in[8];
    float* out = (float*)d_out;

    float *mf, *a0, *zc, *va;
    unsigned short *qhh, *qhl, *khh, *khl, *woh, *wol, *wqh, *wql;
    cudaGetSymbolAddress((void**)&mf, g_mf);
    cudaGetSymbolAddress((void**)&a0, g_a0);
    cudaGetSymbolAddress((void**)&zc, g_zc);
    cudaGetSymbolAddress((void**)&va, g_va);
    cudaGetSymbolAddress((void**)&qhh, g_qhh);
    cudaGetSymbolAddress((void**)&qhl, g_qhl);
    cudaGetSymbolAddress((void**)&khh, g_khh);
    cudaGetSymbolAddress((void**)&khl, g_khl);
    cudaGetSymbolAddress((void**)&woh, g_woh);
    cudaGetSymbolAddress((void**)&wol, g_wol);
    cudaGetSymbolAddress((void**)&wqh, g_wqh);
    cudaGetSymbolAddress((void**)&wql, g_wql);

    cudaFuncSetAttribute(dual_gemm_norm, cudaFuncAttributeMaxDynamicSharedMemorySize, DUAL_SMEM);
    cudaFuncSetAttribute(epilogue_mma, cudaFuncAttributeMaxDynamicSharedMemorySize, EPI3_SMEM);
    cudaFuncSetAttribute(attn_kernel, cudaFuncAttributeMaxDynamicSharedMemorySize, ATTN_SMEM);

    prep_w<<<32, 256>>>(Wo, Wq, woh, wol, wqh, wql);
    conv_kernel<<<dim3(TT / 8, BB), dim3(64, 8)>>>(z, ck, cb, mf);
    dual_gemm_norm<<<BT / 64, 512, DUAL_SMEM>>>(z, Wk, bk, Wq, bq, khh, khl, qhh, qhl);

    const float sws[4] = {1.f / 6.f, 2.f / 6.f, 2.f / 6.f, 1.f / 6.f};
    const float rcs[4] = {0.5f, 0.5f, 1.0f, 0.f};
    const float* zcur = z;
    for (int s = 0; s < 4; s++) {
        // a0 is zero on entry (zero-init at load; epilogue re-zeroes after reading)
        attn_kernel<<<dim3(32, 9), 128, ATTN_SMEM>>>(qhh, qhl, khh, khl, a0);
        epilogue_mma<<<BT / 64, 256, EPI3_SMEM>>>(a0, woh, wol, bo, wqh, wql, bq,
                                                  mf, zcur, z, va, zc, qhh, qhl, out,
                                                  sws[s], rcs[s], s == 0 ? 1 : 0,
                                                  s < 3 ? 1 : 0);
        zcur = zc;
    }
}

// round 14
// speedup vs baseline: 1.0193x; 1.0193x over previous
#include <cuda_runtime.h>
#include <cstdint>

#define BB 2
#define TT 4096
#define DD 128
#define KK 256
#define BT (BB * TT)

// ---------------- scratch ----------------
__device__ float g_mf[BT * DD];
__device__ float g_a0[BT * DD];   // zero-initialized; invariant: zero between stages
__device__ float g_zc[BT * DD];
__device__ float g_va[BT * DD];
__device__ unsigned short g_qhh[BT * DD];
__device__ unsigned short g_qhl[BT * DD];
__device__ unsigned short g_khh[BT * DD];
__device__ unsigned short g_khl[BT * DD];
__device__ unsigned short g_woh[DD * DD];
__device__ unsigned short g_wol[DD * DD];
__device__ unsigned short g_wqh[DD * DD];
__device__ unsigned short g_wql[DD * DD];

// ================= helpers =================
typedef unsigned long long ull;
__device__ __forceinline__ uint32_t smem_u32(const void* p) {
    uint32_t a;
    asm("{ .reg .u64 t; cvta.to.shared.u64 t, %1; cvt.u32.u64 %0, t; }" : "=r"(a) : "l"(p));
    return a;
}
__device__ __forceinline__ void ldsm4(uint32_t& r0, uint32_t& r1, uint32_t& r2, uint32_t& r3,
                                      uint32_t addr) {
    asm volatile("ldmatrix.sync.aligned.m8n8.x4.shared.b16 {%0,%1,%2,%3}, [%4];"
                 : "=r"(r0), "=r"(r1), "=r"(r2), "=r"(r3) : "r"(addr));
}
__device__ __forceinline__ void ldsm4t(uint32_t& r0, uint32_t& r1, uint32_t& r2, uint32_t& r3,
                                       uint32_t addr) {
    asm volatile("ldmatrix.sync.aligned.m8n8.x4.trans.shared.b16 {%0,%1,%2,%3}, [%4];"
                 : "=r"(r0), "=r"(r1), "=r"(r2), "=r"(r3) : "r"(addr));
}
__device__ __forceinline__ void mma16816(float* c, uint32_t a0, uint32_t a1, uint32_t a2,
                                         uint32_t a3, uint32_t b0, uint32_t b1) {
    asm volatile(
        "mma.sync.aligned.m16n8k16.row.col.f32.bf16.bf16.f32 "
        "{%0,%1,%2,%3}, {%4,%5,%6,%7}, {%8,%9}, {%0,%1,%2,%3};"
        : "+f"(c[0]), "+f"(c[1]), "+f"(c[2]), "+f"(c[3])
        : "r"(a0), "r"(a1), "r"(a2), "r"(a3), "r"(b0), "r"(b1));
}
__device__ __forceinline__ void bsplit2(float x0, float x1, uint32_t& h, uint32_t& l) {
    uint16_t h0, h1, l0, l1;
    asm("cvt.rn.bf16.f32 %0, %1;" : "=h"(h0) : "f"(x0));
    asm("cvt.rn.bf16.f32 %0, %1;" : "=h"(h1) : "f"(x1));
    float f0 = __uint_as_float((uint32_t)h0 << 16);
    float f1 = __uint_as_float((uint32_t)h1 << 16);
    asm("cvt.rn.bf16.f32 %0, %1;" : "=h"(l0) : "f"(x0 - f0));
    asm("cvt.rn.bf16.f32 %0, %1;" : "=h"(l1) : "f"(x1 - f1));
    h = (uint32_t)h0 | ((uint32_t)h1 << 16);
    l = (uint32_t)l0 | ((uint32_t)l1 << 16);
}
__device__ __forceinline__ uint32_t sw_off(int row, int d) {
    return (uint32_t)(row * 256 + ((((d >> 3) ^ (row & 7)) & 15) << 4) + (d & 7) * 2);
}
__device__ __forceinline__ float sinpoly(float x) {
    float x2 = x * x;
    float pp = fmaf(x2, 2.7557319e-06f, -1.9841270e-04f);
    pp = fmaf(x2, pp, 8.3333333e-03f);
    pp = fmaf(x2, pp, -1.6666667e-01f);
    return fmaf(x * x2, pp, x);
}
__device__ __forceinline__ ull dup2(float x) {
    ull r; asm("mov.b64 %0, {%1, %1};" : "=l"(r) : "f"(x)); return r;
}
__device__ __forceinline__ ull pack2(float x, float y) {
    ull r; asm("mov.b64 %0, {%1, %2};" : "=l"(r) : "f"(x), "f"(y)); return r;
}
__device__ __forceinline__ void fma2(ull& d, ull a, ull b) {
    asm("fma.rn.f32x2 %0, %1, %2, %0;" : "+l"(d) : "l"(a), "l"(b));
}
__device__ __forceinline__ float2 unpk(ull v) {
    float2 r; asm("mov.b64 {%0, %1}, %2;" : "=f"(r.x), "=f"(r.y) : "l"(v)); return r;
}

__device__ __forceinline__ void cvt_store8o(char* smcp, uint32_t hoff, uint32_t loff,
                                            int row, int col, float4 a, float4 b) {
    uint32_t hw[4], lw[4];
    bsplit2(a.x, a.y, hw[0], lw[0]);
    bsplit2(a.z, a.w, hw[1], lw[1]);
    bsplit2(b.x, b.y, hw[2], lw[2]);
    bsplit2(b.z, b.w, hw[3], lw[3]);
    uint32_t off = sw_off(row, col);
    *(uint4*)(smcp + hoff + off) = make_uint4(hw[0], hw[1], hw[2], hw[3]);
    *(uint4*)(smcp + loff + off) = make_uint4(lw[0], lw[1], lw[2], lw[3]);
}

// ---------------- one-time W prepack ----------------
__global__ __launch_bounds__(256) void prep_w(const float* __restrict__ Wo,
                                              const float* __restrict__ Wq,
                                              unsigned short* __restrict__ Woh,
                                              unsigned short* __restrict__ Wol,
                                              unsigned short* __restrict__ Wqh,
                                              unsigned short* __restrict__ Wql) {
    int i = blockIdx.x * 256 + threadIdx.x;
    float2 a = *(const float2*)(Wo + 2 * i);
    uint32_t h, l;
    bsplit2(a.x, a.y, h, l);
    *(uint32_t*)(Woh + 2 * i) = h;
    *(uint32_t*)(Wol + 2 * i) = l;
    float2 b = *(const float2*)(Wq + 2 * i);
    bsplit2(b.x, b.y, h, l);
    *(uint32_t*)(Wqh + 2 * i) = h;
    *(uint32_t*)(Wql + 2 * i) = l;
}

// attn smem: Qhi 16K | Qlo 16K | K double-buffered (hi 16K + lo 16K) x2 = 96KB
#define QH_OFF 0
#define QL_OFF 16384
#define KBASE_OFF 32768
#define ATTN_SMEM 98304

// ---------------- causal sin-attention (R11 body, branch-free hot loop) ----------------
__global__ __launch_bounds__(128, 2) void attn_kernel(const unsigned short* __restrict__ Qhh,
                                                      const unsigned short* __restrict__ Qhl,
                                                      const unsigned short* __restrict__ Khh,
                                                      const unsigned short* __restrict__ Khl,
                                                      float* __restrict__ O) {
    extern __shared__ char smc[];
    const uint32_t sbase = smem_u32(smc);
    const int tid = threadIdx.x;
    const int lane = tid & 31, w = tid >> 5;
    const int P = blockIdx.x, split = blockIdx.y;
    const int g = lane >> 3, r = lane & 7;
    const int krow = tid >> 1, kc0 = (tid & 1) * 64;
    const int lo = (130 * split) / 9, hi = (130 * (split + 1)) / 9;

    int c = 0;
    for (int sp = 0; sp < 4; sp++) {
        const int b = sp >> 1;
        const int R = (sp & 1) ? (63 - P) : P;
        const int n = R + 1;
        int s_lo = lo - c; if (s_lo < 0) s_lo = 0;
        int s_hi = hi - c; if (s_hi > n) s_hi = n;
        c += n;
        if (s_lo >= s_hi) continue;

        const unsigned short* Qhb = Qhh + (long long)b * TT * DD;
        const unsigned short* Qlb = Qhl + (long long)b * TT * DD;
        const unsigned short* Khb = Khh + (long long)b * TT * DD;
        const unsigned short* Klb = Khl + (long long)b * TT * DD;

        __syncthreads();
        for (int t = tid; t < 1024; t += 128) {
            int row = t >> 4, d0 = (t & 15) * 8;
            long long src = ((long long)R * 64 + row) * DD + d0;
            uint32_t off = sw_off(row, d0);
            *(uint4*)(smc + QH_OFF + off) = *(const uint4*)(Qhb + src);
            *(uint4*)(smc + QL_OFF + off) = *(const uint4*)(Qlb + src);
        }
        {
            long long src = ((long long)s_lo * 64 + krow) * DD + kc0;
#pragma unroll
            for (int q = 0; q < 8; q++) {
                uint32_t off = sw_off(krow, kc0 + 8 * q);
                *(uint4*)(smc + KBASE_OFF + off) = *(const uint4*)(Khb + src + 8 * q);
                *(uint4*)(smc + KBASE_OFF + 16384 + off) = *(const uint4*)(Klb + src + 8 * q);
            }
        }
        float Oc[16][4];
#pragma unroll
        for (int nf = 0; nf < 16; nf++)
#pragma unroll
            for (int e = 0; e < 4; e++) Oc[nf][e] = 0.f;
        __syncthreads();

        // hoist Q A-frags (hi AND lo) into registers
        uint32_t qah[8][4], qal[8][4];
#pragma unroll
        for (int kc = 0; kc < 8; kc++) {
            uint32_t aoff = sw_off(w * 16 + ((g & 1) ? 8 : 0) + r, kc * 16 + ((g >> 1) ? 8 : 0));
            ldsm4(qah[kc][0], qah[kc][1], qah[kc][2], qah[kc][3], sbase + QH_OFF + aoff);
            ldsm4(qal[kc][0], qal[kc][1], qal[kc][2], qal[kc][3], sbase + QL_OFF + aoff);
        }

        for (int sb = s_lo; sb < s_hi; sb++) {
            const int cur = (sb - s_lo) & 1;
            const uint32_t KH = KBASE_OFF + (uint32_t)cur * 32768;
            const uint32_t KL = KH + 16384;
            const bool pre = (sb + 1 < s_hi);
            const uint32_t NH = KBASE_OFF + (uint32_t)(1 - cur) * 32768;
            long long psrc = ((long long)(sb + 1) * 64 + krow) * DD + kc0;

            float C[8][4];
#pragma unroll
            for (int nf = 0; nf < 8; nf++)
#pragma unroll
                for (int e = 0; e < 4; e++) C[nf][e] = 0.f;
#pragma unroll
            for (int kc = 0; kc < 8; kc++) {
                int d0 = kc * 16;
                uint32_t bh[4][4], bl[4][4];
#pragma unroll
                for (int nfp = 0; nfp < 4; nfp++) {
                    uint32_t boff = sw_off(nfp * 16 + ((g >> 1) ? 8 : 0) + r,
                                           d0 + ((g & 1) ? 8 : 0));
                    ldsm4(bh[nfp][0], bh[nfp][1], bh[nfp][2], bh[nfp][3], sbase + KH + boff);
                    ldsm4(bl[nfp][0], bl[nfp][1], bl[nfp][2], bl[nfp][3], sbase + KL + boff);
                }
#pragma unroll
                for (int nfp = 0; nfp < 4; nfp++) {
                    mma16816(C[2 * nfp],     qah[kc][0], qah[kc][1], qah[kc][2], qah[kc][3], bh[nfp][0], bh[nfp][1]);
                    mma16816(C[2 * nfp + 1], qah[kc][0], qah[kc][1], qah[kc][2], qah[kc][3], bh[nfp][2], bh[nfp][3]);
                }
#pragma unroll
                for (int nfp = 0; nfp < 4; nfp++) {
                    mma16816(C[2 * nfp],     qah[kc][0], qah[kc][1], qah[kc][2], qah[kc][3], bl[nfp][0], bl[nfp][1]);
                    mma16816(C[2 * nfp + 1], qah[kc][0], qah[kc][1], qah[kc][2], qah[kc][3], bl[nfp][2], bl[nfp][3]);
                }
#pragma unroll
                for (int nfp = 0; nfp < 4; nfp++) {
                    mma16816(C[2 * nfp],     qal[kc][0], qal[kc][1], qal[kc][2], qal[kc][3], bh[nfp][0], bh[nfp][1]);
                    mma16816(C[2 * nfp + 1], qal[kc][0], qal[kc][1], qal[kc][2], qal[kc][3], bh[nfp][2], bh[nfp][3]);
                }
            }
            if (pre) {
#pragma unroll
                for (int q = 0; q < 8; q++)
                    *(uint4*)(smc + NH + sw_off(krow, kc0 + 8 * q)) =
                        *(const uint4*)(Khb + psrc + 8 * q);
            }

            uint32_t a2h[4][4], a2l[4][4];
            const int ig = R * 64 + w * 16 + (lane >> 2);
#pragma unroll
            for (int nf = 0; nf < 8; nf++) {
                int jb = sb * 64 + nf * 8 + 2 * (lane & 3);
                float s0 = sinpoly(C[nf][0]); if (jb > ig) s0 = 0.f;
                float s1 = sinpoly(C[nf][1]); if (jb + 1 > ig) s1 = 0.f;
                float s2 = sinpoly(C[nf][2]); if (jb > ig + 8) s2 = 0.f;
                float s3 = sinpoly(C[nf][3]); if (jb + 1 > ig + 8) s3 = 0.f;
                int kc2 = nf >> 1, hk = (nf & 1) ? 2 : 0;
                bsplit2(s0, s1, a2h[kc2][hk], a2l[kc2][hk]);
                bsplit2(s2, s3, a2h[kc2][hk + 1], a2l[kc2][hk + 1]);
            }

#pragma unroll
            for (int kc2 = 0; kc2 < 4; kc2++) {
                int j0 = kc2 * 16;
#pragma unroll
                for (int hh = 0; hh < 2; hh++) {
                    uint32_t th[4][4], tl[4][4];
#pragma unroll
                    for (int q = 0; q < 4; q++) {
                        int nfp = hh * 4 + q;
                        uint32_t boff = sw_off(j0 + ((g & 1) ? 8 : 0) + r,
                                               nfp * 16 + ((g >> 1) ? 8 : 0));
                        ldsm4t(th[q][0], th[q][1], th[q][2], th[q][3], sbase + KH + boff);
                        ldsm4t(tl[q][0], tl[q][1], tl[q][2], tl[q][3], sbase + KL + boff);
                    }
#pragma unroll
                    for (int q = 0; q < 4; q++) {
                        int nfp = hh * 4 + q;
                        mma16816(Oc[2 * nfp],     a2h[kc2][0], a2h[kc2][1], a2h[kc2][2], a2h[kc2][3], th[q][0], th[q][1]);
                        mma16816(Oc[2 * nfp + 1], a2h[kc2][0], a2h[kc2][1], a2h[kc2][2], a2h[kc2][3], th[q][2], th[q][3]);
                    }
#pragma unroll
                    for (int q = 0; q < 4; q++) {
                        int nfp = hh * 4 + q;
                        mma16816(Oc[2 * nfp],     a2h[kc2][0], a2h[kc2][1], a2h[kc2][2], a2h[kc2][3], tl[q][0], tl[q][1]);
                        mma16816(Oc[2 * nfp + 1], a2h[kc2][0], a2h[kc2][1], a2h[kc2][2], a2h[kc2][3], tl[q][2], tl[q][3]);
                    }
#pragma unroll
                    for (int q = 0; q < 4; q++) {
                        int nfp = hh * 4 + q;
                        mma16816(Oc[2 * nfp],     a2l[kc2][0], a2l[kc2][1], a2l[kc2][2], a2l[kc2][3], th[q][0], th[q][1]);
                        mma16816(Oc[2 * nfp + 1], a2l[kc2][0], a2l[kc2][1], a2l[kc2][2], a2l[kc2][3], th[q][2], th[q][3]);
                    }
                }
            }
            if (pre) {
#pragma unroll
                for (int q = 0; q < 8; q++)
                    *(uint4*)(smc + NH + 16384 + sw_off(krow, kc0 + 8 * q)) =
                        *(const uint4*)(Klb + psrc + 8 * q);
            }
            __syncthreads();
        }

        {
            long long rbase = (long long)b * TT + (long long)R * 64 + w * 16 + (lane >> 2);
#pragma unroll
            for (int nf = 0; nf < 16; nf++) {
                int d = nf * 8 + 2 * (lane & 3);
                atomicAdd(O + rbase * DD + d,       Oc[nf][0]);
                atomicAdd(O + rbase * DD + d + 1,   Oc[nf][1]);
                atomicAdd(O + (rbase + 8) * DD + d,     Oc[nf][2]);
                atomicAdd(O + (rbase + 8) * DD + d + 1, Oc[nf][3]);
            }
        }
    }
}

// ---------------- depthwise causal conv ----------------
__global__ __launch_bounds__(512) void conv_kernel(const float* __restrict__ z,
                                                   const float* __restrict__ w,
                                                   const float* __restrict__ bias,
                                                   float* __restrict__ mf) {
    int d0 = threadIdx.x * 2;
    int t = blockIdx.x * 8 + threadIdx.y;
    int b = blockIdx.y;
    float2 bv = *(const float2*)(bias + d0);
    ull acc = pack2(bv.x, bv.y);
    int kstart = (KK - 1) - t;
    if (kstart < 0) kstart = 0;
    const float* zp = z + ((long long)b * TT + t - (KK - 1)) * DD + d0;
    const float* wp = w + d0;
#pragma unroll 4
    for (int k = kstart; k < KK; k++)
        fma2(acc, *(const ull*)(zp + (long long)k * DD), *(const ull*)(wp + (long long)k * DD));
    float2 res = unpk(acc);
    *(float2*)(mf + ((long long)b * TT + t) * DD + d0) = res;
}

// ---------------- group reduce (dual_gemm_norm) ----------------
__device__ __forceinline__ void group_reduce8(float v[8], float* red, int grp, int wig, int lane) {
#pragma unroll
    for (int k = 0; k < 8; k++) {
        float x = v[k];
#pragma unroll
        for (int o = 16; o; o >>= 1) x += __shfl_xor_sync(0xffffffffu, x, o);
        if (lane == 0) red[grp * 32 + wig * 8 + k] = x;
    }
    __syncthreads();
#pragma unroll
    for (int k = 0; k < 8; k++)
        v[k] = red[grp * 32 + k] + red[grp * 32 + 8 + k] + red[grp * 32 + 16 + k] +
               red[grp * 32 + 24 + k];
    __syncthreads();
}

__device__ __forceinline__ void matvec8(const float* Ws, const float* xg, int d, float bias,
                                        float tot[8]) {
    ull acc0 = dup2(bias), acc1 = dup2(bias), acc2 = dup2(bias), acc3 = dup2(bias);
#pragma unroll 4
    for (int j = 0; j < 128; j++) {
        ull w2 = dup2(Ws[j * 128 + d]);
        ulonglong2 x01 = *(const ulonglong2*)(xg + j * 8);
        ulonglong2 x23 = *(const ulonglong2*)(xg + j * 8 + 4);
        fma2(acc0, x01.x, w2);
        fma2(acc1, x01.y, w2);
        fma2(acc2, x23.x, w2);
        fma2(acc3, x23.y, w2);
    }
    float2 a0 = unpk(acc0), a1 = unpk(acc1), a2 = unpk(acc2), a3 = unpk(acc3);
    tot[0] = a0.x; tot[1] = a0.y; tot[2] = a1.x; tot[3] = a1.y;
    tot[4] = a2.x; tot[5] = a2.y; tot[6] = a3.x; tot[7] = a3.y;
}

#define DUAL_SMEM ((16384 + 16384 + 4096 + 128) * 4)

__global__ __launch_bounds__(512) void dual_gemm_norm(const float* __restrict__ X,
                                                      const float* __restrict__ W1,
                                                      const float* __restrict__ b1,
                                                      const float* __restrict__ W2,
                                                      const float* __restrict__ b2,
                                                      unsigned short* __restrict__ Y1h,
                                                      unsigned short* __restrict__ Y1l,
                                                      unsigned short* __restrict__ Y2h,
                                                      unsigned short* __restrict__ Y2l) {
    extern __shared__ float sm[];
    float* W1s = sm;
    float* W2s = sm + 16384;
    float* xp  = sm + 32768;
    float* red = sm + 36864;
    int tid = threadIdx.x, grp = tid >> 7, d = tid & 127, wig = (tid >> 5) & 3, lane = tid & 31;
    for (int i = tid; i < 16384; i += 512) { W1s[i] = W1[i]; W2s[i] = W2[i]; }
    float b1v = b1[d], b2v = b2[d];
    __syncthreads();
    long long row0 = (long long)blockIdx.x * 64 + grp * 16;
    float* xg = xp + grp * 1024;
    for (int gg = 0; gg < 16; gg += 8) {
#pragma unroll
        for (int k = 0; k < 8; k++)
            xg[d * 8 + k] = X[(row0 + gg + k) * DD + d];
        __syncthreads();
        float tot[8], v[8];
        matvec8(W1s, xg, d, b1v, tot);
#pragma unroll
        for (int k = 0; k < 8; k++) v[k] = tot[k] * tot[k];
        group_reduce8(v, red, grp, wig, lane);
#pragma unroll
        for (int k = 0; k < 8; k++) {
            float y = __fdividef(tot[k], fmaxf(sqrtf(v[k]), 1e-8f));
            uint16_t h;
            asm("cvt.rn.bf16.f32 %0, %1;" : "=h"(h) : "f"(y));
            float fh = __uint_as_float((uint32_t)h << 16);
            uint16_t l;
            asm("cvt.rn.bf16.f32 %0, %1;" : "=h"(l) : "f"(y - fh));
            long long off = (row0 + gg + k) * DD + d;
            Y1h[off] = h; Y1l[off] = l;
        }
        matvec8(W2s, xg, d, b2v, tot);
#pragma unroll
        for (int k = 0; k < 8; k++) v[k] = tot[k] * tot[k];
        group_reduce8(v, red, grp, wig, lane);
#pragma unroll
        for (int k = 0; k < 8; k++) {
            float y = __fdividef(tot[k], fmaxf(sqrtf(v[k]), 1e-8f));
            uint16_t h;
            asm("cvt.rn.bf16.f32 %0, %1;" : "=h"(h) : "f"(y));
            float fh = __uint_as_float((uint32_t)h << 16);
            uint16_t l;
            asm("cvt.rn.bf16.f32 %0, %1;" : "=h"(l) : "f"(y - fh));
            long long off = (row0 + gg + k) * DD + d;
            Y2h[off] = h; Y2l[off] = l;
        }
        __syncthreads();
    }
}

// ================== MMA epilogue: full W resident, sync-free GEMMs ==================
#define E_AH 0
#define E_AL 16384
#define E_WH 32768
#define E_WL 65536
#define E_RED 98304
#define EPI3_SMEM 98816

__global__ __launch_bounds__(256, 2) void epilogue_mma(
    float* __restrict__ A0,
    const unsigned short* __restrict__ Woh, const unsigned short* __restrict__ Wol,
    const float* __restrict__ bo,
    const unsigned short* __restrict__ Wqh, const unsigned short* __restrict__ Wql,
    const float* __restrict__ bq,
    const float* __restrict__ mf, const float* __restrict__ zin,
    const float* __restrict__ zbase, float* __restrict__ vacc,
    float* __restrict__ zc, unsigned short* __restrict__ qhh,
    unsigned short* __restrict__ qhl, float* __restrict__ out,
    float sw, float rc, int first, int has_next) {
    extern __shared__ char smc[];
    const uint32_t sbase = smem_u32(smc);
    float* red = (float*)(smc + E_RED);
    const int tid = threadIdx.x;
    const int lane = tid & 31, w = tid >> 5;
    const int wr = w & 3, whalf = w >> 2;
    const int ncol0 = whalf * 64;
    const int g = lane >> 3, r = lane & 7;
    const long long row0 = (long long)blockIdx.x * 64;
    const int rowL = wr * 16 + (lane >> 2);
    const long long gA = row0 + rowL;
    const long long gB = gA + 8;

    // stage A (fp32 -> bf16 hi/lo), zero a0 behind the read; copy full Wo planes
    const float4 z4 = make_float4(0.f, 0.f, 0.f, 0.f);
    for (int t = tid; t < 1024; t += 256) {
        int row = t >> 4, d0 = (t & 15) * 8;
        float* src = A0 + (row0 + row) * DD + d0;
        float4 a = *(const float4*)src;
        float4 b = *(const float4*)(src + 4);
        cvt_store8o(smc, E_AH, E_AL, row, d0, a, b);
        *(float4*)src = z4;
        *(float4*)(src + 4) = z4;
    }
    for (int t = tid; t < 2048; t += 256) {
        int row = t >> 4, d0 = (t & 15) * 8;
        uint32_t off = sw_off(row, d0);
        *(uint4*)(smc + E_WH + off) = *(const uint4*)(Woh + row * DD + d0);
        *(uint4*)(smc + E_WL + off) = *(const uint4*)(Wol + row * DD + d0);
    }
    __syncthreads();

    float C[8][4];
#pragma unroll
    for (int nf = 0; nf < 8; nf++)
#pragma unroll
        for (int e = 0; e < 4; e++) C[nf][e] = 0.f;

    // ---- GEMM1: C = A @ Wo ----
#pragma unroll
    for (int kc = 0; kc < 8; kc++) {
        uint32_t aoff = sw_off(wr * 16 + ((g & 1) ? 8 : 0) + r, kc * 16 + ((g >> 1) ? 8 : 0));
        uint32_t ah0, ah1, ah2, ah3, al0, al1, al2, al3;
        ldsm4(ah0, ah1, ah2, ah3, sbase + E_AH + aoff);
        ldsm4(al0, al1, al2, al3, sbase + E_AL + aoff);
        uint32_t th[4][4], tl[4][4];
#pragma unroll
        for (int nfp = 0; nfp < 4; nfp++) {
            uint32_t boff = sw_off(kc * 16 + ((g & 1) ? 8 : 0) + r,
                                   ncol0 + nfp * 16 + ((g >> 1) ? 8 : 0));
            ldsm4t(th[nfp][0], th[nfp][1], th[nfp][2], th[nfp][3], sbase + E_WH + boff);
            ldsm4t(tl[nfp][0], tl[nfp][1], tl[nfp][2], tl[nfp][3], sbase + E_WL + boff);
        }
#pragma unroll
        for (int nfp = 0; nfp < 4; nfp++) {
            mma16816(C[2 * nfp],     ah0, ah1, ah2, ah3, th[nfp][0], th[nfp][1]);
            mma16816(C[2 * nfp + 1], ah0, ah1, ah2, ah3, th[nfp][2], th[nfp][3]);
        }
#pragma unroll
        for (int nfp = 0; nfp < 4; nfp++) {
            mma16816(C[2 * nfp],     ah0, ah1, ah2, ah3, tl[nfp][0], tl[nfp][1]);
            mma16816(C[2 * nfp + 1], ah0, ah1, ah2, ah3, tl[nfp][2], tl[nfp][3]);
        }
#pragma unroll
        for (int nfp = 0; nfp < 4; nfp++) {
            mma16816(C[2 * nfp],     al0, al1, al2, al3, th[nfp][0], th[nfp][1]);
            mma16816(C[2 * nfp + 1], al0, al1, al2, al3, th[nfp][2], th[nfp][3]);
        }
    }

    // ---- bias + mf, tangent dot ----
    float dotA = 0.f, dotB = 0.f;
#pragma unroll
    for (int nf = 0; nf < 8; nf++) {
        int col = ncol0 + nf * 8 + 2 * (lane & 3);
        float2 bov = *(const float2*)(bo + col);
        float2 mA = *(const float2*)(mf + gA * DD + col);
        float2 mB = *(const float2*)(mf + gB * DD + col);
        C[nf][0] += bov.x + mA.x; C[nf][1] += bov.y + mA.y;
        C[nf][2] += bov.x + mB.x; C[nf][3] += bov.y + mB.y;
        float2 zA = *(const float2*)(zin + gA * DD + col);
        float2 zB = *(const float2*)(zin + gB * DD + col);
        dotA += C[nf][0] * zA.x + C[nf][1] * zA.y;
        dotB += C[nf][2] * zB.x + C[nf][3] * zB.y;
    }
    dotA += __shfl_xor_sync(0xffffffffu, dotA, 1);
    dotA += __shfl_xor_sync(0xffffffffu, dotA, 2);
    dotB += __shfl_xor_sync(0xffffffffu, dotB, 1);
    dotB += __shfl_xor_sync(0xffffffffu, dotB, 2);
    if ((lane & 3) == 0) {
        red[whalf * 64 + rowL] = dotA;
        red[whalf * 64 + rowL + 8] = dotB;
    }
    __syncthreads();
    dotA = red[rowL] + red[64 + rowL];
    dotB = red[rowL + 8] + red[64 + rowL + 8];
    __syncthreads();

    // ---- proj, vacc update, zn sumsq; load Wq into W buffer ----
    for (int t = tid; t < 2048; t += 256) {
        int row = t >> 4, d0 = (t & 15) * 8;
        uint32_t off = sw_off(row, d0);
        *(uint4*)(smc + E_WH + off) = *(const uint4*)(Wqh + row * DD + d0);
        *(uint4*)(smc + E_WL + off) = *(const uint4*)(Wql + row * DD + d0);
    }
    float ssA = 0.f, ssB = 0.f;
#pragma unroll
    for (int nf = 0; nf < 8; nf++) {
        int col = ncol0 + nf * 8 + 2 * (lane & 3);
        float2 zA = *(const float2*)(zin + gA * DD + col);
        float2 zB = *(const float2*)(zin + gB * DD + col);
        C[nf][0] -= dotA * zA.x; C[nf][1] -= dotA * zA.y;
        C[nf][2] -= dotB * zB.x; C[nf][3] -= dotB * zB.y;
        float2* vA = (float2*)(vacc + gA * DD + col);
        float2* vB = (float2*)(vacc + gB * DD + col);
        float2 vpA = first ? make_float2(0.f, 0.f) : *vA;
        float2 vpB = first ? make_float2(0.f, 0.f) : *vB;
        float2 vnA = make_float2(vpA.x + sw * C[nf][0], vpA.y + sw * C[nf][1]);
        float2 vnB = make_float2(vpB.x + sw * C[nf][2], vpB.y + sw * C[nf][3]);
        *vA = vnA; *vB = vnB;
        float2 zbA = *(const float2*)(zbase + gA * DD + col);
        float2 zbB = *(const float2*)(zbase + gB * DD + col);
        if (has_next) {
            float a0v = zbA.x + rc * C[nf][0], a1v = zbA.y + rc * C[nf][1];
            float b0v = zbB.x + rc * C[nf][2], b1v = zbB.y + rc * C[nf][3];
            ssA += a0v * a0v + a1v * a1v;
            ssB += b0v * b0v + b1v * b1v;
            C[nf][0] = a0v; C[nf][1] = a1v; C[nf][2] = b0v; C[nf][3] = b1v;
        } else {
            float a0v = zbA.x + vnA.x, a1v = zbA.y + vnA.y;
            float b0v = zbB.x + vnB.x, b1v = zbB.y + vnB.y;
            ssA += a0v * a0v + a1v * a1v;
            ssB += b0v * b0v + b1v * b1v;
            C[nf][0] = a0v; C[nf][1] = a1v; C[nf][2] = b0v; C[nf][3] = b1v;
        }
    }
    ssA += __shfl_xor_sync(0xffffffffu, ssA, 1);
    ssA += __shfl_xor_sync(0xffffffffu, ssA, 2);
    ssB += __shfl_xor_sync(0xffffffffu, ssB, 1);
    ssB += __shfl_xor_sync(0xffffffffu, ssB, 2);
    if ((lane & 3) == 0) {
        red[whalf * 64 + rowL] = ssA;
        red[whalf * 64 + rowL + 8] = ssB;
    }
    __syncthreads();
    ssA = red[rowL] + red[64 + rowL];
    ssB = red[rowL + 8] + red[64 + rowL + 8];
    __syncthreads();
    float invA = __fdividef(1.f, fmaxf(sqrtf(ssA), 1e-8f));
    float invB = __fdividef(1.f, fmaxf(sqrtf(ssB), 1e-8f));

    if (!has_next) {
#pragma unroll
        for (int nf = 0; nf < 8; nf++) {
            int col = ncol0 + nf * 8 + 2 * (lane & 3);
            *(float2*)(out + gA * DD + col) = make_float2(C[nf][0] * invA, C[nf][1] * invA);
            *(float2*)(out + gB * DD + col) = make_float2(C[nf][2] * invB, C[nf][3] * invB);
        }
        return;
    }

    // ---- z0 = norm(zbase + rc*proj): store zc + restage into A tile ----
#pragma unroll
    for (int nf = 0; nf < 8; nf++) {
        int col = ncol0 + nf * 8 + 2 * (lane & 3);
        float a0v = C[nf][0] * invA, a1v = C[nf][1] * invA;
        float b0v = C[nf][2] * invB, b1v = C[nf][3] * invB;
        *(float2*)(zc + gA * DD + col) = make_float2(a0v, a1v);
        *(float2*)(zc + gB * DD + col) = make_float2(b0v, b1v);
        uint32_t h, l;
        bsplit2(a0v, a1v, h, l);
        *(uint32_t*)(smc + E_AH + sw_off(rowL, col)) = h;
        *(uint32_t*)(smc + E_AL + sw_off(rowL, col)) = l;
        bsplit2(b0v, b1v, h, l);
        *(uint32_t*)(smc + E_AH + sw_off(rowL + 8, col)) = h;
        *(uint32_t*)(smc + E_AL + sw_off(rowL + 8, col)) = l;
    }
    __syncthreads();

    // ---- GEMM2: C = z0 @ Wq ----
#pragma unroll
    for (int nf = 0; nf < 8; nf++)
#pragma unroll
        for (int e = 0; e < 4; e++) C[nf][e] = 0.f;
#pragma unroll
    for (int kc = 0; kc < 8; kc++) {
        uint32_t aoff = sw_off(wr * 16 + ((g & 1) ? 8 : 0) + r, kc * 16 + ((g >> 1) ? 8 : 0));
        uint32_t ah0, ah1, ah2, ah3, al0, al1, al2, al3;
        ldsm4(ah0, ah1, ah2, ah3, sbase + E_AH + aoff);
        ldsm4(al0, al1, al2, al3, sbase + E_AL + aoff);
        uint32_t th[4][4], tl[4][4];
#pragma unroll
        for (int nfp = 0; nfp < 4; nfp++) {
            uint32_t boff = sw_off(kc * 16 + ((g & 1) ? 8 : 0) + r,
                                   ncol0 + nfp * 16 + ((g >> 1) ? 8 : 0));
            ldsm4t(th[nfp][0], th[nfp][1], th[nfp][2], th[nfp][3], sbase + E_WH + boff);
            ldsm4t(tl[nfp][0], tl[nfp][1], tl[nfp][2], tl[nfp][3], sbase + E_WL + boff);
        }
#pragma unroll
        for (int nfp = 0; nfp < 4; nfp++) {
            mma16816(C[2 * nfp],     ah0, ah1, ah2, ah3, th[nfp][0], th[nfp][1]);
            mma16816(C[2 * nfp + 1], ah0, ah1, ah2, ah3, th[nfp][2], th[nfp][3]);
        }
#pragma unroll
        for (int nfp = 0; nfp < 4; nfp++) {
            mma16816(C[2 * nfp],     ah0, ah1, ah2, ah3, tl[nfp][0], tl[nfp][1]);
            mma16816(C[2 * nfp + 1], ah0, ah1, ah2, ah3, tl[nfp][2], tl[nfp][3]);
        }
#pragma unroll
        for (int nfp = 0; nfp < 4; nfp++) {
            mma16816(C[2 * nfp],     al0, al1, al2, al3, th[nfp][0], th[nfp][1]);
            mma16816(C[2 * nfp + 1], al0, al1, al2, al3, th[nfp][2], th[nfp][3]);
        }
    }

    // ---- qh = norm(C + bq) -> prepacked bf16 hi/lo ----
    float qsA = 0.f, qsB = 0.f;
#pragma unroll
    for (int nf = 0; nf < 8; nf++) {
        int col = ncol0 + nf * 8 + 2 * (lane & 3);
        float2 bqv = *(const float2*)(bq + col);
        C[nf][0] += bqv.x; C[nf][1] += bqv.y;
        C[nf][2] += bqv.x; C[nf][3] += bqv.y;
        qsA += C[nf][0] * C[nf][0] + C[nf][1] * C[nf][1];
        qsB += C[nf][2] * C[nf][2] + C[nf][3] * C[nf][3];
    }
    qsA += __shfl_xor_sync(0xffffffffu, qsA, 1);
    qsA += __shfl_xor_sync(0xffffffffu, qsA, 2);
    qsB += __shfl_xor_sync(0xffffffffu, qsB, 1);
    qsB += __shfl_xor_sync(0xffffffffu, qsB, 2);
    if ((lane & 3) == 0) {
        red[whalf * 64 + rowL] = qsA;
        red[whalf * 64 + rowL + 8] = qsB;
    }
    __syncthreads();
    qsA = red[rowL] + red[64 + rowL];
    qsB = red[rowL + 8] + red[64 + rowL + 8];
    float qiA = __fdividef(1.f, fmaxf(sqrtf(qsA), 1e-8f));
    float qiB = __fdividef(1.f, fmaxf(sqrtf(qsB), 1e-8f));
#pragma unroll
    for (int nf = 0; nf < 8; nf++) {
        int col = ncol0 + nf * 8 + 2 * (lane & 3);
        uint32_t h, l;
        bsplit2(C[nf][0] * qiA, C[nf][1] * qiA, h, l);
        *(uint32_t*)(qhh + gA * DD + col) = h;
        *(uint32_t*)(qhl + gA * DD + col) = l;
        bsplit2(C[nf][2] * qiB, C[nf][3] * qiB, h, l);
        *(uint32_t*)(qhh + gB * DD + col) = h;
        *(uint32_t*)(qhl + gB * DD + col) = l;
    }
}

// ---------------- launch ----------------
extern "C" void kernel_launch(void* const* d_in, const int* in_sizes, int n_in,
                              void* d_out, int out_size) {
    const float* z  = (const float*)d_in[0];
    const float* ck = (const float*)d_in[1];
    const float* cb = (const float*)d_in[2];
    const float* Wq = (const float*)d_in[3];
    const float* bq = (const float*)d_in[4];
    const float* Wk = (const float*)d_in[5];
    const float* bk = (const float*)d_in[6];
    const float* Wo = (const float*)d_in[7];
    const float* bo = (const float*)d_in[8];
    float* out = (float*)d_out;

    float *mf, *a0, *zc, *va;
    unsigned short *qhh, *qhl, *khh, *khl, *woh, *wol, *wqh, *wql;
    cudaGetSymbolAddress((void**)&mf, g_mf);
    cudaGetSymbolAddress((void**)&a0, g_a0);
    cudaGetSymbolAddress((void**)&zc, g_zc);
    cudaGetSymbolAddress((void**)&va, g_va);
    cudaGetSymbolAddress((void**)&qhh, g_qhh);
    cudaGetSymbolAddress((void**)&qhl, g_qhl);
    cudaGetSymbolAddress((void**)&khh, g_khh);
    cudaGetSymbolAddress((void**)&khl, g_khl);
    cudaGetSymbolAddress((void**)&woh, g_woh);
    cudaGetSymbolAddress((void**)&wol, g_wol);
    cudaGetSymbolAddress((void**)&wqh, g_wqh);
    cudaGetSymbolAddress((void**)&wql, g_wql);

    cudaFuncSetAttribute(dual_gemm_norm, cudaFuncAttributeMaxDynamicSharedMemorySize, DUAL_SMEM);
    cudaFuncSetAttribute(epilogue_mma, cudaFuncAttributeMaxDynamicSharedMemorySize, EPI3_SMEM);
    cudaFuncSetAttribute(attn_kernel, cudaFuncAttributeMaxDynamicSharedMemorySize, ATTN_SMEM);

    prep_w<<<32, 256>>>(Wo, Wq, woh, wol, wqh, wql);
    conv_kernel<<<dim3(TT / 8, BB), dim3(64, 8)>>>(z, ck, cb, mf);
    dual_gemm_norm<<<BT / 64, 512, DUAL_SMEM>>>(z, Wk, bk, Wq, bq, khh, khl, qhh, qhl);

    const float sws[4] = {1.f / 6.f, 2.f / 6.f, 2.f / 6.f, 1.f / 6.f};
    const float rcs[4] = {0.5f, 0.5f, 1.0f, 0.f};
    const float* zcur = z;
    for (int s = 0; s < 4; s++) {
        // a0 is zero on entry (zero-init at load; epilogue re-zeroes after reading)
        attn_kernel<<<dim3(32, 9), 128, ATTN_SMEM>>>(qhh, qhl, khh, khl, a0);
        epilogue_mma<<<BT / 64, 256, EPI3_SMEM>>>(a0, woh, wol, bo, wqh, wql, bq,
                                                  mf, zcur, z, va, zc, qhh, qhl, out,
                                                  sws[s], rcs[s], s == 0 ? 1 : 0,
                                                  s < 3 ? 1 : 0);
        zcur = zc;
    }
}

// round 15
// speedup vs baseline: 1.0682x; 1.0479x over previous
#include <cuda_runtime.h>
#include <cstdint>

#define BB 2
#define TT 4096
#define DD 128
#define KK 256
#define BT (BB * TT)

// ---------------- scratch ----------------
__device__ float g_mf[BT * DD];
__device__ float g_a0[BT * DD];
__device__ float g_zc[BT * DD];
__device__ float g_va[BT * DD];
__device__ unsigned short g_qhh[BT * DD];
__device__ unsigned short g_qhl[BT * DD];
__device__ unsigned short g_khh[BT * DD];
__device__ unsigned short g_khl[BT * DD];
__device__ unsigned short g_woh[DD * DD];
__device__ unsigned short g_wol[DD * DD];
__device__ unsigned short g_wqh[DD * DD];
__device__ unsigned short g_wql[DD * DD];
__device__ unsigned short g_wkh[DD * DD];
__device__ unsigned short g_wkl[DD * DD];

// ================= helpers =================
typedef unsigned long long ull;
__device__ __forceinline__ uint32_t smem_u32(const void* p) {
    uint32_t a;
    asm("{ .reg .u64 t; cvta.to.shared.u64 t, %1; cvt.u32.u64 %0, t; }" : "=r"(a) : "l"(p));
    return a;
}
__device__ __forceinline__ void ldsm4(uint32_t& r0, uint32_t& r1, uint32_t& r2, uint32_t& r3,
                                      uint32_t addr) {
    asm volatile("ldmatrix.sync.aligned.m8n8.x4.shared.b16 {%0,%1,%2,%3}, [%4];"
                 : "=r"(r0), "=r"(r1), "=r"(r2), "=r"(r3) : "r"(addr));
}
__device__ __forceinline__ void ldsm4t(uint32_t& r0, uint32_t& r1, uint32_t& r2, uint32_t& r3,
                                       uint32_t addr) {
    asm volatile("ldmatrix.sync.aligned.m8n8.x4.trans.shared.b16 {%0,%1,%2,%3}, [%4];"
                 : "=r"(r0), "=r"(r1), "=r"(r2), "=r"(r3) : "r"(addr));
}
__device__ __forceinline__ void mma16816(float* c, uint32_t a0, uint32_t a1, uint32_t a2,
                                         uint32_t a3, uint32_t b0, uint32_t b1) {
    asm volatile(
        "mma.sync.aligned.m16n8k16.row.col.f32.bf16.bf16.f32 "
        "{%0,%1,%2,%3}, {%4,%5,%6,%7}, {%8,%9}, {%0,%1,%2,%3};"
        : "+f"(c[0]), "+f"(c[1]), "+f"(c[2]), "+f"(c[3])
        : "r"(a0), "r"(a1), "r"(a2), "r"(a3), "r"(b0), "r"(b1));
}
__device__ __forceinline__ void bsplit2(float x0, float x1, uint32_t& h, uint32_t& l) {
    uint16_t h0, h1, l0, l1;
    asm("cvt.rn.bf16.f32 %0, %1;" : "=h"(h0) : "f"(x0));
    asm("cvt.rn.bf16.f32 %0, %1;" : "=h"(h1) : "f"(x1));
    float f0 = __uint_as_float((uint32_t)h0 << 16);
    float f1 = __uint_as_float((uint32_t)h1 << 16);
    asm("cvt.rn.bf16.f32 %0, %1;" : "=h"(l0) : "f"(x0 - f0));
    asm("cvt.rn.bf16.f32 %0, %1;" : "=h"(l1) : "f"(x1 - f1));
    h = (uint32_t)h0 | ((uint32_t)h1 << 16);
    l = (uint32_t)l0 | ((uint32_t)l1 << 16);
}
__device__ __forceinline__ uint32_t sw_off(int row, int d) {
    return (uint32_t)(row * 256 + ((((d >> 3) ^ (row & 7)) & 15) << 4) + (d & 7) * 2);
}
__device__ __forceinline__ float sinpoly(float x) {
    float x2 = x * x;
    float pp = fmaf(x2, 2.7557319e-06f, -1.9841270e-04f);
    pp = fmaf(x2, pp, 8.3333333e-03f);
    pp = fmaf(x2, pp, -1.6666667e-01f);
    return fmaf(x * x2, pp, x);
}
__device__ __forceinline__ ull pack2(float x, float y) {
    ull r; asm("mov.b64 %0, {%1, %2};" : "=l"(r) : "f"(x), "f"(y)); return r;
}
__device__ __forceinline__ void fma2(ull& d, ull a, ull b) {
    asm("fma.rn.f32x2 %0, %1, %2, %0;" : "+l"(d) : "l"(a), "l"(b));
}
__device__ __forceinline__ float2 unpk(ull v) {
    float2 r; asm("mov.b64 {%0, %1}, %2;" : "=f"(r.x), "=f"(r.y) : "l"(v)); return r;
}

__device__ __forceinline__ void cvt_store8o(char* smcp, uint32_t hoff, uint32_t loff,
                                            int row, int col, float4 a, float4 b) {
    uint32_t hw[4], lw[4];
    bsplit2(a.x, a.y, hw[0], lw[0]);
    bsplit2(a.z, a.w, hw[1], lw[1]);
    bsplit2(b.x, b.y, hw[2], lw[2]);
    bsplit2(b.z, b.w, hw[3], lw[3]);
    uint32_t off = sw_off(row, col);
    *(uint4*)(smcp + hoff + off) = make_uint4(hw[0], hw[1], hw[2], hw[3]);
    *(uint4*)(smcp + loff + off) = make_uint4(lw[0], lw[1], lw[2], lw[3]);
}

// ---------------- one-time W prepack (Wo, Wq, Wk) ----------------
__global__ __launch_bounds__(256) void prep_w(const float* __restrict__ Wo,
                                              const float* __restrict__ Wq,
                                              const float* __restrict__ Wk,
                                              unsigned short* __restrict__ Woh,
                                              unsigned short* __restrict__ Wol,
                                              unsigned short* __restrict__ Wqh,
                                              unsigned short* __restrict__ Wql,
                                              unsigned short* __restrict__ Wkh,
                                              unsigned short* __restrict__ Wkl) {
    int i = blockIdx.x * 256 + threadIdx.x;
    uint32_t h, l;
    float2 a = *(const float2*)(Wo + 2 * i);
    bsplit2(a.x, a.y, h, l);
    *(uint32_t*)(Woh + 2 * i) = h;
    *(uint32_t*)(Wol + 2 * i) = l;
    float2 b = *(const float2*)(Wq + 2 * i);
    bsplit2(b.x, b.y, h, l);
    *(uint32_t*)(Wqh + 2 * i) = h;
    *(uint32_t*)(Wql + 2 * i) = l;
    float2 c = *(const float2*)(Wk + 2 * i);
    bsplit2(c.x, c.y, h, l);
    *(uint32_t*)(Wkh + 2 * i) = h;
    *(uint32_t*)(Wkl + 2 * i) = l;
}

// attn smem: Qhi 16K | Qlo 16K | K double-buffered (hi 16K + lo 16K) x2 = 96KB
#define QH_OFF 0
#define QL_OFF 16384
#define KBASE_OFF 32768
#define ATTN_SMEM 98304

// ---------------- causal sin-attention (R11 body, branch-free hot loop) ----------------
__global__ __launch_bounds__(128, 2) void attn_kernel(const unsigned short* __restrict__ Qhh,
                                                      const unsigned short* __restrict__ Qhl,
                                                      const unsigned short* __restrict__ Khh,
                                                      const unsigned short* __restrict__ Khl,
                                                      float* __restrict__ O) {
    extern __shared__ char smc[];
    const uint32_t sbase = smem_u32(smc);
    const int tid = threadIdx.x;
    const int lane = tid & 31, w = tid >> 5;
    const int P = blockIdx.x, split = blockIdx.y;
    const int g = lane >> 3, r = lane & 7;
    const int krow = tid >> 1, kc0 = (tid & 1) * 64;
    const int lo = (130 * split) / 9, hi = (130 * (split + 1)) / 9;

    int c = 0;
    for (int sp = 0; sp < 4; sp++) {
        const int b = sp >> 1;
        const int R = (sp & 1) ? (63 - P) : P;
        const int n = R + 1;
        int s_lo = lo - c; if (s_lo < 0) s_lo = 0;
        int s_hi = hi - c; if (s_hi > n) s_hi = n;
        c += n;
        if (s_lo >= s_hi) continue;

        const unsigned short* Qhb = Qhh + (long long)b * TT * DD;
        const unsigned short* Qlb = Qhl + (long long)b * TT * DD;
        const unsigned short* Khb = Khh + (long long)b * TT * DD;
        const unsigned short* Klb = Khl + (long long)b * TT * DD;

        __syncthreads();
        for (int t = tid; t < 1024; t += 128) {
            int row = t >> 4, d0 = (t & 15) * 8;
            long long src = ((long long)R * 64 + row) * DD + d0;
            uint32_t off = sw_off(row, d0);
            *(uint4*)(smc + QH_OFF + off) = *(const uint4*)(Qhb + src);
            *(uint4*)(smc + QL_OFF + off) = *(const uint4*)(Qlb + src);
        }
        {
            long long src = ((long long)s_lo * 64 + krow) * DD + kc0;
#pragma unroll
            for (int q = 0; q < 8; q++) {
                uint32_t off = sw_off(krow, kc0 + 8 * q);
                *(uint4*)(smc + KBASE_OFF + off) = *(const uint4*)(Khb + src + 8 * q);
                *(uint4*)(smc + KBASE_OFF + 16384 + off) = *(const uint4*)(Klb + src + 8 * q);
            }
        }
        float Oc[16][4];
#pragma unroll
        for (int nf = 0; nf < 16; nf++)
#pragma unroll
            for (int e = 0; e < 4; e++) Oc[nf][e] = 0.f;
        __syncthreads();

        uint32_t qah[8][4], qal[8][4];
#pragma unroll
        for (int kc = 0; kc < 8; kc++) {
            uint32_t aoff = sw_off(w * 16 + ((g & 1) ? 8 : 0) + r, kc * 16 + ((g >> 1) ? 8 : 0));
            ldsm4(qah[kc][0], qah[kc][1], qah[kc][2], qah[kc][3], sbase + QH_OFF + aoff);
            ldsm4(qal[kc][0], qal[kc][1], qal[kc][2], qal[kc][3], sbase + QL_OFF + aoff);
        }

        for (int sb = s_lo; sb < s_hi; sb++) {
            const int cur = (sb - s_lo) & 1;
            const uint32_t KH = KBASE_OFF + (uint32_t)cur * 32768;
            const uint32_t KL = KH + 16384;
            const bool pre = (sb + 1 < s_hi);
            const uint32_t NH = KBASE_OFF + (uint32_t)(1 - cur) * 32768;
            long long psrc = ((long long)(sb + 1) * 64 + krow) * DD + kc0;

            float C[8][4];
#pragma unroll
            for (int nf = 0; nf < 8; nf++)
#pragma unroll
                for (int e = 0; e < 4; e++) C[nf][e] = 0.f;
#pragma unroll
            for (int kc = 0; kc < 8; kc++) {
                int d0 = kc * 16;
                uint32_t bh[4][4], bl[4][4];
#pragma unroll
                for (int nfp = 0; nfp < 4; nfp++) {
                    uint32_t boff = sw_off(nfp * 16 + ((g >> 1) ? 8 : 0) + r,
                                           d0 + ((g & 1) ? 8 : 0));
                    ldsm4(bh[nfp][0], bh[nfp][1], bh[nfp][2], bh[nfp][3], sbase + KH + boff);
                    ldsm4(bl[nfp][0], bl[nfp][1], bl[nfp][2], bl[nfp][3], sbase + KL + boff);
                }
#pragma unroll
                for (int nfp = 0; nfp < 4; nfp++) {
                    mma16816(C[2 * nfp],     qah[kc][0], qah[kc][1], qah[kc][2], qah[kc][3], bh[nfp][0], bh[nfp][1]);
                    mma16816(C[2 * nfp + 1], qah[kc][0], qah[kc][1], qah[kc][2], qah[kc][3], bh[nfp][2], bh[nfp][3]);
                }
#pragma unroll
                for (int nfp = 0; nfp < 4; nfp++) {
                    mma16816(C[2 * nfp],     qah[kc][0], qah[kc][1], qah[kc][2], qah[kc][3], bl[nfp][0], bl[nfp][1]);
                    mma16816(C[2 * nfp + 1], qah[kc][0], qah[kc][1], qah[kc][2], qah[kc][3], bl[nfp][2], bl[nfp][3]);
                }
#pragma unroll
                for (int nfp = 0; nfp < 4; nfp++) {
                    mma16816(C[2 * nfp],     qal[kc][0], qal[kc][1], qal[kc][2], qal[kc][3], bh[nfp][0], bh[nfp][1]);
                    mma16816(C[2 * nfp + 1], qal[kc][0], qal[kc][1], qal[kc][2], qal[kc][3], bh[nfp][2], bh[nfp][3]);
                }
            }
            if (pre) {
#pragma unroll
                for (int q = 0; q < 8; q++)
                    *(uint4*)(smc + NH + sw_off(krow, kc0 + 8 * q)) =
                        *(const uint4*)(Khb + psrc + 8 * q);
            }

            uint32_t a2h[4][4], a2l[4][4];
            const int ig = R * 64 + w * 16 + (lane >> 2);
#pragma unroll
            for (int nf = 0; nf < 8; nf++) {
                int jb = sb * 64 + nf * 8 + 2 * (lane & 3);
                float s0 = sinpoly(C[nf][0]); if (jb > ig) s0 = 0.f;
                float s1 = sinpoly(C[nf][1]); if (jb + 1 > ig) s1 = 0.f;
                float s2 = sinpoly(C[nf][2]); if (jb > ig + 8) s2 = 0.f;
                float s3 = sinpoly(C[nf][3]); if (jb + 1 > ig + 8) s3 = 0.f;
                int kc2 = nf >> 1, hk = (nf & 1) ? 2 : 0;
                bsplit2(s0, s1, a2h[kc2][hk], a2l[kc2][hk]);
                bsplit2(s2, s3, a2h[kc2][hk + 1], a2l[kc2][hk + 1]);
            }

#pragma unroll
            for (int kc2 = 0; kc2 < 4; kc2++) {
                int j0 = kc2 * 16;
#pragma unroll
                for (int hh = 0; hh < 2; hh++) {
                    uint32_t th[4][4], tl[4][4];
#pragma unroll
                    for (int q = 0; q < 4; q++) {
                        int nfp = hh * 4 + q;
                        uint32_t boff = sw_off(j0 + ((g & 1) ? 8 : 0) + r,
                                               nfp * 16 + ((g >> 1) ? 8 : 0));
                        ldsm4t(th[q][0], th[q][1], th[q][2], th[q][3], sbase + KH + boff);
                        ldsm4t(tl[q][0], tl[q][1], tl[q][2], tl[q][3], sbase + KL + boff);
                    }
#pragma unroll
                    for (int q = 0; q < 4; q++) {
                        int nfp = hh * 4 + q;
                        mma16816(Oc[2 * nfp],     a2h[kc2][0], a2h[kc2][1], a2h[kc2][2], a2h[kc2][3], th[q][0], th[q][1]);
                        mma16816(Oc[2 * nfp + 1], a2h[kc2][0], a2h[kc2][1], a2h[kc2][2], a2h[kc2][3], th[q][2], th[q][3]);
                    }
#pragma unroll
                    for (int q = 0; q < 4; q++) {
                        int nfp = hh * 4 + q;
                        mma16816(Oc[2 * nfp],     a2h[kc2][0], a2h[kc2][1], a2h[kc2][2], a2h[kc2][3], tl[q][0], tl[q][1]);
                        mma16816(Oc[2 * nfp + 1], a2h[kc2][0], a2h[kc2][1], a2h[kc2][2], a2h[kc2][3], tl[q][2], tl[q][3]);
                    }
#pragma unroll
                    for (int q = 0; q < 4; q++) {
                        int nfp = hh * 4 + q;
                        mma16816(Oc[2 * nfp],     a2l[kc2][0], a2l[kc2][1], a2l[kc2][2], a2l[kc2][3], th[q][0], th[q][1]);
                        mma16816(Oc[2 * nfp + 1], a2l[kc2][0], a2l[kc2][1], a2l[kc2][2], a2l[kc2][3], th[q][2], th[q][3]);
                    }
                }
            }
            if (pre) {
#pragma unroll
                for (int q = 0; q < 8; q++)
                    *(uint4*)(smc + NH + 16384 + sw_off(krow, kc0 + 8 * q)) =
                        *(const uint4*)(Klb + psrc + 8 * q);
            }
            __syncthreads();
        }

        {
            long long rbase = (long long)b * TT + (long long)R * 64 + w * 16 + (lane >> 2);
#pragma unroll
            for (int nf = 0; nf < 16; nf++) {
                int d = nf * 8 + 2 * (lane & 3);
                atomicAdd(O + rbase * DD + d,       Oc[nf][0]);
                atomicAdd(O + rbase * DD + d + 1,   Oc[nf][1]);
                atomicAdd(O + (rbase + 8) * DD + d,     Oc[nf][2]);
                atomicAdd(O + (rbase + 8) * DD + d + 1, Oc[nf][3]);
            }
        }
    }
}

// ---------------- depthwise causal conv ----------------
__global__ __launch_bounds__(512) void conv_kernel(const float* __restrict__ z,
                                                   const float* __restrict__ w,
                                                   const float* __restrict__ bias,
                                                   float* __restrict__ mf) {
    int d0 = threadIdx.x * 2;
    int t = blockIdx.x * 8 + threadIdx.y;
    int b = blockIdx.y;
    float2 bv = *(const float2*)(bias + d0);
    ull acc = pack2(bv.x, bv.y);
    int kstart = (KK - 1) - t;
    if (kstart < 0) kstart = 0;
    const float* zp = z + ((long long)b * TT + t - (KK - 1)) * DD + d0;
    const float* wp = w + d0;
#pragma unroll 4
    for (int k = kstart; k < KK; k++)
        fma2(acc, *(const ull*)(zp + (long long)k * DD), *(const ull*)(wp + (long long)k * DD));
    float2 res = unpk(acc);
    *(float2*)(mf + ((long long)b * TT + t) * DD + d0) = res;
}

// ================== shared smem layout for MMA GEMM kernels ==================
#define E_AH 0
#define E_AL 16384
#define E_WH 32768
#define E_WL 65536
#define E_RED 98304
#define EPI3_SMEM 98816

// ---------------- dual projection via MMA: kh + qh from z ----------------
__global__ __launch_bounds__(256, 2) void dual_mma(
    const float* __restrict__ X,
    const unsigned short* __restrict__ Wkh_, const unsigned short* __restrict__ Wkl_,
    const float* __restrict__ bk,
    const unsigned short* __restrict__ Wqh_, const unsigned short* __restrict__ Wql_,
    const float* __restrict__ bq,
    unsigned short* __restrict__ khh, unsigned short* __restrict__ khl,
    unsigned short* __restrict__ qhh, unsigned short* __restrict__ qhl) {
    extern __shared__ char smc[];
    const uint32_t sbase = smem_u32(smc);
    float* red = (float*)(smc + E_RED);
    const int tid = threadIdx.x;
    const int lane = tid & 31, w = tid >> 5;
    const int wr = w & 3, whalf = w >> 2;
    const int ncol0 = whalf * 64;
    const int g = lane >> 3, r = lane & 7;
    const long long row0 = (long long)blockIdx.x * 64;
    const int rowL = wr * 16 + (lane >> 2);
    const long long gA = row0 + rowL;
    const long long gB = gA + 8;

    // stage A = z tile (fp32 -> bf16 hi/lo); load Wk planes
    for (int t = tid; t < 1024; t += 256) {
        int row = t >> 4, d0 = (t & 15) * 8;
        const float* src = X + (row0 + row) * DD + d0;
        cvt_store8o(smc, E_AH, E_AL, row, d0, *(const float4*)src, *(const float4*)(src + 4));
    }
    for (int t = tid; t < 2048; t += 256) {
        int row = t >> 4, d0 = (t & 15) * 8;
        uint32_t off = sw_off(row, d0);
        *(uint4*)(smc + E_WH + off) = *(const uint4*)(Wkh_ + row * DD + d0);
        *(uint4*)(smc + E_WL + off) = *(const uint4*)(Wkl_ + row * DD + d0);
    }
    __syncthreads();

    float C[8][4];
#pragma unroll
    for (int nf = 0; nf < 8; nf++)
#pragma unroll
        for (int e = 0; e < 4; e++) C[nf][e] = 0.f;

    // ---- GEMM1: C = z @ Wk (3-pass, sync-free) ----
#pragma unroll
    for (int kc = 0; kc < 8; kc++) {
        uint32_t aoff = sw_off(wr * 16 + ((g & 1) ? 8 : 0) + r, kc * 16 + ((g >> 1) ? 8 : 0));
        uint32_t ah0, ah1, ah2, ah3, al0, al1, al2, al3;
        ldsm4(ah0, ah1, ah2, ah3, sbase + E_AH + aoff);
        ldsm4(al0, al1, al2, al3, sbase + E_AL + aoff);
        uint32_t th[4][4], tl[4][4];
#pragma unroll
        for (int nfp = 0; nfp < 4; nfp++) {
            uint32_t boff = sw_off(kc * 16 + ((g & 1) ? 8 : 0) + r,
                                   ncol0 + nfp * 16 + ((g >> 1) ? 8 : 0));
            ldsm4t(th[nfp][0], th[nfp][1], th[nfp][2], th[nfp][3], sbase + E_WH + boff);
            ldsm4t(tl[nfp][0], tl[nfp][1], tl[nfp][2], tl[nfp][3], sbase + E_WL + boff);
        }
#pragma unroll
        for (int nfp = 0; nfp < 4; nfp++) {
            mma16816(C[2 * nfp],     ah0, ah1, ah2, ah3, th[nfp][0], th[nfp][1]);
            mma16816(C[2 * nfp + 1], ah0, ah1, ah2, ah3, th[nfp][2], th[nfp][3]);
        }
#pragma unroll
        for (int nfp = 0; nfp < 4; nfp++) {
            mma16816(C[2 * nfp],     ah0, ah1, ah2, ah3, tl[nfp][0], tl[nfp][1]);
            mma16816(C[2 * nfp + 1], ah0, ah1, ah2, ah3, tl[nfp][2], tl[nfp][3]);
        }
#pragma unroll
        for (int nfp = 0; nfp < 4; nfp++) {
            mma16816(C[2 * nfp],     al0, al1, al2, al3, th[nfp][0], th[nfp][1]);
            mma16816(C[2 * nfp + 1], al0, al1, al2, al3, th[nfp][2], th[nfp][3]);
        }
    }

    // ---- kh = norm(C + bk) ----
    float qsA = 0.f, qsB = 0.f;
#pragma unroll
    for (int nf = 0; nf < 8; nf++) {
        int col = ncol0 + nf * 8 + 2 * (lane & 3);
        float2 bkv = *(const float2*)(bk + col);
        C[nf][0] += bkv.x; C[nf][1] += bkv.y;
        C[nf][2] += bkv.x; C[nf][3] += bkv.y;
        qsA += C[nf][0] * C[nf][0] + C[nf][1] * C[nf][1];
        qsB += C[nf][2] * C[nf][2] + C[nf][3] * C[nf][3];
    }
    qsA += __shfl_xor_sync(0xffffffffu, qsA, 1);
    qsA += __shfl_xor_sync(0xffffffffu, qsA, 2);
    qsB += __shfl_xor_sync(0xffffffffu, qsB, 1);
    qsB += __shfl_xor_sync(0xffffffffu, qsB, 2);
    if ((lane & 3) == 0) {
        red[whalf * 64 + rowL] = qsA;
        red[whalf * 64 + rowL + 8] = qsB;
    }
    __syncthreads();
    qsA = red[rowL] + red[64 + rowL];
    qsB = red[rowL + 8] + red[64 + rowL + 8];
    __syncthreads();
    // all warps past GEMM1 reads (they stored red before the sync) -> rewrite W with Wq
    for (int t = tid; t < 2048; t += 256) {
        int row = t >> 4, d0 = (t & 15) * 8;
        uint32_t off = sw_off(row, d0);
        *(uint4*)(smc + E_WH + off) = *(const uint4*)(Wqh_ + row * DD + d0);
        *(uint4*)(smc + E_WL + off) = *(const uint4*)(Wql_ + row * DD + d0);
    }
    {
        float qiA = __fdividef(1.f, fmaxf(sqrtf(qsA), 1e-8f));
        float qiB = __fdividef(1.f, fmaxf(sqrtf(qsB), 1e-8f));
#pragma unroll
        for (int nf = 0; nf < 8; nf++) {
            int col = ncol0 + nf * 8 + 2 * (lane & 3);
            uint32_t h, l;
            bsplit2(C[nf][0] * qiA, C[nf][1] * qiA, h, l);
            *(uint32_t*)(khh + gA * DD + col) = h;
            *(uint32_t*)(khl + gA * DD + col) = l;
            bsplit2(C[nf][2] * qiB, C[nf][3] * qiB, h, l);
            *(uint32_t*)(khh + gB * DD + col) = h;
            *(uint32_t*)(khl + gB * DD + col) = l;
        }
    }
    __syncthreads();

    // ---- GEMM2: C = z @ Wq (same A frags) ----
#pragma unroll
    for (int nf = 0; nf < 8; nf++)
#pragma unroll
        for (int e = 0; e < 4; e++) C[nf][e] = 0.f;
#pragma unroll
    for (int kc = 0; kc < 8; kc++) {
        uint32_t aoff = sw_off(wr * 16 + ((g & 1) ? 8 : 0) + r, kc * 16 + ((g >> 1) ? 8 : 0));
        uint32_t ah0, ah1, ah2, ah3, al0, al1, al2, al3;
        ldsm4(ah0, ah1, ah2, ah3, sbase + E_AH + aoff);
        ldsm4(al0, al1, al2, al3, sbase + E_AL + aoff);
        uint32_t th[4][4], tl[4][4];
#pragma unroll
        for (int nfp = 0; nfp < 4; nfp++) {
            uint32_t boff = sw_off(kc * 16 + ((g & 1) ? 8 : 0) + r,
                                   ncol0 + nfp * 16 + ((g >> 1) ? 8 : 0));
            ldsm4t(th[nfp][0], th[nfp][1], th[nfp][2], th[nfp][3], sbase + E_WH + boff);
            ldsm4t(tl[nfp][0], tl[nfp][1], tl[nfp][2], tl[nfp][3], sbase + E_WL + boff);
        }
#pragma unroll
        for (int nfp = 0; nfp < 4; nfp++) {
            mma16816(C[2 * nfp],     ah0, ah1, ah2, ah3, th[nfp][0], th[nfp][1]);
            mma16816(C[2 * nfp + 1], ah0, ah1, ah2, ah3, th[nfp][2], th[nfp][3]);
        }
#pragma unroll
        for (int nfp = 0; nfp < 4; nfp++) {
            mma16816(C[2 * nfp],     ah0, ah1, ah2, ah3, tl[nfp][0], tl[nfp][1]);
            mma16816(C[2 * nfp + 1], ah0, ah1, ah2, ah3, tl[nfp][2], tl[nfp][3]);
        }
#pragma unroll
        for (int nfp = 0; nfp < 4; nfp++) {
            mma16816(C[2 * nfp],     al0, al1, al2, al3, th[nfp][0], th[nfp][1]);
            mma16816(C[2 * nfp + 1], al0, al1, al2, al3, th[nfp][2], th[nfp][3]);
        }
    }

    // ---- qh = norm(C + bq) ----
    qsA = 0.f; qsB = 0.f;
#pragma unroll
    for (int nf = 0; nf < 8; nf++) {
        int col = ncol0 + nf * 8 + 2 * (lane & 3);
        float2 bqv = *(const float2*)(bq + col);
        C[nf][0] += bqv.x; C[nf][1] += bqv.y;
        C[nf][2] += bqv.x; C[nf][3] += bqv.y;
        qsA += C[nf][0] * C[nf][0] + C[nf][1] * C[nf][1];
        qsB += C[nf][2] * C[nf][2] + C[nf][3] * C[nf][3];
    }
    qsA += __shfl_xor_sync(0xffffffffu, qsA, 1);
    qsA += __shfl_xor_sync(0xffffffffu, qsA, 2);
    qsB += __shfl_xor_sync(0xffffffffu, qsB, 1);
    qsB += __shfl_xor_sync(0xffffffffu, qsB, 2);
    if ((lane & 3) == 0) {
        red[whalf * 64 + rowL] = qsA;
        red[whalf * 64 + rowL + 8] = qsB;
    }
    __syncthreads();
    qsA = red[rowL] + red[64 + rowL];
    qsB = red[rowL + 8] + red[64 + rowL + 8];
    float qiA = __fdividef(1.f, fmaxf(sqrtf(qsA), 1e-8f));
    float qiB = __fdividef(1.f, fmaxf(sqrtf(qsB), 1e-8f));
#pragma unroll
    for (int nf = 0; nf < 8; nf++) {
        int col = ncol0 + nf * 8 + 2 * (lane & 3);
        uint32_t h, l;
        bsplit2(C[nf][0] * qiA, C[nf][1] * qiA, h, l);
        *(uint32_t*)(qhh + gA * DD + col) = h;
        *(uint32_t*)(qhl + gA * DD + col) = l;
        bsplit2(C[nf][2] * qiB, C[nf][3] * qiB, h, l);
        *(uint32_t*)(qhh + gB * DD + col) = h;
        *(uint32_t*)(qhl + gB * DD + col) = l;
    }
}

// ================== MMA epilogue: full W resident, sync-free GEMMs ==================
__global__ __launch_bounds__(256, 2) void epilogue_mma(
    const float* __restrict__ A0,
    const unsigned short* __restrict__ Woh, const unsigned short* __restrict__ Wol,
    const float* __restrict__ bo,
    const unsigned short* __restrict__ Wqh, const unsigned short* __restrict__ Wql,
    const float* __restrict__ bq,
    const float* __restrict__ mf, const float* __restrict__ zin,
    const float* __restrict__ zbase, float* __restrict__ vacc,
    float* __restrict__ zc, unsigned short* __restrict__ qhh,
    unsigned short* __restrict__ qhl, float* __restrict__ out,
    float sw, float rc, int first, int has_next) {
    extern __shared__ char smc[];
    const uint32_t sbase = smem_u32(smc);
    float* red = (float*)(smc + E_RED);
    const int tid = threadIdx.x;
    const int lane = tid & 31, w = tid >> 5;
    const int wr = w & 3, whalf = w >> 2;
    const int ncol0 = whalf * 64;
    const int g = lane >> 3, r = lane & 7;
    const long long row0 = (long long)blockIdx.x * 64;
    const int rowL = wr * 16 + (lane >> 2);
    const long long gA = row0 + rowL;
    const long long gB = gA + 8;

    for (int t = tid; t < 1024; t += 256) {
        int row = t >> 4, d0 = (t & 15) * 8;
        const float* src = A0 + (row0 + row) * DD + d0;
        cvt_store8o(smc, E_AH, E_AL, row, d0, *(const float4*)src, *(const float4*)(src + 4));
    }
    for (int t = tid; t < 2048; t += 256) {
        int row = t >> 4, d0 = (t & 15) * 8;
        uint32_t off = sw_off(row, d0);
        *(uint4*)(smc + E_WH + off) = *(const uint4*)(Woh + row * DD + d0);
        *(uint4*)(smc + E_WL + off) = *(const uint4*)(Wol + row * DD + d0);
    }
    __syncthreads();

    float C[8][4];
#pragma unroll
    for (int nf = 0; nf < 8; nf++)
#pragma unroll
        for (int e = 0; e < 4; e++) C[nf][e] = 0.f;

    // ---- GEMM1: C = A @ Wo ----
#pragma unroll
    for (int kc = 0; kc < 8; kc++) {
        uint32_t aoff = sw_off(wr * 16 + ((g & 1) ? 8 : 0) + r, kc * 16 + ((g >> 1) ? 8 : 0));
        uint32_t ah0, ah1, ah2, ah3, al0, al1, al2, al3;
        ldsm4(ah0, ah1, ah2, ah3, sbase + E_AH + aoff);
        ldsm4(al0, al1, al2, al3, sbase + E_AL + aoff);
        uint32_t th[4][4], tl[4][4];
#pragma unroll
        for (int nfp = 0; nfp < 4; nfp++) {
            uint32_t boff = sw_off(kc * 16 + ((g & 1) ? 8 : 0) + r,
                                   ncol0 + nfp * 16 + ((g >> 1) ? 8 : 0));
            ldsm4t(th[nfp][0], th[nfp][1], th[nfp][2], th[nfp][3], sbase + E_WH + boff);
            ldsm4t(tl[nfp][0], tl[nfp][1], tl[nfp][2], tl[nfp][3], sbase + E_WL + boff);
        }
#pragma unroll
        for (int nfp = 0; nfp < 4; nfp++) {
            mma16816(C[2 * nfp],     ah0, ah1, ah2, ah3, th[nfp][0], th[nfp][1]);
            mma16816(C[2 * nfp + 1], ah0, ah1, ah2, ah3, th[nfp][2], th[nfp][3]);
        }
#pragma unroll
        for (int nfp = 0; nfp < 4; nfp++) {
            mma16816(C[2 * nfp],     ah0, ah1, ah2, ah3, tl[nfp][0], tl[nfp][1]);
            mma16816(C[2 * nfp + 1], ah0, ah1, ah2, ah3, tl[nfp][2], tl[nfp][3]);
        }
#pragma unroll
        for (int nfp = 0; nfp < 4; nfp++) {
            mma16816(C[2 * nfp],     al0, al1, al2, al3, th[nfp][0], th[nfp][1]);
            mma16816(C[2 * nfp + 1], al0, al1, al2, al3, th[nfp][2], th[nfp][3]);
        }
    }

    // ---- bias + mf, tangent dot ----
    float dotA = 0.f, dotB = 0.f;
#pragma unroll
    for (int nf = 0; nf < 8; nf++) {
        int col = ncol0 + nf * 8 + 2 * (lane & 3);
        float2 bov = *(const float2*)(bo + col);
        float2 mA = *(const float2*)(mf + gA * DD + col);
        float2 mB = *(const float2*)(mf + gB * DD + col);
        C[nf][0] += bov.x + mA.x; C[nf][1] += bov.y + mA.y;
        C[nf][2] += bov.x + mB.x; C[nf][3] += bov.y + mB.y;
        float2 zA = *(const float2*)(zin + gA * DD + col);
        float2 zB = *(const float2*)(zin + gB * DD + col);
        dotA += C[nf][0] * zA.x + C[nf][1] * zA.y;
        dotB += C[nf][2] * zB.x + C[nf][3] * zB.y;
    }
    dotA += __shfl_xor_sync(0xffffffffu, dotA, 1);
    dotA += __shfl_xor_sync(0xffffffffu, dotA, 2);
    dotB += __shfl_xor_sync(0xffffffffu, dotB, 1);
    dotB += __shfl_xor_sync(0xffffffffu, dotB, 2);
    if ((lane & 3) == 0) {
        red[whalf * 64 + rowL] = dotA;
        red[whalf * 64 + rowL + 8] = dotB;
    }
    __syncthreads();
    dotA = red[rowL] + red[64 + rowL];
    dotB = red[rowL + 8] + red[64 + rowL + 8];
    __syncthreads();

    // ---- proj, vacc update, zn sumsq; load Wq into W buffer ----
    for (int t = tid; t < 2048; t += 256) {
        int row = t >> 4, d0 = (t & 15) * 8;
        uint32_t off = sw_off(row, d0);
        *(uint4*)(smc + E_WH + off) = *(const uint4*)(Wqh + row * DD + d0);
        *(uint4*)(smc + E_WL + off) = *(const uint4*)(Wql + row * DD + d0);
    }
    float ssA = 0.f, ssB = 0.f;
#pragma unroll
    for (int nf = 0; nf < 8; nf++) {
        int col = ncol0 + nf * 8 + 2 * (lane & 3);
        float2 zA = *(const float2*)(zin + gA * DD + col);
        float2 zB = *(const float2*)(zin + gB * DD + col);
        C[nf][0] -= dotA * zA.x; C[nf][1] -= dotA * zA.y;
        C[nf][2] -= dotB * zB.x; C[nf][3] -= dotB * zB.y;
        float2* vA = (float2*)(vacc + gA * DD + col);
        float2* vB = (float2*)(vacc + gB * DD + col);
        float2 vpA = first ? make_float2(0.f, 0.f) : *vA;
        float2 vpB = first ? make_float2(0.f, 0.f) : *vB;
        float2 vnA = make_float2(vpA.x + sw * C[nf][0], vpA.y + sw * C[nf][1]);
        float2 vnB = make_float2(vpB.x + sw * C[nf][2], vpB.y + sw * C[nf][3]);
        *vA = vnA; *vB = vnB;
        float2 zbA = *(const float2*)(zbase + gA * DD + col);
        float2 zbB = *(const float2*)(zbase + gB * DD + col);
        if (has_next) {
            float a0v = zbA.x + rc * C[nf][0], a1v = zbA.y + rc * C[nf][1];
            float b0v = zbB.x + rc * C[nf][2], b1v = zbB.y + rc * C[nf][3];
            ssA += a0v * a0v + a1v * a1v;
            ssB += b0v * b0v + b1v * b1v;
            C[nf][0] = a0v; C[nf][1] = a1v; C[nf][2] = b0v; C[nf][3] = b1v;
        } else {
            float a0v = zbA.x + vnA.x, a1v = zbA.y + vnA.y;
            float b0v = zbB.x + vnB.x, b1v = zbB.y + vnB.y;
            ssA += a0v * a0v + a1v * a1v;
            ssB += b0v * b0v + b1v * b1v;
            C[nf][0] = a0v; C[nf][1] = a1v; C[nf][2] = b0v; C[nf][3] = b1v;
        }
    }
    ssA += __shfl_xor_sync(0xffffffffu, ssA, 1);
    ssA += __shfl_xor_sync(0xffffffffu, ssA, 2);
    ssB += __shfl_xor_sync(0xffffffffu, ssB, 1);
    ssB += __shfl_xor_sync(0xffffffffu, ssB, 2);
    if ((lane & 3) == 0) {
        red[whalf * 64 + rowL] = ssA;
        red[whalf * 64 + rowL + 8] = ssB;
    }
    __syncthreads();
    ssA = red[rowL] + red[64 + rowL];
    ssB = red[rowL + 8] + red[64 + rowL + 8];
    __syncthreads();
    float invA = __fdividef(1.f, fmaxf(sqrtf(ssA), 1e-8f));
    float invB = __fdividef(1.f, fmaxf(sqrtf(ssB), 1e-8f));

    if (!has_next) {
#pragma unroll
        for (int nf = 0; nf < 8; nf++) {
            int col = ncol0 + nf * 8 + 2 * (lane & 3);
            *(float2*)(out + gA * DD + col) = make_float2(C[nf][0] * invA, C[nf][1] * invA);
            *(float2*)(out + gB * DD + col) = make_float2(C[nf][2] * invB, C[nf][3] * invB);
        }
        return;
    }

    // ---- z0 = norm(zbase + rc*proj): store zc + restage into A tile ----
#pragma unroll
    for (int nf = 0; nf < 8; nf++) {
        int col = ncol0 + nf * 8 + 2 * (lane & 3);
        float a0v = C[nf][0] * invA, a1v = C[nf][1] * invA;
        float b0v = C[nf][2] * invB, b1v = C[nf][3] * invB;
        *(float2*)(zc + gA * DD + col) = make_float2(a0v, a1v);
        *(float2*)(zc + gB * DD + col) = make_float2(b0v, b1v);
        uint32_t h, l;
        bsplit2(a0v, a1v, h, l);
        *(uint32_t*)(smc + E_AH + sw_off(rowL, col)) = h;
        *(uint32_t*)(smc + E_AL + sw_off(rowL, col)) = l;
        bsplit2(b0v, b1v, h, l);
        *(uint32_t*)(smc + E_AH + sw_off(rowL + 8, col)) = h;
        *(uint32_t*)(smc + E_AL + sw_off(rowL + 8, col)) = l;
    }
    __syncthreads();

    // ---- GEMM2: C = z0 @ Wq ----
#pragma unroll
    for (int nf = 0; nf < 8; nf++)
#pragma unroll
        for (int e = 0; e < 4; e++) C[nf][e] = 0.f;
#pragma unroll
    for (int kc = 0; kc < 8; kc++) {
        uint32_t aoff = sw_off(wr * 16 + ((g & 1) ? 8 : 0) + r, kc * 16 + ((g >> 1) ? 8 : 0));
        uint32_t ah0, ah1, ah2, ah3, al0, al1, al2, al3;
        ldsm4(ah0, ah1, ah2, ah3, sbase + E_AH + aoff);
        ldsm4(al0, al1, al2, al3, sbase + E_AL + aoff);
        uint32_t th[4][4], tl[4][4];
#pragma unroll
        for (int nfp = 0; nfp < 4; nfp++) {
            uint32_t boff = sw_off(kc * 16 + ((g & 1) ? 8 : 0) + r,
                                   ncol0 + nfp * 16 + ((g >> 1) ? 8 : 0));
            ldsm4t(th[nfp][0], th[nfp][1], th[nfp][2], th[nfp][3], sbase + E_WH + boff);
            ldsm4t(tl[nfp][0], tl[nfp][1], tl[nfp][2], tl[nfp][3], sbase + E_WL + boff);
        }
#pragma unroll
        for (int nfp = 0; nfp < 4; nfp++) {
            mma16816(C[2 * nfp],     ah0, ah1, ah2, ah3, th[nfp][0], th[nfp][1]);
            mma16816(C[2 * nfp + 1], ah0, ah1, ah2, ah3, th[nfp][2], th[nfp][3]);
        }
#pragma unroll
        for (int nfp = 0; nfp < 4; nfp++) {
            mma16816(C[2 * nfp],     ah0, ah1, ah2, ah3, tl[nfp][0], tl[nfp][1]);
            mma16816(C[2 * nfp + 1], ah0, ah1, ah2, ah3, tl[nfp][2], tl[nfp][3]);
        }
#pragma unroll
        for (int nfp = 0; nfp < 4; nfp++) {
            mma16816(C[2 * nfp],     al0, al1, al2, al3, th[nfp][0], th[nfp][1]);
            mma16816(C[2 * nfp + 1], al0, al1, al2, al3, th[nfp][2], th[nfp][3]);
        }
    }

    // ---- qh = norm(C + bq) -> prepacked bf16 hi/lo ----
    float qsA = 0.f, qsB = 0.f;
#pragma unroll
    for (int nf = 0; nf < 8; nf++) {
        int col = ncol0 + nf * 8 + 2 * (lane & 3);
        float2 bqv = *(const float2*)(bq + col);
        C[nf][0] += bqv.x; C[nf][1] += bqv.y;
        C[nf][2] += bqv.x; C[nf][3] += bqv.y;
        qsA += C[nf][0] * C[nf][0] + C[nf][1] * C[nf][1];
        qsB += C[nf][2] * C[nf][2] + C[nf][3] * C[nf][3];
    }
    qsA += __shfl_xor_sync(0xffffffffu, qsA, 1);
    qsA += __shfl_xor_sync(0xffffffffu, qsA, 2);
    qsB += __shfl_xor_sync(0xffffffffu, qsB, 1);
    qsB += __shfl_xor_sync(0xffffffffu, qsB, 2);
    if ((lane & 3) == 0) {
        red[whalf * 64 + rowL] = qsA;
        red[whalf * 64 + rowL + 8] = qsB;
    }
    __syncthreads();
    qsA = red[rowL] + red[64 + rowL];
    qsB = red[rowL + 8] + red[64 + rowL + 8];
    float qiA = __fdividef(1.f, fmaxf(sqrtf(qsA), 1e-8f));
    float qiB = __fdividef(1.f, fmaxf(sqrtf(qsB), 1e-8f));
#pragma unroll
    for (int nf = 0; nf < 8; nf++) {
        int col = ncol0 + nf * 8 + 2 * (lane & 3);
        uint32_t h, l;
        bsplit2(C[nf][0] * qiA, C[nf][1] * qiA, h, l);
        *(uint32_t*)(qhh + gA * DD + col) = h;
        *(uint32_t*)(qhl + gA * DD + col) = l;
        bsplit2(C[nf][2] * qiB, C[nf][3] * qiB, h, l);
        *(uint32_t*)(qhh + gB * DD + col) = h;
        *(uint32_t*)(qhl + gB * DD + col) = l;
    }
}

// ---------------- launch ----------------
extern "C" void kernel_launch(void* const* d_in, const int* in_sizes, int n_in,
                              void* d_out, int out_size) {
    const float* z  = (const float*)d_in[0];
    const float* ck = (const float*)d_in[1];
    const float* cb = (const float*)d_in[2];
    const float* Wq = (const float*)d_in[3];
    const float* bq = (const float*)d_in[4];
    const float* Wk = (const float*)d_in[5];
    const float* bk = (const float*)d_in[6];
    const float* Wo = (const float*)d_in[7];
    const float* bo = (const float*)d_in[8];
    float* out = (float*)d_out;

    float *mf, *a0, *zc, *va;
    unsigned short *qhh, *qhl, *khh, *khl, *woh, *wol, *wqh, *wql, *wkh, *wkl;
    cudaGetSymbolAddress((void**)&mf, g_mf);
    cudaGetSymbolAddress((void**)&a0, g_a0);
    cudaGetSymbolAddress((void**)&zc, g_zc);
    cudaGetSymbolAddress((void**)&va, g_va);
    cudaGetSymbolAddress((void**)&qhh, g_qhh);
    cudaGetSymbolAddress((void**)&qhl, g_qhl);
    cudaGetSymbolAddress((void**)&khh, g_khh);
    cudaGetSymbolAddress((void**)&khl, g_khl);
    cudaGetSymbolAddress((void**)&woh, g_woh);
    cudaGetSymbolAddress((void**)&wol, g_wol);
    cudaGetSymbolAddress((void**)&wqh, g_wqh);
    cudaGetSymbolAddress((void**)&wql, g_wql);
    cudaGetSymbolAddress((void**)&wkh, g_wkh);
    cudaGetSymbolAddress((void**)&wkl, g_wkl);

    cudaFuncSetAttribute(dual_mma, cudaFuncAttributeMaxDynamicSharedMemorySize, EPI3_SMEM);
    cudaFuncSetAttribute(epilogue_mma, cudaFuncAttributeMaxDynamicSharedMemorySize, EPI3_SMEM);
    cudaFuncSetAttribute(attn_kernel, cudaFuncAttributeMaxDynamicSharedMemorySize, ATTN_SMEM);

    prep_w<<<32, 256>>>(Wo, Wq, Wk, woh, wol, wqh, wql, wkh, wkl);
    conv_kernel<<<dim3(TT / 8, BB), dim3(64, 8)>>>(z, ck, cb, mf);
    dual_mma<<<BT / 64, 256, EPI3_SMEM>>>(z, wkh, wkl, bk, wqh, wql, bq,
                                          khh, khl, qhh, qhl);

    const float sws[4] = {1.f / 6.f, 2.f / 6.f, 2.f / 6.f, 1.f / 6.f};
    const float rcs[4] = {0.5f, 0.5f, 1.0f, 0.f};
    const float* zcur = z;
    for (int s = 0; s < 4; s++) {
        cudaMemsetAsync(a0, 0, (size_t)BT * DD * sizeof(float));
        attn_kernel<<<dim3(32, 9), 128, ATTN_SMEM>>>(qhh, qhl, khh, khl, a0);
        epilogue_mma<<<BT / 64, 256, EPI3_SMEM>>>(a0, woh, wol, bo, wqh, wql, bq,
                                                  mf, zcur, z, va, zc, qhh, qhl, out,
                                                  sws[s], rcs[s], s == 0 ? 1 : 0,
                                                  s < 3 ? 1 : 0);
        zcur = zc;
    }
}

// round 16
// speedup vs baseline: 1.0738x; 1.0052x over previous
#include <cuda_runtime.h>
#include <cstdint>

#define BB 2
#define TT 4096
#define DD 128
#define KK 256
#define BT (BB * TT)

// ---------------- scratch ----------------
__device__ float g_mf[BT * DD];
__device__ float g_a0[BT * DD];
__device__ float g_zc[BT * DD];
__device__ float g_va[BT * DD];
__device__ unsigned short g_qhh[BT * DD];
__device__ unsigned short g_qhl[BT * DD];
__device__ unsigned short g_khh[BT * DD];
__device__ unsigned short g_khl[BT * DD];
__device__ unsigned short g_woh[DD * DD];
__device__ unsigned short g_wol[DD * DD];
__device__ unsigned short g_wqh[DD * DD];
__device__ unsigned short g_wql[DD * DD];
__device__ unsigned short g_wkh[DD * DD];
__device__ unsigned short g_wkl[DD * DD];

// ================= helpers =================
typedef unsigned long long ull;
__device__ __forceinline__ uint32_t smem_u32(const void* p) {
    uint32_t a;
    asm("{ .reg .u64 t; cvta.to.shared.u64 t, %1; cvt.u32.u64 %0, t; }" : "=r"(a) : "l"(p));
    return a;
}
__device__ __forceinline__ void ldsm4(uint32_t& r0, uint32_t& r1, uint32_t& r2, uint32_t& r3,
                                      uint32_t addr) {
    asm volatile("ldmatrix.sync.aligned.m8n8.x4.shared.b16 {%0,%1,%2,%3}, [%4];"
                 : "=r"(r0), "=r"(r1), "=r"(r2), "=r"(r3) : "r"(addr));
}
__device__ __forceinline__ void ldsm4t(uint32_t& r0, uint32_t& r1, uint32_t& r2, uint32_t& r3,
                                       uint32_t addr) {
    asm volatile("ldmatrix.sync.aligned.m8n8.x4.trans.shared.b16 {%0,%1,%2,%3}, [%4];"
                 : "=r"(r0), "=r"(r1), "=r"(r2), "=r"(r3) : "r"(addr));
}
__device__ __forceinline__ void mma16816(float* c, uint32_t a0, uint32_t a1, uint32_t a2,
                                         uint32_t a3, uint32_t b0, uint32_t b1) {
    asm volatile(
        "mma.sync.aligned.m16n8k16.row.col.f32.bf16.bf16.f32 "
        "{%0,%1,%2,%3}, {%4,%5,%6,%7}, {%8,%9}, {%0,%1,%2,%3};"
        : "+f"(c[0]), "+f"(c[1]), "+f"(c[2]), "+f"(c[3])
        : "r"(a0), "r"(a1), "r"(a2), "r"(a3), "r"(b0), "r"(b1));
}
__device__ __forceinline__ void bsplit2(float x0, float x1, uint32_t& h, uint32_t& l) {
    uint16_t h0, h1, l0, l1;
    asm("cvt.rn.bf16.f32 %0, %1;" : "=h"(h0) : "f"(x0));
    asm("cvt.rn.bf16.f32 %0, %1;" : "=h"(h1) : "f"(x1));
    float f0 = __uint_as_float((uint32_t)h0 << 16);
    float f1 = __uint_as_float((uint32_t)h1 << 16);
    asm("cvt.rn.bf16.f32 %0, %1;" : "=h"(l0) : "f"(x0 - f0));
    asm("cvt.rn.bf16.f32 %0, %1;" : "=h"(l1) : "f"(x1 - f1));
    h = (uint32_t)h0 | ((uint32_t)h1 << 16);
    l = (uint32_t)l0 | ((uint32_t)l1 << 16);
}
__device__ __forceinline__ uint32_t sw_off(int row, int d) {
    return (uint32_t)(row * 256 + ((((d >> 3) ^ (row & 7)) & 15) << 4) + (d & 7) * 2);
}
__device__ __forceinline__ float sinpoly(float x) {
    float x2 = x * x;
    float pp = fmaf(x2, 2.7557319e-06f, -1.9841270e-04f);
    pp = fmaf(x2, pp, 8.3333333e-03f);
    pp = fmaf(x2, pp, -1.6666667e-01f);
    return fmaf(x * x2, pp, x);
}
__device__ __forceinline__ ull pack2(float x, float y) {
    ull r; asm("mov.b64 %0, {%1, %2};" : "=l"(r) : "f"(x), "f"(y)); return r;
}
__device__ __forceinline__ void fma2(ull& d, ull a, ull b) {
    asm("fma.rn.f32x2 %0, %1, %2, %0;" : "+l"(d) : "l"(a), "l"(b));
}
__device__ __forceinline__ float2 unpk(ull v) {
    float2 r; asm("mov.b64 {%0, %1}, %2;" : "=f"(r.x), "=f"(r.y) : "l"(v)); return r;
}

__device__ __forceinline__ void cvt_store8o(char* smcp, uint32_t hoff, uint32_t loff,
                                            int row, int col, float4 a, float4 b) {
    uint32_t hw[4], lw[4];
    bsplit2(a.x, a.y, hw[0], lw[0]);
    bsplit2(a.z, a.w, hw[1], lw[1]);
    bsplit2(b.x, b.y, hw[2], lw[2]);
    bsplit2(b.z, b.w, hw[3], lw[3]);
    uint32_t off = sw_off(row, col);
    *(uint4*)(smcp + hoff + off) = make_uint4(hw[0], hw[1], hw[2], hw[3]);
    *(uint4*)(smcp + loff + off) = make_uint4(lw[0], lw[1], lw[2], lw[3]);
}

// ---------------- one-time W prepack (Wo, Wq, Wk) ----------------
__global__ __launch_bounds__(256) void prep_w(const float* __restrict__ Wo,
                                              const float* __restrict__ Wq,
                                              const float* __restrict__ Wk,
                                              unsigned short* __restrict__ Woh,
                                              unsigned short* __restrict__ Wol,
                                              unsigned short* __restrict__ Wqh,
                                              unsigned short* __restrict__ Wql,
                                              unsigned short* __restrict__ Wkh,
                                              unsigned short* __restrict__ Wkl) {
    int i = blockIdx.x * 256 + threadIdx.x;
    uint32_t h, l;
    float2 a = *(const float2*)(Wo + 2 * i);
    bsplit2(a.x, a.y, h, l);
    *(uint32_t*)(Woh + 2 * i) = h;
    *(uint32_t*)(Wol + 2 * i) = l;
    float2 b = *(const float2*)(Wq + 2 * i);
    bsplit2(b.x, b.y, h, l);
    *(uint32_t*)(Wqh + 2 * i) = h;
    *(uint32_t*)(Wql + 2 * i) = l;
    float2 c = *(const float2*)(Wk + 2 * i);
    bsplit2(c.x, c.y, h, l);
    *(uint32_t*)(Wkh + 2 * i) = h;
    *(uint32_t*)(Wkl + 2 * i) = l;
}

// attn smem: Qhi 16K | Qlo 16K | K double-buffered (hi 16K + lo 16K) x2 = 96KB
#define QH_OFF 0
#define QL_OFF 16384
#define KBASE_OFF 32768
#define ATTN_SMEM 98304

// ---------------- causal sin-attention (R11 body, branch-free hot loop) ----------------
__global__ __launch_bounds__(128, 2) void attn_kernel(const unsigned short* __restrict__ Qhh,
                                                      const unsigned short* __restrict__ Qhl,
                                                      const unsigned short* __restrict__ Khh,
                                                      const unsigned short* __restrict__ Khl,
                                                      float* __restrict__ O) {
    extern __shared__ char smc[];
    const uint32_t sbase = smem_u32(smc);
    const int tid = threadIdx.x;
    const int lane = tid & 31, w = tid >> 5;
    const int P = blockIdx.x, split = blockIdx.y;
    const int g = lane >> 3, r = lane & 7;
    const int krow = tid >> 1, kc0 = (tid & 1) * 64;
    const int lo = (130 * split) / 9, hi = (130 * (split + 1)) / 9;

    int c = 0;
    for (int sp = 0; sp < 4; sp++) {
        const int b = sp >> 1;
        const int R = (sp & 1) ? (63 - P) : P;
        const int n = R + 1;
        int s_lo = lo - c; if (s_lo < 0) s_lo = 0;
        int s_hi = hi - c; if (s_hi > n) s_hi = n;
        c += n;
        if (s_lo >= s_hi) continue;

        const unsigned short* Qhb = Qhh + (long long)b * TT * DD;
        const unsigned short* Qlb = Qhl + (long long)b * TT * DD;
        const unsigned short* Khb = Khh + (long long)b * TT * DD;
        const unsigned short* Klb = Khl + (long long)b * TT * DD;

        __syncthreads();
        for (int t = tid; t < 1024; t += 128) {
            int row = t >> 4, d0 = (t & 15) * 8;
            long long src = ((long long)R * 64 + row) * DD + d0;
            uint32_t off = sw_off(row, d0);
            *(uint4*)(smc + QH_OFF + off) = *(const uint4*)(Qhb + src);
            *(uint4*)(smc + QL_OFF + off) = *(const uint4*)(Qlb + src);
        }
        {
            long long src = ((long long)s_lo * 64 + krow) * DD + kc0;
#pragma unroll
            for (int q = 0; q < 8; q++) {
                uint32_t off = sw_off(krow, kc0 + 8 * q);
                *(uint4*)(smc + KBASE_OFF + off) = *(const uint4*)(Khb + src + 8 * q);
                *(uint4*)(smc + KBASE_OFF + 16384 + off) = *(const uint4*)(Klb + src + 8 * q);
            }
        }
        float Oc[16][4];
#pragma unroll
        for (int nf = 0; nf < 16; nf++)
#pragma unroll
            for (int e = 0; e < 4; e++) Oc[nf][e] = 0.f;
        __syncthreads();

        uint32_t qah[8][4], qal[8][4];
#pragma unroll
        for (int kc = 0; kc < 8; kc++) {
            uint32_t aoff = sw_off(w * 16 + ((g & 1) ? 8 : 0) + r, kc * 16 + ((g >> 1) ? 8 : 0));
            ldsm4(qah[kc][0], qah[kc][1], qah[kc][2], qah[kc][3], sbase + QH_OFF + aoff);
            ldsm4(qal[kc][0], qal[kc][1], qal[kc][2], qal[kc][3], sbase + QL_OFF + aoff);
        }

        for (int sb = s_lo; sb < s_hi; sb++) {
            const int cur = (sb - s_lo) & 1;
            const uint32_t KH = KBASE_OFF + (uint32_t)cur * 32768;
            const uint32_t KL = KH + 16384;
            const bool pre = (sb + 1 < s_hi);
            const uint32_t NH = KBASE_OFF + (uint32_t)(1 - cur) * 32768;
            long long psrc = ((long long)(sb + 1) * 64 + krow) * DD + kc0;

            float C[8][4];
#pragma unroll
            for (int nf = 0; nf < 8; nf++)
#pragma unroll
                for (int e = 0; e < 4; e++) C[nf][e] = 0.f;
#pragma unroll
            for (int kc = 0; kc < 8; kc++) {
                int d0 = kc * 16;
                uint32_t bh[4][4], bl[4][4];
#pragma unroll
                for (int nfp = 0; nfp < 4; nfp++) {
                    uint32_t boff = sw_off(nfp * 16 + ((g >> 1) ? 8 : 0) + r,
                                           d0 + ((g & 1) ? 8 : 0));
                    ldsm4(bh[nfp][0], bh[nfp][1], bh[nfp][2], bh[nfp][3], sbase + KH + boff);
                    ldsm4(bl[nfp][0], bl[nfp][1], bl[nfp][2], bl[nfp][3], sbase + KL + boff);
                }
#pragma unroll
                for (int nfp = 0; nfp < 4; nfp++) {
                    mma16816(C[2 * nfp],     qah[kc][0], qah[kc][1], qah[kc][2], qah[kc][3], bh[nfp][0], bh[nfp][1]);
                    mma16816(C[2 * nfp + 1], qah[kc][0], qah[kc][1], qah[kc][2], qah[kc][3], bh[nfp][2], bh[nfp][3]);
                }
#pragma unroll
                for (int nfp = 0; nfp < 4; nfp++) {
                    mma16816(C[2 * nfp],     qah[kc][0], qah[kc][1], qah[kc][2], qah[kc][3], bl[nfp][0], bl[nfp][1]);
                    mma16816(C[2 * nfp + 1], qah[kc][0], qah[kc][1], qah[kc][2], qah[kc][3], bl[nfp][2], bl[nfp][3]);
                }
#pragma unroll
                for (int nfp = 0; nfp < 4; nfp++) {
                    mma16816(C[2 * nfp],     qal[kc][0], qal[kc][1], qal[kc][2], qal[kc][3], bh[nfp][0], bh[nfp][1]);
                    mma16816(C[2 * nfp + 1], qal[kc][0], qal[kc][1], qal[kc][2], qal[kc][3], bh[nfp][2], bh[nfp][3]);
                }
            }
            if (pre) {
#pragma unroll
                for (int q = 0; q < 8; q++)
                    *(uint4*)(smc + NH + sw_off(krow, kc0 + 8 * q)) =
                        *(const uint4*)(Khb + psrc + 8 * q);
            }

            uint32_t a2h[4][4], a2l[4][4];
            const int ig = R * 64 + w * 16 + (lane >> 2);
#pragma unroll
            for (int nf = 0; nf < 8; nf++) {
                int jb = sb * 64 + nf * 8 + 2 * (lane & 3);
                float s0 = sinpoly(C[nf][0]); if (jb > ig) s0 = 0.f;
                float s1 = sinpoly(C[nf][1]); if (jb + 1 > ig) s1 = 0.f;
                float s2 = sinpoly(C[nf][2]); if (jb > ig + 8) s2 = 0.f;
                float s3 = sinpoly(C[nf][3]); if (jb + 1 > ig + 8) s3 = 0.f;
                int kc2 = nf >> 1, hk = (nf & 1) ? 2 : 0;
                bsplit2(s0, s1, a2h[kc2][hk], a2l[kc2][hk]);
                bsplit2(s2, s3, a2h[kc2][hk + 1], a2l[kc2][hk + 1]);
            }

#pragma unroll
            for (int kc2 = 0; kc2 < 4; kc2++) {
                int j0 = kc2 * 16;
#pragma unroll
                for (int hh = 0; hh < 2; hh++) {
                    uint32_t th[4][4], tl[4][4];
#pragma unroll
                    for (int q = 0; q < 4; q++) {
                        int nfp = hh * 4 + q;
                        uint32_t boff = sw_off(j0 + ((g & 1) ? 8 : 0) + r,
                                               nfp * 16 + ((g >> 1) ? 8 : 0));
                        ldsm4t(th[q][0], th[q][1], th[q][2], th[q][3], sbase + KH + boff);
                        ldsm4t(tl[q][0], tl[q][1], tl[q][2], tl[q][3], sbase + KL + boff);
                    }
#pragma unroll
                    for (int q = 0; q < 4; q++) {
                        int nfp = hh * 4 + q;
                        mma16816(Oc[2 * nfp],     a2h[kc2][0], a2h[kc2][1], a2h[kc2][2], a2h[kc2][3], th[q][0], th[q][1]);
                        mma16816(Oc[2 * nfp + 1], a2h[kc2][0], a2h[kc2][1], a2h[kc2][2], a2h[kc2][3], th[q][2], th[q][3]);
                    }
#pragma unroll
                    for (int q = 0; q < 4; q++) {
                        int nfp = hh * 4 + q;
                        mma16816(Oc[2 * nfp],     a2h[kc2][0], a2h[kc2][1], a2h[kc2][2], a2h[kc2][3], tl[q][0], tl[q][1]);
                        mma16816(Oc[2 * nfp + 1], a2h[kc2][0], a2h[kc2][1], a2h[kc2][2], a2h[kc2][3], tl[q][2], tl[q][3]);
                    }
#pragma unroll
                    for (int q = 0; q < 4; q++) {
                        int nfp = hh * 4 + q;
                        mma16816(Oc[2 * nfp],     a2l[kc2][0], a2l[kc2][1], a2l[kc2][2], a2l[kc2][3], th[q][0], th[q][1]);
                        mma16816(Oc[2 * nfp + 1], a2l[kc2][0], a2l[kc2][1], a2l[kc2][2], a2l[kc2][3], th[q][2], th[q][3]);
                    }
                }
            }
            if (pre) {
#pragma unroll
                for (int q = 0; q < 8; q++)
                    *(uint4*)(smc + NH + 16384 + sw_off(krow, kc0 + 8 * q)) =
                        *(const uint4*)(Klb + psrc + 8 * q);
            }
            __syncthreads();
        }

        {
            long long rbase = (long long)b * TT + (long long)R * 64 + w * 16 + (lane >> 2);
#pragma unroll
            for (int nf = 0; nf < 16; nf++) {
                int d = nf * 8 + 2 * (lane & 3);
                atomicAdd(O + rbase * DD + d,       Oc[nf][0]);
                atomicAdd(O + rbase * DD + d + 1,   Oc[nf][1]);
                atomicAdd(O + (rbase + 8) * DD + d,     Oc[nf][2]);
                atomicAdd(O + (rbase + 8) * DD + d + 1, Oc[nf][3]);
            }
        }
    }
}

// ---------------- depthwise causal conv ----------------
__global__ __launch_bounds__(512) void conv_kernel(const float* __restrict__ z,
                                                   const float* __restrict__ w,
                                                   const float* __restrict__ bias,
                                                   float* __restrict__ mf) {
    int d0 = threadIdx.x * 2;
    int t = blockIdx.x * 8 + threadIdx.y;
    int b = blockIdx.y;
    float2 bv = *(const float2*)(bias + d0);
    ull acc = pack2(bv.x, bv.y);
    int kstart = (KK - 1) - t;
    if (kstart < 0) kstart = 0;
    const float* zp = z + ((long long)b * TT + t - (KK - 1)) * DD + d0;
    const float* wp = w + d0;
#pragma unroll 4
    for (int k = kstart; k < KK; k++)
        fma2(acc, *(const ull*)(zp + (long long)k * DD), *(const ull*)(wp + (long long)k * DD));
    float2 res = unpk(acc);
    *(float2*)(mf + ((long long)b * TT + t) * DD + d0) = res;
}

// ================== 32-row MMA GEMM kernels: smem layout ==================
// A hi 8K | A lo 8K | W hi 32K | W lo 32K | red 512B = 80.5KB -> 2 CTAs/SM
#define F_AH 0
#define F_AL 8192
#define F_WH 16384
#define F_WL 49152
#define F_RED 81920
#define EPI4_SMEM 82432

// ---------------- dual projection via MMA: kh + qh from z (32-row tiles) ----------------
__global__ __launch_bounds__(256, 2) void dual_mma(
    const float* __restrict__ X,
    const unsigned short* __restrict__ Wkh_, const unsigned short* __restrict__ Wkl_,
    const float* __restrict__ bk,
    const unsigned short* __restrict__ Wqh_, const unsigned short* __restrict__ Wql_,
    const float* __restrict__ bq,
    unsigned short* __restrict__ khh, unsigned short* __restrict__ khl,
    unsigned short* __restrict__ qhh, unsigned short* __restrict__ qhl) {
    extern __shared__ char smc[];
    const uint32_t sbase = smem_u32(smc);
    float* red = (float*)(smc + F_RED);
    const int tid = threadIdx.x;
    const int lane = tid & 31, w = tid >> 5;
    const int wr = w & 1, wc = w >> 1;
    const int ncol0 = wc * 32;
    const int g = lane >> 3, r = lane & 7;
    const long long row0 = (long long)blockIdx.x * 32;
    const int rowL = wr * 16 + (lane >> 2);
    const long long gA = row0 + rowL;
    const long long gB = gA + 8;

    for (int t = tid; t < 512; t += 256) {
        int row = t >> 4, d0 = (t & 15) * 8;
        const float* src = X + (row0 + row) * DD + d0;
        cvt_store8o(smc, F_AH, F_AL, row, d0, *(const float4*)src, *(const float4*)(src + 4));
    }
    for (int t = tid; t < 2048; t += 256) {
        int row = t >> 4, d0 = (t & 15) * 8;
        uint32_t off = sw_off(row, d0);
        *(uint4*)(smc + F_WH + off) = *(const uint4*)(Wkh_ + row * DD + d0);
        *(uint4*)(smc + F_WL + off) = *(const uint4*)(Wkl_ + row * DD + d0);
    }
    __syncthreads();

    float C[4][4];
#pragma unroll
    for (int nf = 0; nf < 4; nf++)
#pragma unroll
        for (int e = 0; e < 4; e++) C[nf][e] = 0.f;

    // ---- GEMM1: C = z @ Wk (3-pass, sync-free) ----
#pragma unroll
    for (int kc = 0; kc < 8; kc++) {
        uint32_t aoff = sw_off(wr * 16 + ((g & 1) ? 8 : 0) + r, kc * 16 + ((g >> 1) ? 8 : 0));
        uint32_t ah0, ah1, ah2, ah3, al0, al1, al2, al3;
        ldsm4(ah0, ah1, ah2, ah3, sbase + F_AH + aoff);
        ldsm4(al0, al1, al2, al3, sbase + F_AL + aoff);
        uint32_t th[2][4], tl[2][4];
#pragma unroll
        for (int nfp = 0; nfp < 2; nfp++) {
            uint32_t boff = sw_off(kc * 16 + ((g & 1) ? 8 : 0) + r,
                                   ncol0 + nfp * 16 + ((g >> 1) ? 8 : 0));
            ldsm4t(th[nfp][0], th[nfp][1], th[nfp][2], th[nfp][3], sbase + F_WH + boff);
            ldsm4t(tl[nfp][0], tl[nfp][1], tl[nfp][2], tl[nfp][3], sbase + F_WL + boff);
        }
#pragma unroll
        for (int nfp = 0; nfp < 2; nfp++) {
            mma16816(C[2 * nfp],     ah0, ah1, ah2, ah3, th[nfp][0], th[nfp][1]);
            mma16816(C[2 * nfp + 1], ah0, ah1, ah2, ah3, th[nfp][2], th[nfp][3]);
        }
#pragma unroll
        for (int nfp = 0; nfp < 2; nfp++) {
            mma16816(C[2 * nfp],     ah0, ah1, ah2, ah3, tl[nfp][0], tl[nfp][1]);
            mma16816(C[2 * nfp + 1], ah0, ah1, ah2, ah3, tl[nfp][2], tl[nfp][3]);
        }
#pragma unroll
        for (int nfp = 0; nfp < 2; nfp++) {
            mma16816(C[2 * nfp],     al0, al1, al2, al3, th[nfp][0], th[nfp][1]);
            mma16816(C[2 * nfp + 1], al0, al1, al2, al3, th[nfp][2], th[nfp][3]);
        }
    }

    // ---- kh = norm(C + bk) ----
    float qsA = 0.f, qsB = 0.f;
#pragma unroll
    for (int nf = 0; nf < 4; nf++) {
        int col = ncol0 + nf * 8 + 2 * (lane & 3);
        float2 bkv = *(const float2*)(bk + col);
        C[nf][0] += bkv.x; C[nf][1] += bkv.y;
        C[nf][2] += bkv.x; C[nf][3] += bkv.y;
        qsA += C[nf][0] * C[nf][0] + C[nf][1] * C[nf][1];
        qsB += C[nf][2] * C[nf][2] + C[nf][3] * C[nf][3];
    }
    qsA += __shfl_xor_sync(0xffffffffu, qsA, 1);
    qsA += __shfl_xor_sync(0xffffffffu, qsA, 2);
    qsB += __shfl_xor_sync(0xffffffffu, qsB, 1);
    qsB += __shfl_xor_sync(0xffffffffu, qsB, 2);
    if ((lane & 3) == 0) {
        red[wc * 32 + rowL] = qsA;
        red[wc * 32 + rowL + 8] = qsB;
    }
    __syncthreads();
    qsA = red[rowL] + red[32 + rowL] + red[64 + rowL] + red[96 + rowL];
    qsB = red[rowL + 8] + red[32 + rowL + 8] + red[64 + rowL + 8] + red[96 + rowL + 8];
    __syncthreads();
    // rewrite W with Wq (all warps past GEMM1 reads)
    for (int t = tid; t < 2048; t += 256) {
        int row = t >> 4, d0 = (t & 15) * 8;
        uint32_t off = sw_off(row, d0);
        *(uint4*)(smc + F_WH + off) = *(const uint4*)(Wqh_ + row * DD + d0);
        *(uint4*)(smc + F_WL + off) = *(const uint4*)(Wql_ + row * DD + d0);
    }
    {
        float qiA = __fdividef(1.f, fmaxf(sqrtf(qsA), 1e-8f));
        float qiB = __fdividef(1.f, fmaxf(sqrtf(qsB), 1e-8f));
#pragma unroll
        for (int nf = 0; nf < 4; nf++) {
            int col = ncol0 + nf * 8 + 2 * (lane & 3);
            uint32_t h, l;
            bsplit2(C[nf][0] * qiA, C[nf][1] * qiA, h, l);
            *(uint32_t*)(khh + gA * DD + col) = h;
            *(uint32_t*)(khl + gA * DD + col) = l;
            bsplit2(C[nf][2] * qiB, C[nf][3] * qiB, h, l);
            *(uint32_t*)(khh + gB * DD + col) = h;
            *(uint32_t*)(khl + gB * DD + col) = l;
        }
    }
    __syncthreads();

    // ---- GEMM2: C = z @ Wq ----
#pragma unroll
    for (int nf = 0; nf < 4; nf++)
#pragma unroll
        for (int e = 0; e < 4; e++) C[nf][e] = 0.f;
#pragma unroll
    for (int kc = 0; kc < 8; kc++) {
        uint32_t aoff = sw_off(wr * 16 + ((g & 1) ? 8 : 0) + r, kc * 16 + ((g >> 1) ? 8 : 0));
        uint32_t ah0, ah1, ah2, ah3, al0, al1, al2, al3;
        ldsm4(ah0, ah1, ah2, ah3, sbase + F_AH + aoff);
        ldsm4(al0, al1, al2, al3, sbase + F_AL + aoff);
        uint32_t th[2][4], tl[2][4];
#pragma unroll
        for (int nfp = 0; nfp < 2; nfp++) {
            uint32_t boff = sw_off(kc * 16 + ((g & 1) ? 8 : 0) + r,
                                   ncol0 + nfp * 16 + ((g >> 1) ? 8 : 0));
            ldsm4t(th[nfp][0], th[nfp][1], th[nfp][2], th[nfp][3], sbase + F_WH + boff);
            ldsm4t(tl[nfp][0], tl[nfp][1], tl[nfp][2], tl[nfp][3], sbase + F_WL + boff);
        }
#pragma unroll
        for (int nfp = 0; nfp < 2; nfp++) {
            mma16816(C[2 * nfp],     ah0, ah1, ah2, ah3, th[nfp][0], th[nfp][1]);
            mma16816(C[2 * nfp + 1], ah0, ah1, ah2, ah3, th[nfp][2], th[nfp][3]);
        }
#pragma unroll
        for (int nfp = 0; nfp < 2; nfp++) {
            mma16816(C[2 * nfp],     ah0, ah1, ah2, ah3, tl[nfp][0], tl[nfp][1]);
            mma16816(C[2 * nfp + 1], ah0, ah1, ah2, ah3, tl[nfp][2], tl[nfp][3]);
        }
#pragma unroll
        for (int nfp = 0; nfp < 2; nfp++) {
            mma16816(C[2 * nfp],     al0, al1, al2, al3, th[nfp][0], th[nfp][1]);
            mma16816(C[2 * nfp + 1], al0, al1, al2, al3, th[nfp][2], th[nfp][3]);
        }
    }

    // ---- qh = norm(C + bq) ----
    qsA = 0.f; qsB = 0.f;
#pragma unroll
    for (int nf = 0; nf < 4; nf++) {
        int col = ncol0 + nf * 8 + 2 * (lane & 3);
        float2 bqv = *(const float2*)(bq + col);
        C[nf][0] += bqv.x; C[nf][1] += bqv.y;
        C[nf][2] += bqv.x; C[nf][3] += bqv.y;
        qsA += C[nf][0] * C[nf][0] + C[nf][1] * C[nf][1];
        qsB += C[nf][2] * C[nf][2] + C[nf][3] * C[nf][3];
    }
    qsA += __shfl_xor_sync(0xffffffffu, qsA, 1);
    qsA += __shfl_xor_sync(0xffffffffu, qsA, 2);
    qsB += __shfl_xor_sync(0xffffffffu, qsB, 1);
    qsB += __shfl_xor_sync(0xffffffffu, qsB, 2);
    if ((lane & 3) == 0) {
        red[wc * 32 + rowL] = qsA;
        red[wc * 32 + rowL + 8] = qsB;
    }
    __syncthreads();
    qsA = red[rowL] + red[32 + rowL] + red[64 + rowL] + red[96 + rowL];
    qsB = red[rowL + 8] + red[32 + rowL + 8] + red[64 + rowL + 8] + red[96 + rowL + 8];
    float qiA = __fdividef(1.f, fmaxf(sqrtf(qsA), 1e-8f));
    float qiB = __fdividef(1.f, fmaxf(sqrtf(qsB), 1e-8f));
#pragma unroll
    for (int nf = 0; nf < 4; nf++) {
        int col = ncol0 + nf * 8 + 2 * (lane & 3);
        uint32_t h, l;
        bsplit2(C[nf][0] * qiA, C[nf][1] * qiA, h, l);
        *(uint32_t*)(qhh + gA * DD + col) = h;
        *(uint32_t*)(qhl + gA * DD + col) = l;
        bsplit2(C[nf][2] * qiB, C[nf][3] * qiB, h, l);
        *(uint32_t*)(qhh + gB * DD + col) = h;
        *(uint32_t*)(qhl + gB * DD + col) = l;
    }
}

// ================== MMA epilogue: 32-row tiles, full W resident ==================
__global__ __launch_bounds__(256, 2) void epilogue_mma(
    const float* __restrict__ A0,
    const unsigned short* __restrict__ Woh, const unsigned short* __restrict__ Wol,
    const float* __restrict__ bo,
    const unsigned short* __restrict__ Wqh, const unsigned short* __restrict__ Wql,
    const float* __restrict__ bq,
    const float* __restrict__ mf, const float* __restrict__ zin,
    const float* __restrict__ zbase, float* __restrict__ vacc,
    float* __restrict__ zc, unsigned short* __restrict__ qhh,
    unsigned short* __restrict__ qhl, float* __restrict__ out,
    float sw, float rc, int first, int has_next) {
    extern __shared__ char smc[];
    const uint32_t sbase = smem_u32(smc);
    float* red = (float*)(smc + F_RED);
    const int tid = threadIdx.x;
    const int lane = tid & 31, w = tid >> 5;
    const int wr = w & 1, wc = w >> 1;
    const int ncol0 = wc * 32;
    const int g = lane >> 3, r = lane & 7;
    const long long row0 = (long long)blockIdx.x * 32;
    const int rowL = wr * 16 + (lane >> 2);
    const long long gA = row0 + rowL;
    const long long gB = gA + 8;

    for (int t = tid; t < 512; t += 256) {
        int row = t >> 4, d0 = (t & 15) * 8;
        const float* src = A0 + (row0 + row) * DD + d0;
        cvt_store8o(smc, F_AH, F_AL, row, d0, *(const float4*)src, *(const float4*)(src + 4));
    }
    for (int t = tid; t < 2048; t += 256) {
        int row = t >> 4, d0 = (t & 15) * 8;
        uint32_t off = sw_off(row, d0);
        *(uint4*)(smc + F_WH + off) = *(const uint4*)(Woh + row * DD + d0);
        *(uint4*)(smc + F_WL + off) = *(const uint4*)(Wol + row * DD + d0);
    }
    __syncthreads();

    float C[4][4];
#pragma unroll
    for (int nf = 0; nf < 4; nf++)
#pragma unroll
        for (int e = 0; e < 4; e++) C[nf][e] = 0.f;

    // ---- GEMM1: C = A @ Wo ----
#pragma unroll
    for (int kc = 0; kc < 8; kc++) {
        uint32_t aoff = sw_off(wr * 16 + ((g & 1) ? 8 : 0) + r, kc * 16 + ((g >> 1) ? 8 : 0));
        uint32_t ah0, ah1, ah2, ah3, al0, al1, al2, al3;
        ldsm4(ah0, ah1, ah2, ah3, sbase + F_AH + aoff);
        ldsm4(al0, al1, al2, al3, sbase + F_AL + aoff);
        uint32_t th[2][4], tl[2][4];
#pragma unroll
        for (int nfp = 0; nfp < 2; nfp++) {
            uint32_t boff = sw_off(kc * 16 + ((g & 1) ? 8 : 0) + r,
                                   ncol0 + nfp * 16 + ((g >> 1) ? 8 : 0));
            ldsm4t(th[nfp][0], th[nfp][1], th[nfp][2], th[nfp][3], sbase + F_WH + boff);
            ldsm4t(tl[nfp][0], tl[nfp][1], tl[nfp][2], tl[nfp][3], sbase + F_WL + boff);
        }
#pragma unroll
        for (int nfp = 0; nfp < 2; nfp++) {
            mma16816(C[2 * nfp],     ah0, ah1, ah2, ah3, th[nfp][0], th[nfp][1]);
            mma16816(C[2 * nfp + 1], ah0, ah1, ah2, ah3, th[nfp][2], th[nfp][3]);
        }
#pragma unroll
        for (int nfp = 0; nfp < 2; nfp++) {
            mma16816(C[2 * nfp],     ah0, ah1, ah2, ah3, tl[nfp][0], tl[nfp][1]);
            mma16816(C[2 * nfp + 1], ah0, ah1, ah2, ah3, tl[nfp][2], tl[nfp][3]);
        }
#pragma unroll
        for (int nfp = 0; nfp < 2; nfp++) {
            mma16816(C[2 * nfp],     al0, al1, al2, al3, th[nfp][0], th[nfp][1]);
            mma16816(C[2 * nfp + 1], al0, al1, al2, al3, th[nfp][2], th[nfp][3]);
        }
    }

    // ---- bias + mf, tangent dot ----
    float dotA = 0.f, dotB = 0.f;
#pragma unroll
    for (int nf = 0; nf < 4; nf++) {
        int col = ncol0 + nf * 8 + 2 * (lane & 3);
        float2 bov = *(const float2*)(bo + col);
        float2 mA = *(const float2*)(mf + gA * DD + col);
        float2 mB = *(const float2*)(mf + gB * DD + col);
        C[nf][0] += bov.x + mA.x; C[nf][1] += bov.y + mA.y;
        C[nf][2] += bov.x + mB.x; C[nf][3] += bov.y + mB.y;
        float2 zA = *(const float2*)(zin + gA * DD + col);
        float2 zB = *(const float2*)(zin + gB * DD + col);
        dotA += C[nf][0] * zA.x + C[nf][1] * zA.y;
        dotB += C[nf][2] * zB.x + C[nf][3] * zB.y;
    }
    dotA += __shfl_xor_sync(0xffffffffu, dotA, 1);
    dotA += __shfl_xor_sync(0xffffffffu, dotA, 2);
    dotB += __shfl_xor_sync(0xffffffffu, dotB, 1);
    dotB += __shfl_xor_sync(0xffffffffu, dotB, 2);
    if ((lane & 3) == 0) {
        red[wc * 32 + rowL] = dotA;
        red[wc * 32 + rowL + 8] = dotB;
    }
    __syncthreads();
    dotA = red[rowL] + red[32 + rowL] + red[64 + rowL] + red[96 + rowL];
    dotB = red[rowL + 8] + red[32 + rowL + 8] + red[64 + rowL + 8] + red[96 + rowL + 8];
    __syncthreads();

    // ---- proj, vacc update, zn sumsq; load Wq into W buffer ----
    for (int t = tid; t < 2048; t += 256) {
        int row = t >> 4, d0 = (t & 15) * 8;
        uint32_t off = sw_off(row, d0);
        *(uint4*)(smc + F_WH + off) = *(const uint4*)(Wqh + row * DD + d0);
        *(uint4*)(smc + F_WL + off) = *(const uint4*)(Wql + row * DD + d0);
    }
    float ssA = 0.f, ssB = 0.f;
#pragma unroll
    for (int nf = 0; nf < 4; nf++) {
        int col = ncol0 + nf * 8 + 2 * (lane & 3);
        float2 zA = *(const float2*)(zin + gA * DD + col);
        float2 zB = *(const float2*)(zin + gB * DD + col);
        C[nf][0] -= dotA * zA.x; C[nf][1] -= dotA * zA.y;
        C[nf][2] -= dotB * zB.x; C[nf][3] -= dotB * zB.y;
        float2* vA = (float2*)(vacc + gA * DD + col);
        float2* vB = (float2*)(vacc + gB * DD + col);
        float2 vpA = first ? make_float2(0.f, 0.f) : *vA;
        float2 vpB = first ? make_float2(0.f, 0.f) : *vB;
        float2 vnA = make_float2(vpA.x + sw * C[nf][0], vpA.y + sw * C[nf][1]);
        float2 vnB = make_float2(vpB.x + sw * C[nf][2], vpB.y + sw * C[nf][3]);
        *vA = vnA; *vB = vnB;
        float2 zbA = *(const float2*)(zbase + gA * DD + col);
        float2 zbB = *(const float2*)(zbase + gB * DD + col);
        if (has_next) {
            float a0v = zbA.x + rc * C[nf][0], a1v = zbA.y + rc * C[nf][1];
            float b0v = zbB.x + rc * C[nf][2], b1v = zbB.y + rc * C[nf][3];
            ssA += a0v * a0v + a1v * a1v;
            ssB += b0v * b0v + b1v * b1v;
            C[nf][0] = a0v; C[nf][1] = a1v; C[nf][2] = b0v; C[nf][3] = b1v;
        } else {
            float a0v = zbA.x + vnA.x, a1v = zbA.y + vnA.y;
            float b0v = zbB.x + vnB.x, b1v = zbB.y + vnB.y;
            ssA += a0v * a0v + a1v * a1v;
            ssB += b0v * b0v + b1v * b1v;
            C[nf][0] = a0v; C[nf][1] = a1v; C[nf][2] = b0v; C[nf][3] = b1v;
        }
    }
    ssA += __shfl_xor_sync(0xffffffffu, ssA, 1);
    ssA += __shfl_xor_sync(0xffffffffu, ssA, 2);
    ssB += __shfl_xor_sync(0xffffffffu, ssB, 1);
    ssB += __shfl_xor_sync(0xffffffffu, ssB, 2);
    if ((lane & 3) == 0) {
        red[wc * 32 + rowL] = ssA;
        red[wc * 32 + rowL + 8] = ssB;
    }
    __syncthreads();
    ssA = red[rowL] + red[32 + rowL] + red[64 + rowL] + red[96 + rowL];
    ssB = red[rowL + 8] + red[32 + rowL + 8] + red[64 + rowL + 8] + red[96 + rowL + 8];
    __syncthreads();
    float invA = __fdividef(1.f, fmaxf(sqrtf(ssA), 1e-8f));
    float invB = __fdividef(1.f, fmaxf(sqrtf(ssB), 1e-8f));

    if (!has_next) {
#pragma unroll
        for (int nf = 0; nf < 4; nf++) {
            int col = ncol0 + nf * 8 + 2 * (lane & 3);
            *(float2*)(out + gA * DD + col) = make_float2(C[nf][0] * invA, C[nf][1] * invA);
            *(float2*)(out + gB * DD + col) = make_float2(C[nf][2] * invB, C[nf][3] * invB);
        }
        return;
    }

    // ---- z0 = norm(zbase + rc*proj): store zc + restage into A tile ----
#pragma unroll
    for (int nf = 0; nf < 4; nf++) {
        int col = ncol0 + nf * 8 + 2 * (lane & 3);
        float a0v = C[nf][0] * invA, a1v = C[nf][1] * invA;
        float b0v = C[nf][2] * invB, b1v = C[nf][3] * invB;
        *(float2*)(zc + gA * DD + col) = make_float2(a0v, a1v);
        *(float2*)(zc + gB * DD + col) = make_float2(b0v, b1v);
        uint32_t h, l;
        bsplit2(a0v, a1v, h, l);
        *(uint32_t*)(smc + F_AH + sw_off(rowL, col)) = h;
        *(uint32_t*)(smc + F_AL + sw_off(rowL, col)) = l;
        bsplit2(b0v, b1v, h, l);
        *(uint32_t*)(smc + F_AH + sw_off(rowL + 8, col)) = h;
        *(uint32_t*)(smc + F_AL + sw_off(rowL + 8, col)) = l;
    }
    __syncthreads();

    // ---- GEMM2: C = z0 @ Wq ----
#pragma unroll
    for (int nf = 0; nf < 4; nf++)
#pragma unroll
        for (int e = 0; e < 4; e++) C[nf][e] = 0.f;
#pragma unroll
    for (int kc = 0; kc < 8; kc++) {
        uint32_t aoff = sw_off(wr * 16 + ((g & 1) ? 8 : 0) + r, kc * 16 + ((g >> 1) ? 8 : 0));
        uint32_t ah0, ah1, ah2, ah3, al0, al1, al2, al3;
        ldsm4(ah0, ah1, ah2, ah3, sbase + F_AH + aoff);
        ldsm4(al0, al1, al2, al3, sbase + F_AL + aoff);
        uint32_t th[2][4], tl[2][4];
#pragma unroll
        for (int nfp = 0; nfp < 2; nfp++) {
            uint32_t boff = sw_off(kc * 16 + ((g & 1) ? 8 : 0) + r,
                                   ncol0 + nfp * 16 + ((g >> 1) ? 8 : 0));
            ldsm4t(th[nfp][0], th[nfp][1], th[nfp][2], th[nfp][3], sbase + F_WH + boff);
            ldsm4t(tl[nfp][0], tl[nfp][1], tl[nfp][2], tl[nfp][3], sbase + F_WL + boff);
        }
#pragma unroll
        for (int nfp = 0; nfp < 2; nfp++) {
            mma16816(C[2 * nfp],     ah0, ah1, ah2, ah3, th[nfp][0], th[nfp][1]);
            mma16816(C[2 * nfp + 1], ah0, ah1, ah2, ah3, th[nfp][2], th[nfp][3]);
        }
#pragma unroll
        for (int nfp = 0; nfp < 2; nfp++) {
            mma16816(C[2 * nfp],     ah0, ah1, ah2, ah3, tl[nfp][0], tl[nfp][1]);
            mma16816(C[2 * nfp + 1], ah0, ah1, ah2, ah3, tl[nfp][2], tl[nfp][3]);
        }
#pragma unroll
        for (int nfp = 0; nfp < 2; nfp++) {
            mma16816(C[2 * nfp],     al0, al1, al2, al3, th[nfp][0], th[nfp][1]);
            mma16816(C[2 * nfp + 1], al0, al1, al2, al3, th[nfp][2], th[nfp][3]);
        }
    }

    // ---- qh = norm(C + bq) -> prepacked bf16 hi/lo ----
    float qsA = 0.f, qsB = 0.f;
#pragma unroll
    for (int nf = 0; nf < 4; nf++) {
        int col = ncol0 + nf * 8 + 2 * (lane & 3);
        float2 bqv = *(const float2*)(bq + col);
        C[nf][0] += bqv.x; C[nf][1] += bqv.y;
        C[nf][2] += bqv.x; C[nf][3] += bqv.y;
        qsA += C[nf][0] * C[nf][0] + C[nf][1] * C[nf][1];
        qsB += C[nf][2] * C[nf][2] + C[nf][3] * C[nf][3];
    }
    qsA += __shfl_xor_sync(0xffffffffu, qsA, 1);
    qsA += __shfl_xor_sync(0xffffffffu, qsA, 2);
    qsB += __shfl_xor_sync(0xffffffffu, qsB, 1);
    qsB += __shfl_xor_sync(0xffffffffu, qsB, 2);
    if ((lane & 3) == 0) {
        red[wc * 32 + rowL] = qsA;
        red[wc * 32 + rowL + 8] = qsB;
    }
    __syncthreads();
    qsA = red[rowL] + red[32 + rowL] + red[64 + rowL] + red[96 + rowL];
    qsB = red[rowL + 8] + red[32 + rowL + 8] + red[64 + rowL + 8] + red[96 + rowL + 8];
    float qiA = __fdividef(1.f, fmaxf(sqrtf(qsA), 1e-8f));
    float qiB = __fdividef(1.f, fmaxf(sqrtf(qsB), 1e-8f));
#pragma unroll
    for (int nf = 0; nf < 4; nf++) {
        int col = ncol0 + nf * 8 + 2 * (lane & 3);
        uint32_t h, l;
        bsplit2(C[nf][0] * qiA, C[nf][1] * qiA, h, l);
        *(uint32_t*)(qhh + gA * DD + col) = h;
        *(uint32_t*)(qhl + gA * DD + col) = l;
        bsplit2(C[nf][2] * qiB, C[nf][3] * qiB, h, l);
        *(uint32_t*)(qhh + gB * DD + col) = h;
        *(uint32_t*)(qhl + gB * DD + col) = l;
    }
}

// ---------------- launch ----------------
extern "C" void kernel_launch(void* const* d_in, const int* in_sizes, int n_in,
                              void* d_out, int out_size) {
    const float* z  = (const float*)d_in[0];
    const float* ck = (const float*)d_in[1];
    const float* cb = (const float*)d_in[2];
    const float* Wq = (const float*)d_in[3];
    const float* bq = (const float*)d_in[4];
    const float* Wk = (const float*)d_in[5];
    const float* bk = (const float*)d_in[6];
    const float* Wo = (const float*)d_in[7];
    const float* bo = (const float*)d_in[8];
    float* out = (float*)d_out;

    float *mf, *a0, *zc, *va;
    unsigned short *qhh, *qhl, *khh, *khl, *woh, *wol, *wqh, *wql, *wkh, *wkl;
    cudaGetSymbolAddress((void**)&mf, g_mf);
    cudaGetSymbolAddress((void**)&a0, g_a0);
    cudaGetSymbolAddress((void**)&zc, g_zc);
    cudaGetSymbolAddress((void**)&va, g_va);
    cudaGetSymbolAddress((void**)&qhh, g_qhh);
    cudaGetSymbolAddress((void**)&qhl, g_qhl);
    cudaGetSymbolAddress((void**)&khh, g_khh);
    cudaGetSymbolAddress((void**)&khl, g_khl);
    cudaGetSymbolAddress((void**)&woh, g_woh);
    cudaGetSymbolAddress((void**)&wol, g_wol);
    cudaGetSymbolAddress((void**)&wqh, g_wqh);
    cudaGetSymbolAddress((void**)&wql, g_wql);
    cudaGetSymbolAddress((void**)&wkh, g_wkh);
    cudaGetSymbolAddress((void**)&wkl, g_wkl);

    cudaFuncSetAttribute(dual_mma, cudaFuncAttributeMaxDynamicSharedMemorySize, EPI4_SMEM);
    cudaFuncSetAttribute(epilogue_mma, cudaFuncAttributeMaxDynamicSharedMemorySize, EPI4_SMEM);
    cudaFuncSetAttribute(attn_kernel, cudaFuncAttributeMaxDynamicSharedMemorySize, ATTN_SMEM);

    prep_w<<<32, 256>>>(Wo, Wq, Wk, woh, wol, wqh, wql, wkh, wkl);
    conv_kernel<<<dim3(TT / 8, BB), dim3(64, 8)>>>(z, ck, cb, mf);
    dual_mma<<<BT / 32, 256, EPI4_SMEM>>>(z, wkh, wkl, bk, wqh, wql, bq,
                                          khh, khl, qhh, qhl);

    const float sws[4] = {1.f / 6.f, 2.f / 6.f, 2.f / 6.f, 1.f / 6.f};
    const float rcs[4] = {0.5f, 0.5f, 1.0f, 0.f};
    const float* zcur = z;
    for (int s = 0; s < 4; s++) {
        cudaMemsetAsync(a0, 0, (size_t)BT * DD * sizeof(float));
        attn_kernel<<<dim3(32, 9), 128, ATTN_SMEM>>>(qhh, qhl, khh, khl, a0);
        epilogue_mma<<<BT / 32, 256, EPI4_SMEM>>>(a0, woh, wol, bo, wqh, wql, bq,
                                                  mf, zcur, z, va, zc, qhh, qhl, out,
                                                  sws[s], rcs[s], s == 0 ? 1 : 0,
                                                  s < 3 ? 1 : 0);
        zcur = zc;
    }
}

// round 17
// speedup vs baseline: 1.0849x; 1.0103x over previous
#include <cuda_runtime.h>
#include <cstdint>

#define BB 2
#define TT 4096
#define DD 128
#define KK 256
#define BT (BB * TT)

// ---------------- scratch ----------------
__device__ float g_mf[BT * DD];
__device__ float g_a0[4ll * BT * DD];   // per-stage attention accumulators
__device__ float g_zc[BT * DD];
__device__ float g_va[BT * DD];
__device__ unsigned short g_qhh[BT * DD];
__device__ unsigned short g_qhl[BT * DD];
__device__ unsigned short g_khh[BT * DD];
__device__ unsigned short g_khl[BT * DD];
__device__ unsigned short g_woh[DD * DD];
__device__ unsigned short g_wol[DD * DD];
__device__ unsigned short g_wqh[DD * DD];
__device__ unsigned short g_wql[DD * DD];
__device__ unsigned short g_wkh[DD * DD];
__device__ unsigned short g_wkl[DD * DD];

// ================= helpers =================
typedef unsigned long long ull;
__device__ __forceinline__ uint32_t smem_u32(const void* p) {
    uint32_t a;
    asm("{ .reg .u64 t; cvta.to.shared.u64 t, %1; cvt.u32.u64 %0, t; }" : "=r"(a) : "l"(p));
    return a;
}
__device__ __forceinline__ void ldsm4(uint32_t& r0, uint32_t& r1, uint32_t& r2, uint32_t& r3,
                                      uint32_t addr) {
    asm volatile("ldmatrix.sync.aligned.m8n8.x4.shared.b16 {%0,%1,%2,%3}, [%4];"
                 : "=r"(r0), "=r"(r1), "=r"(r2), "=r"(r3) : "r"(addr));
}
__device__ __forceinline__ void ldsm4t(uint32_t& r0, uint32_t& r1, uint32_t& r2, uint32_t& r3,
                                       uint32_t addr) {
    asm volatile("ldmatrix.sync.aligned.m8n8.x4.trans.shared.b16 {%0,%1,%2,%3}, [%4];"
                 : "=r"(r0), "=r"(r1), "=r"(r2), "=r"(r3) : "r"(addr));
}
__device__ __forceinline__ void mma16816(float* c, uint32_t a0, uint32_t a1, uint32_t a2,
                                         uint32_t a3, uint32_t b0, uint32_t b1) {
    asm volatile(
        "mma.sync.aligned.m16n8k16.row.col.f32.bf16.bf16.f32 "
        "{%0,%1,%2,%3}, {%4,%5,%6,%7}, {%8,%9}, {%0,%1,%2,%3};"
        : "+f"(c[0]), "+f"(c[1]), "+f"(c[2]), "+f"(c[3])
        : "r"(a0), "r"(a1), "r"(a2), "r"(a3), "r"(b0), "r"(b1));
}
__device__ __forceinline__ void bsplit2(float x0, float x1, uint32_t& h, uint32_t& l) {
    uint16_t h0, h1, l0, l1;
    asm("cvt.rn.bf16.f32 %0, %1;" : "=h"(h0) : "f"(x0));
    asm("cvt.rn.bf16.f32 %0, %1;" : "=h"(h1) : "f"(x1));
    float f0 = __uint_as_float((uint32_t)h0 << 16);
    float f1 = __uint_as_float((uint32_t)h1 << 16);
    asm("cvt.rn.bf16.f32 %0, %1;" : "=h"(l0) : "f"(x0 - f0));
    asm("cvt.rn.bf16.f32 %0, %1;" : "=h"(l1) : "f"(x1 - f1));
    h = (uint32_t)h0 | ((uint32_t)h1 << 16);
    l = (uint32_t)l0 | ((uint32_t)l1 << 16);
}
__device__ __forceinline__ uint32_t sw_off(int row, int d) {
    return (uint32_t)(row * 256 + ((((d >> 3) ^ (row & 7)) & 15) << 4) + (d & 7) * 2);
}
__device__ __forceinline__ float sinpoly(float x) {
    float x2 = x * x;
    float pp = fmaf(x2, 2.7557319e-06f, -1.9841270e-04f);
    pp = fmaf(x2, pp, 8.3333333e-03f);
    pp = fmaf(x2, pp, -1.6666667e-01f);
    return fmaf(x * x2, pp, x);
}
__device__ __forceinline__ ull pack2(float x, float y) {
    ull r; asm("mov.b64 %0, {%1, %2};" : "=l"(r) : "f"(x), "f"(y)); return r;
}
__device__ __forceinline__ void fma2(ull& d, ull a, ull b) {
    asm("fma.rn.f32x2 %0, %1, %2, %0;" : "+l"(d) : "l"(a), "l"(b));
}
__device__ __forceinline__ float2 unpk(ull v) {
    float2 r; asm("mov.b64 {%0, %1}, %2;" : "=f"(r.x), "=f"(r.y) : "l"(v)); return r;
}

__device__ __forceinline__ void cvt_store8o(char* smcp, uint32_t hoff, uint32_t loff,
                                            int row, int col, float4 a, float4 b) {
    uint32_t hw[4], lw[4];
    bsplit2(a.x, a.y, hw[0], lw[0]);
    bsplit2(a.z, a.w, hw[1], lw[1]);
    bsplit2(b.x, b.y, hw[2], lw[2]);
    bsplit2(b.z, b.w, hw[3], lw[3]);
    uint32_t off = sw_off(row, col);
    *(uint4*)(smcp + hoff + off) = make_uint4(hw[0], hw[1], hw[2], hw[3]);
    *(uint4*)(smcp + loff + off) = make_uint4(lw[0], lw[1], lw[2], lw[3]);
}

// attn smem: Qhi 16K | Qlo 16K | K double-buffered (hi 16K + lo 16K) x2 = 96KB
#define QH_OFF 0
#define QL_OFF 16384
#define KBASE_OFF 32768
#define ATTN_SMEM 98304

// ---------------- causal sin-attention (R11 body, branch-free hot loop) ----------------
__global__ __launch_bounds__(128, 2) void attn_kernel(const unsigned short* __restrict__ Qhh,
                                                      const unsigned short* __restrict__ Qhl,
                                                      const unsigned short* __restrict__ Khh,
                                                      const unsigned short* __restrict__ Khl,
                                                      float* __restrict__ O) {
    extern __shared__ char smc[];
    const uint32_t sbase = smem_u32(smc);
    const int tid = threadIdx.x;
    const int lane = tid & 31, w = tid >> 5;
    const int P = blockIdx.x, split = blockIdx.y;
    const int g = lane >> 3, r = lane & 7;
    const int krow = tid >> 1, kc0 = (tid & 1) * 64;
    const int lo = (130 * split) / 9, hi = (130 * (split + 1)) / 9;

    int c = 0;
    for (int sp = 0; sp < 4; sp++) {
        const int b = sp >> 1;
        const int R = (sp & 1) ? (63 - P) : P;
        const int n = R + 1;
        int s_lo = lo - c; if (s_lo < 0) s_lo = 0;
        int s_hi = hi - c; if (s_hi > n) s_hi = n;
        c += n;
        if (s_lo >= s_hi) continue;

        const unsigned short* Qhb = Qhh + (long long)b * TT * DD;
        const unsigned short* Qlb = Qhl + (long long)b * TT * DD;
        const unsigned short* Khb = Khh + (long long)b * TT * DD;
        const unsigned short* Klb = Khl + (long long)b * TT * DD;

        __syncthreads();
        for (int t = tid; t < 1024; t += 128) {
            int row = t >> 4, d0 = (t & 15) * 8;
            long long src = ((long long)R * 64 + row) * DD + d0;
            uint32_t off = sw_off(row, d0);
            *(uint4*)(smc + QH_OFF + off) = *(const uint4*)(Qhb + src);
            *(uint4*)(smc + QL_OFF + off) = *(const uint4*)(Qlb + src);
        }
        {
            long long src = ((long long)s_lo * 64 + krow) * DD + kc0;
#pragma unroll
            for (int q = 0; q < 8; q++) {
                uint32_t off = sw_off(krow, kc0 + 8 * q);
                *(uint4*)(smc + KBASE_OFF + off) = *(const uint4*)(Khb + src + 8 * q);
                *(uint4*)(smc + KBASE_OFF + 16384 + off) = *(const uint4*)(Klb + src + 8 * q);
            }
        }
        float Oc[16][4];
#pragma unroll
        for (int nf = 0; nf < 16; nf++)
#pragma unroll
            for (int e = 0; e < 4; e++) Oc[nf][e] = 0.f;
        __syncthreads();

        uint32_t qah[8][4], qal[8][4];
#pragma unroll
        for (int kc = 0; kc < 8; kc++) {
            uint32_t aoff = sw_off(w * 16 + ((g & 1) ? 8 : 0) + r, kc * 16 + ((g >> 1) ? 8 : 0));
            ldsm4(qah[kc][0], qah[kc][1], qah[kc][2], qah[kc][3], sbase + QH_OFF + aoff);
            ldsm4(qal[kc][0], qal[kc][1], qal[kc][2], qal[kc][3], sbase + QL_OFF + aoff);
        }

        for (int sb = s_lo; sb < s_hi; sb++) {
            const int cur = (sb - s_lo) & 1;
            const uint32_t KH = KBASE_OFF + (uint32_t)cur * 32768;
            const uint32_t KL = KH + 16384;
            const bool pre = (sb + 1 < s_hi);
            const uint32_t NH = KBASE_OFF + (uint32_t)(1 - cur) * 32768;
            long long psrc = ((long long)(sb + 1) * 64 + krow) * DD + kc0;

            float C[8][4];
#pragma unroll
            for (int nf = 0; nf < 8; nf++)
#pragma unroll
                for (int e = 0; e < 4; e++) C[nf][e] = 0.f;
#pragma unroll
            for (int kc = 0; kc < 8; kc++) {
                int d0 = kc * 16;
                uint32_t bh[4][4], bl[4][4];
#pragma unroll
                for (int nfp = 0; nfp < 4; nfp++) {
                    uint32_t boff = sw_off(nfp * 16 + ((g >> 1) ? 8 : 0) + r,
                                           d0 + ((g & 1) ? 8 : 0));
                    ldsm4(bh[nfp][0], bh[nfp][1], bh[nfp][2], bh[nfp][3], sbase + KH + boff);
                    ldsm4(bl[nfp][0], bl[nfp][1], bl[nfp][2], bl[nfp][3], sbase + KL + boff);
                }
#pragma unroll
                for (int nfp = 0; nfp < 4; nfp++) {
                    mma16816(C[2 * nfp],     qah[kc][0], qah[kc][1], qah[kc][2], qah[kc][3], bh[nfp][0], bh[nfp][1]);
                    mma16816(C[2 * nfp + 1], qah[kc][0], qah[kc][1], qah[kc][2], qah[kc][3], bh[nfp][2], bh[nfp][3]);
                }
#pragma unroll
                for (int nfp = 0; nfp < 4; nfp++) {
                    mma16816(C[2 * nfp],     qah[kc][0], qah[kc][1], qah[kc][2], qah[kc][3], bl[nfp][0], bl[nfp][1]);
                    mma16816(C[2 * nfp + 1], qah[kc][0], qah[kc][1], qah[kc][2], qah[kc][3], bl[nfp][2], bl[nfp][3]);
                }
#pragma unroll
                for (int nfp = 0; nfp < 4; nfp++) {
                    mma16816(C[2 * nfp],     qal[kc][0], qal[kc][1], qal[kc][2], qal[kc][3], bh[nfp][0], bh[nfp][1]);
                    mma16816(C[2 * nfp + 1], qal[kc][0], qal[kc][1], qal[kc][2], qal[kc][3], bh[nfp][2], bh[nfp][3]);
                }
            }
            if (pre) {
#pragma unroll
                for (int q = 0; q < 8; q++)
                    *(uint4*)(smc + NH + sw_off(krow, kc0 + 8 * q)) =
                        *(const uint4*)(Khb + psrc + 8 * q);
            }

            uint32_t a2h[4][4], a2l[4][4];
            const int ig = R * 64 + w * 16 + (lane >> 2);
#pragma unroll
            for (int nf = 0; nf < 8; nf++) {
                int jb = sb * 64 + nf * 8 + 2 * (lane & 3);
                float s0 = sinpoly(C[nf][0]); if (jb > ig) s0 = 0.f;
                float s1 = sinpoly(C[nf][1]); if (jb + 1 > ig) s1 = 0.f;
                float s2 = sinpoly(C[nf][2]); if (jb > ig + 8) s2 = 0.f;
                float s3 = sinpoly(C[nf][3]); if (jb + 1 > ig + 8) s3 = 0.f;
                int kc2 = nf >> 1, hk = (nf & 1) ? 2 : 0;
                bsplit2(s0, s1, a2h[kc2][hk], a2l[kc2][hk]);
                bsplit2(s2, s3, a2h[kc2][hk + 1], a2l[kc2][hk + 1]);
            }

#pragma unroll
            for (int kc2 = 0; kc2 < 4; kc2++) {
                int j0 = kc2 * 16;
#pragma unroll
                for (int hh = 0; hh < 2; hh++) {
                    uint32_t th[4][4], tl[4][4];
#pragma unroll
                    for (int q = 0; q < 4; q++) {
                        int nfp = hh * 4 + q;
                        uint32_t boff = sw_off(j0 + ((g & 1) ? 8 : 0) + r,
                                               nfp * 16 + ((g >> 1) ? 8 : 0));
                        ldsm4t(th[q][0], th[q][1], th[q][2], th[q][3], sbase + KH + boff);
                        ldsm4t(tl[q][0], tl[q][1], tl[q][2], tl[q][3], sbase + KL + boff);
                    }
#pragma unroll
                    for (int q = 0; q < 4; q++) {
                        int nfp = hh * 4 + q;
                        mma16816(Oc[2 * nfp],     a2h[kc2][0], a2h[kc2][1], a2h[kc2][2], a2h[kc2][3], th[q][0], th[q][1]);
                        mma16816(Oc[2 * nfp + 1], a2h[kc2][0], a2h[kc2][1], a2h[kc2][2], a2h[kc2][3], th[q][2], th[q][3]);
                    }
#pragma unroll
                    for (int q = 0; q < 4; q++) {
                        int nfp = hh * 4 + q;
                        mma16816(Oc[2 * nfp],     a2h[kc2][0], a2h[kc2][1], a2h[kc2][2], a2h[kc2][3], tl[q][0], tl[q][1]);
                        mma16816(Oc[2 * nfp + 1], a2h[kc2][0], a2h[kc2][1], a2h[kc2][2], a2h[kc2][3], tl[q][2], tl[q][3]);
                    }
#pragma unroll
                    for (int q = 0; q < 4; q++) {
                        int nfp = hh * 4 + q;
                        mma16816(Oc[2 * nfp],     a2l[kc2][0], a2l[kc2][1], a2l[kc2][2], a2l[kc2][3], th[q][0], th[q][1]);
                        mma16816(Oc[2 * nfp + 1], a2l[kc2][0], a2l[kc2][1], a2l[kc2][2], a2l[kc2][3], th[q][2], th[q][3]);
                    }
                }
            }
            if (pre) {
#pragma unroll
                for (int q = 0; q < 8; q++)
                    *(uint4*)(smc + NH + 16384 + sw_off(krow, kc0 + 8 * q)) =
                        *(const uint4*)(Klb + psrc + 8 * q);
            }
            __syncthreads();
        }

        {
            long long rbase = (long long)b * TT + (long long)R * 64 + w * 16 + (lane >> 2);
#pragma unroll
            for (int nf = 0; nf < 16; nf++) {
                int d = nf * 8 + 2 * (lane & 3);
                atomicAdd(O + rbase * DD + d,       Oc[nf][0]);
                atomicAdd(O + rbase * DD + d + 1,   Oc[nf][1]);
                atomicAdd(O + (rbase + 8) * DD + d,     Oc[nf][2]);
                atomicAdd(O + (rbase + 8) * DD + d + 1, Oc[nf][3]);
            }
        }
    }
}

// ---------------- depthwise causal conv + fused W prepack ----------------
__global__ __launch_bounds__(512) void conv_kernel(const float* __restrict__ z,
                                                   const float* __restrict__ w,
                                                   const float* __restrict__ bias,
                                                   float* __restrict__ mf,
                                                   const float* __restrict__ Wo,
                                                   const float* __restrict__ Wq,
                                                   const float* __restrict__ Wk,
                                                   unsigned short* __restrict__ Woh,
                                                   unsigned short* __restrict__ Wol,
                                                   unsigned short* __restrict__ Wqh,
                                                   unsigned short* __restrict__ Wql,
                                                   unsigned short* __restrict__ Wkh,
                                                   unsigned short* __restrict__ Wkl) {
    if (blockIdx.y == 2) {
        // W prepack plane: blocks 0..15 cover 8192 threads, 2 elems each
        int i = blockIdx.x * 512 + threadIdx.y * 64 + threadIdx.x;
        if (i >= 8192) return;
        uint32_t h, l;
        float2 a = *(const float2*)(Wo + 2 * i);
        bsplit2(a.x, a.y, h, l);
        *(uint32_t*)(Woh + 2 * i) = h;
        *(uint32_t*)(Wol + 2 * i) = l;
        float2 b = *(const float2*)(Wq + 2 * i);
        bsplit2(b.x, b.y, h, l);
        *(uint32_t*)(Wqh + 2 * i) = h;
        *(uint32_t*)(Wql + 2 * i) = l;
        float2 c = *(const float2*)(Wk + 2 * i);
        bsplit2(c.x, c.y, h, l);
        *(uint32_t*)(Wkh + 2 * i) = h;
        *(uint32_t*)(Wkl + 2 * i) = l;
        return;
    }
    int d0 = threadIdx.x * 2;
    int t = blockIdx.x * 8 + threadIdx.y;
    int b = blockIdx.y;
    float2 bv = *(const float2*)(bias + d0);
    ull acc = pack2(bv.x, bv.y);
    int kstart = (KK - 1) - t;
    if (kstart < 0) kstart = 0;
    const float* zp = z + ((long long)b * TT + t - (KK - 1)) * DD + d0;
    const float* wp = w + d0;
#pragma unroll 4
    for (int k = kstart; k < KK; k++)
        fma2(acc, *(const ull*)(zp + (long long)k * DD), *(const ull*)(wp + (long long)k * DD));
    float2 res = unpk(acc);
    *(float2*)(mf + ((long long)b * TT + t) * DD + d0) = res;
}

// ================== 32-row MMA GEMM kernels: smem layout ==================
#define F_AH 0
#define F_AL 8192
#define F_WH 16384
#define F_WL 49152
#define F_RED 81920
#define EPI4_SMEM 82432

// ---------------- dual projection via MMA: kh + qh from z (32-row tiles) ----------------
__global__ __launch_bounds__(256, 2) void dual_mma(
    const float* __restrict__ X,
    const unsigned short* __restrict__ Wkh_, const unsigned short* __restrict__ Wkl_,
    const float* __restrict__ bk,
    const unsigned short* __restrict__ Wqh_, const unsigned short* __restrict__ Wql_,
    const float* __restrict__ bq,
    unsigned short* __restrict__ khh, unsigned short* __restrict__ khl,
    unsigned short* __restrict__ qhh, unsigned short* __restrict__ qhl) {
    extern __shared__ char smc[];
    const uint32_t sbase = smem_u32(smc);
    float* red = (float*)(smc + F_RED);
    const int tid = threadIdx.x;
    const int lane = tid & 31, w = tid >> 5;
    const int wr = w & 1, wc = w >> 1;
    const int ncol0 = wc * 32;
    const int g = lane >> 3, r = lane & 7;
    const long long row0 = (long long)blockIdx.x * 32;
    const int rowL = wr * 16 + (lane >> 2);
    const long long gA = row0 + rowL;
    const long long gB = gA + 8;

    for (int t = tid; t < 512; t += 256) {
        int row = t >> 4, d0 = (t & 15) * 8;
        const float* src = X + (row0 + row) * DD + d0;
        cvt_store8o(smc, F_AH, F_AL, row, d0, *(const float4*)src, *(const float4*)(src + 4));
    }
    for (int t = tid; t < 2048; t += 256) {
        int row = t >> 4, d0 = (t & 15) * 8;
        uint32_t off = sw_off(row, d0);
        *(uint4*)(smc + F_WH + off) = *(const uint4*)(Wkh_ + row * DD + d0);
        *(uint4*)(smc + F_WL + off) = *(const uint4*)(Wkl_ + row * DD + d0);
    }
    __syncthreads();

    float C[4][4];
#pragma unroll
    for (int nf = 0; nf < 4; nf++)
#pragma unroll
        for (int e = 0; e < 4; e++) C[nf][e] = 0.f;

#pragma unroll
    for (int kc = 0; kc < 8; kc++) {
        uint32_t aoff = sw_off(wr * 16 + ((g & 1) ? 8 : 0) + r, kc * 16 + ((g >> 1) ? 8 : 0));
        uint32_t ah0, ah1, ah2, ah3, al0, al1, al2, al3;
        ldsm4(ah0, ah1, ah2, ah3, sbase + F_AH + aoff);
        ldsm4(al0, al1, al2, al3, sbase + F_AL + aoff);
        uint32_t th[2][4], tl[2][4];
#pragma unroll
        for (int nfp = 0; nfp < 2; nfp++) {
            uint32_t boff = sw_off(kc * 16 + ((g & 1) ? 8 : 0) + r,
                                   ncol0 + nfp * 16 + ((g >> 1) ? 8 : 0));
            ldsm4t(th[nfp][0], th[nfp][1], th[nfp][2], th[nfp][3], sbase + F_WH + boff);
            ldsm4t(tl[nfp][0], tl[nfp][1], tl[nfp][2], tl[nfp][3], sbase + F_WL + boff);
        }
#pragma unroll
        for (int nfp = 0; nfp < 2; nfp++) {
            mma16816(C[2 * nfp],     ah0, ah1, ah2, ah3, th[nfp][0], th[nfp][1]);
            mma16816(C[2 * nfp + 1], ah0, ah1, ah2, ah3, th[nfp][2], th[nfp][3]);
        }
#pragma unroll
        for (int nfp = 0; nfp < 2; nfp++) {
            mma16816(C[2 * nfp],     ah0, ah1, ah2, ah3, tl[nfp][0], tl[nfp][1]);
            mma16816(C[2 * nfp + 1], ah0, ah1, ah2, ah3, tl[nfp][2], tl[nfp][3]);
        }
#pragma unroll
        for (int nfp = 0; nfp < 2; nfp++) {
            mma16816(C[2 * nfp],     al0, al1, al2, al3, th[nfp][0], th[nfp][1]);
            mma16816(C[2 * nfp + 1], al0, al1, al2, al3, th[nfp][2], th[nfp][3]);
        }
    }

    float qsA = 0.f, qsB = 0.f;
#pragma unroll
    for (int nf = 0; nf < 4; nf++) {
        int col = ncol0 + nf * 8 + 2 * (lane & 3);
        float2 bkv = *(const float2*)(bk + col);
        C[nf][0] += bkv.x; C[nf][1] += bkv.y;
        C[nf][2] += bkv.x; C[nf][3] += bkv.y;
        qsA += C[nf][0] * C[nf][0] + C[nf][1] * C[nf][1];
        qsB += C[nf][2] * C[nf][2] + C[nf][3] * C[nf][3];
    }
    qsA += __shfl_xor_sync(0xffffffffu, qsA, 1);
    qsA += __shfl_xor_sync(0xffffffffu, qsA, 2);
    qsB += __shfl_xor_sync(0xffffffffu, qsB, 1);
    qsB += __shfl_xor_sync(0xffffffffu, qsB, 2);
    if ((lane & 3) == 0) {
        red[wc * 32 + rowL] = qsA;
        red[wc * 32 + rowL + 8] = qsB;
    }
    __syncthreads();
    qsA = red[rowL] + red[32 + rowL] + red[64 + rowL] + red[96 + rowL];
    qsB = red[rowL + 8] + red[32 + rowL + 8] + red[64 + rowL + 8] + red[96 + rowL + 8];
    __syncthreads();
    for (int t = tid; t < 2048; t += 256) {
        int row = t >> 4, d0 = (t & 15) * 8;
        uint32_t off = sw_off(row, d0);
        *(uint4*)(smc + F_WH + off) = *(const uint4*)(Wqh_ + row * DD + d0);
        *(uint4*)(smc + F_WL + off) = *(const uint4*)(Wql_ + row * DD + d0);
    }
    {
        float qiA = __fdividef(1.f, fmaxf(sqrtf(qsA), 1e-8f));
        float qiB = __fdividef(1.f, fmaxf(sqrtf(qsB), 1e-8f));
#pragma unroll
        for (int nf = 0; nf < 4; nf++) {
            int col = ncol0 + nf * 8 + 2 * (lane & 3);
            uint32_t h, l;
            bsplit2(C[nf][0] * qiA, C[nf][1] * qiA, h, l);
            *(uint32_t*)(khh + gA * DD + col) = h;
            *(uint32_t*)(khl + gA * DD + col) = l;
            bsplit2(C[nf][2] * qiB, C[nf][3] * qiB, h, l);
            *(uint32_t*)(khh + gB * DD + col) = h;
            *(uint32_t*)(khl + gB * DD + col) = l;
        }
    }
    __syncthreads();

#pragma unroll
    for (int nf = 0; nf < 4; nf++)
#pragma unroll
        for (int e = 0; e < 4; e++) C[nf][e] = 0.f;
#pragma unroll
    for (int kc = 0; kc < 8; kc++) {
        uint32_t aoff = sw_off(wr * 16 + ((g & 1) ? 8 : 0) + r, kc * 16 + ((g >> 1) ? 8 : 0));
        uint32_t ah0, ah1, ah2, ah3, al0, al1, al2, al3;
        ldsm4(ah0, ah1, ah2, ah3, sbase + F_AH + aoff);
        ldsm4(al0, al1, al2, al3, sbase + F_AL + aoff);
        uint32_t th[2][4], tl[2][4];
#pragma unroll
        for (int nfp = 0; nfp < 2; nfp++) {
            uint32_t boff = sw_off(kc * 16 + ((g & 1) ? 8 : 0) + r,
                                   ncol0 + nfp * 16 + ((g >> 1) ? 8 : 0));
            ldsm4t(th[nfp][0], th[nfp][1], th[nfp][2], th[nfp][3], sbase + F_WH + boff);
            ldsm4t(tl[nfp][0], tl[nfp][1], tl[nfp][2], tl[nfp][3], sbase + F_WL + boff);
        }
#pragma unroll
        for (int nfp = 0; nfp < 2; nfp++) {
            mma16816(C[2 * nfp],     ah0, ah1, ah2, ah3, th[nfp][0], th[nfp][1]);
            mma16816(C[2 * nfp + 1], ah0, ah1, ah2, ah3, th[nfp][2], th[nfp][3]);
        }
#pragma unroll
        for (int nfp = 0; nfp < 2; nfp++) {
            mma16816(C[2 * nfp],     ah0, ah1, ah2, ah3, tl[nfp][0], tl[nfp][1]);
            mma16816(C[2 * nfp + 1], ah0, ah1, ah2, ah3, tl[nfp][2], tl[nfp][3]);
        }
#pragma unroll
        for (int nfp = 0; nfp < 2; nfp++) {
            mma16816(C[2 * nfp],     al0, al1, al2, al3, th[nfp][0], th[nfp][1]);
            mma16816(C[2 * nfp + 1], al0, al1, al2, al3, th[nfp][2], th[nfp][3]);
        }
    }

    qsA = 0.f; qsB = 0.f;
#pragma unroll
    for (int nf = 0; nf < 4; nf++) {
        int col = ncol0 + nf * 8 + 2 * (lane & 3);
        float2 bqv = *(const float2*)(bq + col);
        C[nf][0] += bqv.x; C[nf][1] += bqv.y;
        C[nf][2] += bqv.x; C[nf][3] += bqv.y;
        qsA += C[nf][0] * C[nf][0] + C[nf][1] * C[nf][1];
        qsB += C[nf][2] * C[nf][2] + C[nf][3] * C[nf][3];
    }
    qsA += __shfl_xor_sync(0xffffffffu, qsA, 1);
    qsA += __shfl_xor_sync(0xffffffffu, qsA, 2);
    qsB += __shfl_xor_sync(0xffffffffu, qsB, 1);
    qsB += __shfl_xor_sync(0xffffffffu, qsB, 2);
    if ((lane & 3) == 0) {
        red[wc * 32 + rowL] = qsA;
        red[wc * 32 + rowL + 8] = qsB;
    }
    __syncthreads();
    qsA = red[rowL] + red[32 + rowL] + red[64 + rowL] + red[96 + rowL];
    qsB = red[rowL + 8] + red[32 + rowL + 8] + red[64 + rowL + 8] + red[96 + rowL + 8];
    float qiA = __fdividef(1.f, fmaxf(sqrtf(qsA), 1e-8f));
    float qiB = __fdividef(1.f, fmaxf(sqrtf(qsB), 1e-8f));
#pragma unroll
    for (int nf = 0; nf < 4; nf++) {
        int col = ncol0 + nf * 8 + 2 * (lane & 3);
        uint32_t h, l;
        bsplit2(C[nf][0] * qiA, C[nf][1] * qiA, h, l);
        *(uint32_t*)(qhh + gA * DD + col) = h;
        *(uint32_t*)(qhl + gA * DD + col) = l;
        bsplit2(C[nf][2] * qiB, C[nf][3] * qiB, h, l);
        *(uint32_t*)(qhh + gB * DD + col) = h;
        *(uint32_t*)(qhl + gB * DD + col) = l;
    }
}

// ================== MMA epilogue: 32-row tiles, full W resident ==================
__global__ __launch_bounds__(256, 2) void epilogue_mma(
    const float* __restrict__ A0,
    const unsigned short* __restrict__ Woh, const unsigned short* __restrict__ Wol,
    const float* __restrict__ bo,
    const unsigned short* __restrict__ Wqh, const unsigned short* __restrict__ Wql,
    const float* __restrict__ bq,
    const float* __restrict__ mf, const float* __restrict__ zin,
    const float* __restrict__ zbase, float* __restrict__ vacc,
    float* __restrict__ zc, unsigned short* __restrict__ qhh,
    unsigned short* __restrict__ qhl, float* __restrict__ out,
    float sw, float rc, int first, int has_next) {
    extern __shared__ char smc[];
    const uint32_t sbase = smem_u32(smc);
    float* red = (float*)(smc + F_RED);
    const int tid = threadIdx.x;
    const int lane = tid & 31, w = tid >> 5;
    const int wr = w & 1, wc = w >> 1;
    const int ncol0 = wc * 32;
    const int g = lane >> 3, r = lane & 7;
    const long long row0 = (long long)blockIdx.x * 32;
    const int rowL = wr * 16 + (lane >> 2);
    const long long gA = row0 + rowL;
    const long long gB = gA + 8;

    for (int t = tid; t < 512; t += 256) {
        int row = t >> 4, d0 = (t & 15) * 8;
        const float* src = A0 + (row0 + row) * DD + d0;
        cvt_store8o(smc, F_AH, F_AL, row, d0, *(const float4*)src, *(const float4*)(src + 4));
    }
    for (int t = tid; t < 2048; t += 256) {
        int row = t >> 4, d0 = (t & 15) * 8;
        uint32_t off = sw_off(row, d0);
        *(uint4*)(smc + F_WH + off) = *(const uint4*)(Woh + row * DD + d0);
        *(uint4*)(smc + F_WL + off) = *(const uint4*)(Wol + row * DD + d0);
    }
    __syncthreads();

    float C[4][4];
#pragma unroll
    for (int nf = 0; nf < 4; nf++)
#pragma unroll
        for (int e = 0; e < 4; e++) C[nf][e] = 0.f;

#pragma unroll
    for (int kc = 0; kc < 8; kc++) {
        uint32_t aoff = sw_off(wr * 16 + ((g & 1) ? 8 : 0) + r, kc * 16 + ((g >> 1) ? 8 : 0));
        uint32_t ah0, ah1, ah2, ah3, al0, al1, al2, al3;
        ldsm4(ah0, ah1, ah2, ah3, sbase + F_AH + aoff);
        ldsm4(al0, al1, al2, al3, sbase + F_AL + aoff);
        uint32_t th[2][4], tl[2][4];
#pragma unroll
        for (int nfp = 0; nfp < 2; nfp++) {
            uint32_t boff = sw_off(kc * 16 + ((g & 1) ? 8 : 0) + r,
                                   ncol0 + nfp * 16 + ((g >> 1) ? 8 : 0));
            ldsm4t(th[nfp][0], th[nfp][1], th[nfp][2], th[nfp][3], sbase + F_WH + boff);
            ldsm4t(tl[nfp][0], tl[nfp][1], tl[nfp][2], tl[nfp][3], sbase + F_WL + boff);
        }
#pragma unroll
        for (int nfp = 0; nfp < 2; nfp++) {
            mma16816(C[2 * nfp],     ah0, ah1, ah2, ah3, th[nfp][0], th[nfp][1]);
            mma16816(C[2 * nfp + 1], ah0, ah1, ah2, ah3, th[nfp][2], th[nfp][3]);
        }
#pragma unroll
        for (int nfp = 0; nfp < 2; nfp++) {
            mma16816(C[2 * nfp],     ah0, ah1, ah2, ah3, tl[nfp][0], tl[nfp][1]);
            mma16816(C[2 * nfp + 1], ah0, ah1, ah2, ah3, tl[nfp][2], tl[nfp][3]);
        }
#pragma unroll
        for (int nfp = 0; nfp < 2; nfp++) {
            mma16816(C[2 * nfp],     al0, al1, al2, al3, th[nfp][0], th[nfp][1]);
            mma16816(C[2 * nfp + 1], al0, al1, al2, al3, th[nfp][2], th[nfp][3]);
        }
    }

    float dotA = 0.f, dotB = 0.f;
#pragma unroll
    for (int nf = 0; nf < 4; nf++) {
        int col = ncol0 + nf * 8 + 2 * (lane & 3);
        float2 bov = *(const float2*)(bo + col);
        float2 mA = *(const float2*)(mf + gA * DD + col);
        float2 mB = *(const float2*)(mf + gB * DD + col);
        C[nf][0] += bov.x + mA.x; C[nf][1] += bov.y + mA.y;
        C[nf][2] += bov.x + mB.x; C[nf][3] += bov.y + mB.y;
        float2 zA = *(const float2*)(zin + gA * DD + col);
        float2 zB = *(const float2*)(zin + gB * DD + col);
        dotA += C[nf][0] * zA.x + C[nf][1] * zA.y;
        dotB += C[nf][2] * zB.x + C[nf][3] * zB.y;
    }
    dotA += __shfl_xor_sync(0xffffffffu, dotA, 1);
    dotA += __shfl_xor_sync(0xffffffffu, dotA, 2);
    dotB += __shfl_xor_sync(0xffffffffu, dotB, 1);
    dotB += __shfl_xor_sync(0xffffffffu, dotB, 2);
    if ((lane & 3) == 0) {
        red[wc * 32 + rowL] = dotA;
        red[wc * 32 + rowL + 8] = dotB;
    }
    __syncthreads();
    dotA = red[rowL] + red[32 + rowL] + red[64 + rowL] + red[96 + rowL];
    dotB = red[rowL + 8] + red[32 + rowL + 8] + red[64 + rowL + 8] + red[96 + rowL + 8];
    __syncthreads();

    for (int t = tid; t < 2048; t += 256) {
        int row = t >> 4, d0 = (t & 15) * 8;
        uint32_t off = sw_off(row, d0);
        *(uint4*)(smc + F_WH + off) = *(const uint4*)(Wqh + row * DD + d0);
        *(uint4*)(smc + F_WL + off) = *(const uint4*)(Wql + row * DD + d0);
    }
    float ssA = 0.f, ssB = 0.f;
#pragma unroll
    for (int nf = 0; nf < 4; nf++) {
        int col = ncol0 + nf * 8 + 2 * (lane & 3);
        float2 zA = *(const float2*)(zin + gA * DD + col);
        float2 zB = *(const float2*)(zin + gB * DD + col);
        C[nf][0] -= dotA * zA.x; C[nf][1] -= dotA * zA.y;
        C[nf][2] -= dotB * zB.x; C[nf][3] -= dotB * zB.y;
        float2* vA = (float2*)(vacc + gA * DD + col);
        float2* vB = (float2*)(vacc + gB * DD + col);
        float2 vpA = first ? make_float2(0.f, 0.f) : *vA;
        float2 vpB = first ? make_float2(0.f, 0.f) : *vB;
        float2 vnA = make_float2(vpA.x + sw * C[nf][0], vpA.y + sw * C[nf][1]);
        float2 vnB = make_float2(vpB.x + sw * C[nf][2], vpB.y + sw * C[nf][3]);
        *vA = vnA; *vB = vnB;
        float2 zbA = *(const float2*)(zbase + gA * DD + col);
        float2 zbB = *(const float2*)(zbase + gB * DD + col);
        if (has_next) {
            float a0v = zbA.x + rc * C[nf][0], a1v = zbA.y + rc * C[nf][1];
            float b0v = zbB.x + rc * C[nf][2], b1v = zbB.y + rc * C[nf][3];
            ssA += a0v * a0v + a1v * a1v;
            ssB += b0v * b0v + b1v * b1v;
            C[nf][0] = a0v; C[nf][1] = a1v; C[nf][2] = b0v; C[nf][3] = b1v;
        } else {
            float a0v = zbA.x + vnA.x, a1v = zbA.y + vnA.y;
            float b0v = zbB.x + vnB.x, b1v = zbB.y + vnB.y;
            ssA += a0v * a0v + a1v * a1v;
            ssB += b0v * b0v + b1v * b1v;
            C[nf][0] = a0v; C[nf][1] = a1v; C[nf][2] = b0v; C[nf][3] = b1v;
        }
    }
    ssA += __shfl_xor_sync(0xffffffffu, ssA, 1);
    ssA += __shfl_xor_sync(0xffffffffu, ssA, 2);
    ssB += __shfl_xor_sync(0xffffffffu, ssB, 1);
    ssB += __shfl_xor_sync(0xffffffffu, ssB, 2);
    if ((lane & 3) == 0) {
        red[wc * 32 + rowL] = ssA;
        red[wc * 32 + rowL + 8] = ssB;
    }
    __syncthreads();
    ssA = red[rowL] + red[32 + rowL] + red[64 + rowL] + red[96 + rowL];
    ssB = red[rowL + 8] + red[32 + rowL + 8] + red[64 + rowL + 8] + red[96 + rowL + 8];
    __syncthreads();
    float invA = __fdividef(1.f, fmaxf(sqrtf(ssA), 1e-8f));
    float invB = __fdividef(1.f, fmaxf(sqrtf(ssB), 1e-8f));

    if (!has_next) {
#pragma unroll
        for (int nf = 0; nf < 4; nf++) {
            int col = ncol0 + nf * 8 + 2 * (lane & 3);
            *(float2*)(out + gA * DD + col) = make_float2(C[nf][0] * invA, C[nf][1] * invA);
            *(float2*)(out + gB * DD + col) = make_float2(C[nf][2] * invB, C[nf][3] * invB);
        }
        return;
    }

#pragma unroll
    for (int nf = 0; nf < 4; nf++) {
        int col = ncol0 + nf * 8 + 2 * (lane & 3);
        float a0v = C[nf][0] * invA, a1v = C[nf][1] * invA;
        float b0v = C[nf][2] * invB, b1v = C[nf][3] * invB;
        *(float2*)(zc + gA * DD + col) = make_float2(a0v, a1v);
        *(float2*)(zc + gB * DD + col) = make_float2(b0v, b1v);
        uint32_t h, l;
        bsplit2(a0v, a1v, h, l);
        *(uint32_t*)(smc + F_AH + sw_off(rowL, col)) = h;
        *(uint32_t*)(smc + F_AL + sw_off(rowL, col)) = l;
        bsplit2(b0v, b1v, h, l);
        *(uint32_t*)(smc + F_AH + sw_off(rowL + 8, col)) = h;
        *(uint32_t*)(smc + F_AL + sw_off(rowL + 8, col)) = l;
    }
    __syncthreads();

#pragma unroll
    for (int nf = 0; nf < 4; nf++)
#pragma unroll
        for (int e = 0; e < 4; e++) C[nf][e] = 0.f;
#pragma unroll
    for (int kc = 0; kc < 8; kc++) {
        uint32_t aoff = sw_off(wr * 16 + ((g & 1) ? 8 : 0) + r, kc * 16 + ((g >> 1) ? 8 : 0));
        uint32_t ah0, ah1, ah2, ah3, al0, al1, al2, al3;
        ldsm4(ah0, ah1, ah2, ah3, sbase + F_AH + aoff);
        ldsm4(al0, al1, al2, al3, sbase + F_AL + aoff);
        uint32_t th[2][4], tl[2][4];
#pragma unroll
        for (int nfp = 0; nfp < 2; nfp++) {
            uint32_t boff = sw_off(kc * 16 + ((g & 1) ? 8 : 0) + r,
                                   ncol0 + nfp * 16 + ((g >> 1) ? 8 : 0));
            ldsm4t(th[nfp][0], th[nfp][1], th[nfp][2], th[nfp][3], sbase + F_WH + boff);
            ldsm4t(tl[nfp][0], tl[nfp][1], tl[nfp][2], tl[nfp][3], sbase + F_WL + boff);
        }
#pragma unroll
        for (int nfp = 0; nfp < 2; nfp++) {
            mma16816(C[2 * nfp],     ah0, ah1, ah2, ah3, th[nfp][0], th[nfp][1]);
            mma16816(C[2 * nfp + 1], ah0, ah1, ah2, ah3, th[nfp][2], th[nfp][3]);
        }
#pragma unroll
        for (int nfp = 0; nfp < 2; nfp++) {
            mma16816(C[2 * nfp],     ah0, ah1, ah2, ah3, tl[nfp][0], tl[nfp][1]);
            mma16816(C[2 * nfp + 1], ah0, ah1, ah2, ah3, tl[nfp][2], tl[nfp][3]);
        }
#pragma unroll
        for (int nfp = 0; nfp < 2; nfp++) {
            mma16816(C[2 * nfp],     al0, al1, al2, al3, th[nfp][0], th[nfp][1]);
            mma16816(C[2 * nfp + 1], al0, al1, al2, al3, th[nfp][2], th[nfp][3]);
        }
    }

    float qsA = 0.f, qsB = 0.f;
#pragma unroll
    for (int nf = 0; nf < 4; nf++) {
        int col = ncol0 + nf * 8 + 2 * (lane & 3);
        float2 bqv = *(const float2*)(bq + col);
        C[nf][0] += bqv.x; C[nf][1] += bqv.y;
        C[nf][2] += bqv.x; C[nf][3] += bqv.y;
        qsA += C[nf][0] * C[nf][0] + C[nf][1] * C[nf][1];
        qsB += C[nf][2] * C[nf][2] + C[nf][3] * C[nf][3];
    }
    qsA += __shfl_xor_sync(0xffffffffu, qsA, 1);
    qsA += __shfl_xor_sync(0xffffffffu, qsA, 2);
    qsB += __shfl_xor_sync(0xffffffffu, qsB, 1);
    qsB += __shfl_xor_sync(0xffffffffu, qsB, 2);
    if ((lane & 3) == 0) {
        red[wc * 32 + rowL] = qsA;
        red[wc * 32 + rowL + 8] = qsB;
    }
    __syncthreads();
    qsA = red[rowL] + red[32 + rowL] + red[64 + rowL] + red[96 + rowL];
    qsB = red[rowL + 8] + red[32 + rowL + 8] + red[64 + rowL + 8] + red[96 + rowL + 8];
    float qiA = __fdividef(1.f, fmaxf(sqrtf(qsA), 1e-8f));
    float qiB = __fdividef(1.f, fmaxf(sqrtf(qsB), 1e-8f));
#pragma unroll
    for (int nf = 0; nf < 4; nf++) {
        int col = ncol0 + nf * 8 + 2 * (lane & 3);
        uint32_t h, l;
        bsplit2(C[nf][0] * qiA, C[nf][1] * qiA, h, l);
        *(uint32_t*)(qhh + gA * DD + col) = h;
        *(uint32_t*)(qhl + gA * DD + col) = l;
        bsplit2(C[nf][2] * qiB, C[nf][3] * qiB, h, l);
        *(uint32_t*)(qhh + gB * DD + col) = h;
        *(uint32_t*)(qhl + gB * DD + col) = l;
    }
}

// ---------------- launch ----------------
extern "C" void kernel_launch(void* const* d_in, const int* in_sizes, int n_in,
                              void* d_out, int out_size) {
    const float* z  = (const float*)d_in[0];
    const float* ck = (const float*)d_in[1];
    const float* cb = (const float*)d_in[2];
    const float* Wq = (const float*)d_in[3];
    const float* bq = (const float*)d_in[4];
    const float* Wk = (const float*)d_in[5];
    const float* bk = (const float*)d_in[6];
    const float* Wo = (const float*)d_in[7];
    const float* bo = (const float*)d_in[8];
    float* out = (float*)d_out;

    float *mf, *a0, *zc, *va;
    unsigned short *qhh, *qhl, *khh, *khl, *woh, *wol, *wqh, *wql, *wkh, *wkl;
    cudaGetSymbolAddress((void**)&mf, g_mf);
    cudaGetSymbolAddress((void**)&a0, g_a0);
    cudaGetSymbolAddress((void**)&zc, g_zc);
    cudaGetSymbolAddress((void**)&va, g_va);
    cudaGetSymbolAddress((void**)&qhh, g_qhh);
    cudaGetSymbolAddress((void**)&qhl, g_qhl);
    cudaGetSymbolAddress((void**)&khh, g_khh);
    cudaGetSymbolAddress((void**)&khl, g_khl);
    cudaGetSymbolAddress((void**)&woh, g_woh);
    cudaGetSymbolAddress((void**)&wol, g_wol);
    cudaGetSymbolAddress((void**)&wqh, g_wqh);
    cudaGetSymbolAddress((void**)&wql, g_wql);
    cudaGetSymbolAddress((void**)&wkh, g_wkh);
    cudaGetSymbolAddress((void**)&wkl, g_wkl);

    cudaFuncSetAttribute(dual_mma, cudaFuncAttributeMaxDynamicSharedMemorySize, EPI4_SMEM);
    cudaFuncSetAttribute(epilogue_mma, cudaFuncAttributeMaxDynamicSharedMemorySize, EPI4_SMEM);
    cudaFuncSetAttribute(attn_kernel, cudaFuncAttributeMaxDynamicSharedMemorySize, ATTN_SMEM);

    // one memset for all 4 stage accumulators
    cudaMemsetAsync(a0, 0, 4ll * BT * DD * sizeof(float));
    // conv + fused W prepack (blockIdx.y == 2 plane)
    conv_kernel<<<dim3(TT / 8, 3), dim3(64, 8)>>>(z, ck, cb, mf, Wo, Wq, Wk,
                                                  woh, wol, wqh, wql, wkh, wkl);
    dual_mma<<<BT / 32, 256, EPI4_SMEM>>>(z, wkh, wkl, bk, wqh, wql, bq,
                                          khh, khl, qhh, qhl);

    const float sws[4] = {1.f / 6.f, 2.f / 6.f, 2.f / 6.f, 1.f / 6.f};
    const float rcs[4] = {0.5f, 0.5f, 1.0f, 0.f};
    const float* zcur = z;
    for (int s = 0; s < 4; s++) {
        float* as = a0 + (long long)s * BT * DD;
        attn_kernel<<<dim3(32, 9), 128, ATTN_SMEM>>>(qhh, qhl, khh, khl, as);
        epilogue_mma<<<BT / 32, 256, EPI4_SMEM>>>(as, woh, wol, bo, wqh, wql, bq,
                                                  mf, zcur, z, va, zc, qhh, qhl, out,
                                                  sws[s], rcs[s], s == 0 ? 1 : 0,
                                                  s < 3 ? 1 : 0);
        zcur = zc;
    }
}